// round 6
// baseline (speedup 1.0000x reference)
#include <cuda_runtime.h>
#include <cstdint>

// Problem constants
#define NB     4
#define KWIN   2048
#define DMODEL 512
#define NHEAD  8
#define HDIM   64

// Scratch (allocation-free rule: __device__ globals).
// Layout for all four: [B, K, H*64] row-major == [8192, 512]
__device__ float g_qp[NB * KWIN * DMODEL];
__device__ float g_kp[NB * KWIN * DMODEL];
__device__ float g_vp[NB * KWIN * DMODEL];
__device__ float g_ct[NB * KWIN * DMODEL];

// ---------------------------------------------------------------------------
// Generic SGEMM: C[m, nb*64 + n] = X[m, :] (512) @ Wt[:, n] + bias
//   grid = (8192/128, 8), block = 128
//   Wt = W + blockIdx.y * wstride_y, element (k, n) at Wt[k*ldb + n]
//   Used for:
//     projections: wstride_y = 512*64, ldb = 64   (per-head weight block)
//     output proj: wstride_y = 64,     ldb = 512  (column slice of W_o)
//   xsel==1 -> read X from g_ct; osel selects g_qp/g_kp/g_vp or `out`.
// ---------------------------------------------------------------------------
__global__ __launch_bounds__(128)
void gemm512_kernel(const float* X, const float* __restrict__ W,
                    const float* __restrict__ bias, float* out,
                    int wstride_y, int ldb, int xsel, int osel)
{
    const float* Xp = (xsel == 1) ? (const float*)g_ct : X;
    float* op = out;
    if (osel == 1) op = g_qp;
    else if (osel == 2) op = g_kp;
    else if (osel == 3) op = g_vp;

    __shared__ float As[16][128];   // [k][m] transposed
    __shared__ float Bs[16][64];    // [k][n]

    const int tid = threadIdx.x;
    const int txc = tid & 7;        // col group: cols txc*8..+7
    const int tyr = tid >> 3;       // row group: rows tyr*8..+7
    const int m0  = blockIdx.x * 128;
    const int nb  = blockIdx.y;
    const float* Wt = W + (size_t)nb * wstride_y;

    float C[8][8];
#pragma unroll
    for (int i = 0; i < 8; ++i)
#pragma unroll
        for (int j = 0; j < 8; ++j) C[i][j] = 0.f;

    for (int k0 = 0; k0 < 512; k0 += 16) {
        // A tile: rows m0..m0+127, cols k0..k0+15 (coalesced, store transposed)
#pragma unroll
        for (int j = 0; j < 4; ++j) {
            int f   = tid + 128 * j;        // 0..511 float4 slots
            int row = f >> 2;               // 0..127
            int q4  = (f & 3) << 2;         // 0,4,8,12
            float4 v = *(const float4*)(Xp + (size_t)(m0 + row) * 512 + k0 + q4);
            As[q4 + 0][row] = v.x;
            As[q4 + 1][row] = v.y;
            As[q4 + 2][row] = v.z;
            As[q4 + 3][row] = v.w;
        }
        // B tile: rows k0..k0+15, 64 cols
#pragma unroll
        for (int j = 0; j < 2; ++j) {
            int f  = tid * 2 + j;           // 0..255 float4 slots
            int r  = f >> 4;                // 0..15
            int c4 = (f & 15) << 2;         // 0..60
            *(float4*)&Bs[r][c4] = *(const float4*)(Wt + (size_t)(k0 + r) * ldb + c4);
        }
        __syncthreads();

#pragma unroll
        for (int kk = 0; kk < 16; ++kk) {
            float a[8], b[8];
            *(float4*)&a[0] = *(const float4*)&As[kk][tyr * 8];
            *(float4*)&a[4] = *(const float4*)&As[kk][tyr * 8 + 4];
            *(float4*)&b[0] = *(const float4*)&Bs[kk][txc * 8];
            *(float4*)&b[4] = *(const float4*)&Bs[kk][txc * 8 + 4];
#pragma unroll
            for (int i = 0; i < 8; ++i)
#pragma unroll
                for (int j = 0; j < 8; ++j)
                    C[i][j] += a[i] * b[j];
        }
        __syncthreads();
    }

    float bb[8];
#pragma unroll
    for (int j = 0; j < 8; ++j) bb[j] = bias[nb * 64 + txc * 8 + j];

#pragma unroll
    for (int i = 0; i < 8; ++i) {
        float* o = op + (size_t)(m0 + tyr * 8 + i) * 512 + nb * 64 + txc * 8;
        float4 v0 = make_float4(C[i][0] + bb[0], C[i][1] + bb[1],
                                C[i][2] + bb[2], C[i][3] + bb[3]);
        float4 v1 = make_float4(C[i][4] + bb[4], C[i][5] + bb[5],
                                C[i][6] + bb[6], C[i][7] + bb[7]);
        *(float4*)o       = v0;
        *(float4*)(o + 4) = v1;
    }
}

// ---------------------------------------------------------------------------
// Causal flash attention, fp32.
//   grid = (32 q-tiles, B*H = 32), block = 256 (16x16, 4x4 microtile)
//   Per (b,h): Q,K,V planes are [2048, 64] with row stride 512 in g_qp/kp/vp.
//   Writes heads output into g_ct[b, k, h*64 + v] (same layout).
//   Smem: Qs[d][r], KPs = K-as-[d][c] then reused as P-as-[c][r], Vs[c][v].
//   3 * 16KB = 48KB static smem exactly.
// ---------------------------------------------------------------------------
__global__ __launch_bounds__(256)
void attn_kernel()
{
    __shared__ float Qs[64][64];    // [d][r]
    __shared__ float KPs[64][64];   // K: [d][c]; after S-GEMM reused as P: [c][r]
    __shared__ float Vs[64][64];    // [c][v]

    const int qi  = (int)gridDim.x - 1 - (int)blockIdx.x;  // big tiles first
    const int bh  = blockIdx.y;
    const int b   = bh >> 3;
    const int h   = bh & 7;
    const int tid = threadIdx.x;
    const int tx  = tid & 15;       // col group (4 cols)
    const int ty  = tid >> 4;       // row group (4 rows)
    const float scale   = 0.022097086912079608f;  // 1/sqrt(2048)
    const float NEG_INF = __int_as_float(0xff800000);

    const size_t plane = (size_t)b * (KWIN * DMODEL) + (size_t)h * 64;
    const float* qp = g_qp;
    const float* kp = g_kp;
    const float* vp = g_vp;

    // Load Q tile transposed: Qs[d][r], rows qi*64..+63
    {
        int r  = tid >> 2;
        int dq = (tid & 3) << 4;
        const float* src = qp + plane + (size_t)(qi * 64 + r) * 512 + dq;
#pragma unroll
        for (int j = 0; j < 4; ++j) {
            float4 v = *(const float4*)(src + j * 4);
            Qs[dq + j * 4 + 0][r] = v.x;
            Qs[dq + j * 4 + 1][r] = v.y;
            Qs[dq + j * 4 + 2][r] = v.z;
            Qs[dq + j * 4 + 3][r] = v.w;
        }
    }

    float O[4][4];
    float m_i[4], l_i[4];
#pragma unroll
    for (int i = 0; i < 4; ++i) {
        m_i[i] = NEG_INF;
        l_i[i] = 0.f;
#pragma unroll
        for (int j = 0; j < 4; ++j) O[i][j] = 0.f;
    }

    for (int kt = 0; kt <= qi; ++kt) {
        __syncthreads();   // prior chunk done reading KPs/Vs (and Qs store visible)
        {
            int c  = tid >> 2;
            int dq = (tid & 3) << 4;
            const float* ks = kp + plane + (size_t)(kt * 64 + c) * 512 + dq;
            const float* vs = vp + plane + (size_t)(kt * 64 + c) * 512 + dq;
#pragma unroll
            for (int j = 0; j < 4; ++j) {
                float4 v = *(const float4*)(ks + j * 4);
                KPs[dq + j * 4 + 0][c] = v.x;
                KPs[dq + j * 4 + 1][c] = v.y;
                KPs[dq + j * 4 + 2][c] = v.z;
                KPs[dq + j * 4 + 3][c] = v.w;
            }
#pragma unroll
            for (int j = 0; j < 4; ++j)
                *(float4*)&Vs[c][dq + j * 4] = *(const float4*)(vs + j * 4);
        }
        __syncthreads();

        // S = Q @ K^T (4x4 per thread), reduce over d
        float S[4][4];
#pragma unroll
        for (int i = 0; i < 4; ++i)
#pragma unroll
            for (int j = 0; j < 4; ++j) S[i][j] = 0.f;

#pragma unroll 8
        for (int d = 0; d < 64; ++d) {
            float a[4], kv[4];
            *(float4*)a  = *(const float4*)&Qs[d][ty * 4];
            *(float4*)kv = *(const float4*)&KPs[d][tx * 4];
#pragma unroll
            for (int i = 0; i < 4; ++i)
#pragma unroll
                for (int j = 0; j < 4; ++j)
                    S[i][j] += a[i] * kv[j];
        }

        // scale + causal mask + online softmax (row reduce over tx lanes)
        const bool diag = (kt == qi);
#pragma unroll
        for (int i = 0; i < 4; ++i) {
            const int rg = ty * 4 + i;
#pragma unroll
            for (int j = 0; j < 4; ++j) {
                float s = S[i][j] * scale;
                if (diag && (tx * 4 + j > rg)) s = NEG_INF;
                S[i][j] = s;
            }
            float mx = fmaxf(fmaxf(S[i][0], S[i][1]), fmaxf(S[i][2], S[i][3]));
#pragma unroll
            for (int off = 1; off < 16; off <<= 1)
                mx = fmaxf(mx, __shfl_xor_sync(0xffffffffu, mx, off));
            const float mn = fmaxf(m_i[i], mx);
            float sum = 0.f;
#pragma unroll
            for (int j = 0; j < 4; ++j) {
                float p = __expf(S[i][j] - mn);
                S[i][j] = p;
                sum += p;
            }
#pragma unroll
            for (int off = 1; off < 16; off <<= 1)
                sum += __shfl_xor_sync(0xffffffffu, sum, off);
            const float alpha = __expf(m_i[i] - mn);
            l_i[i] = l_i[i] * alpha + sum;
            m_i[i] = mn;
#pragma unroll
            for (int j = 0; j < 4; ++j) O[i][j] *= alpha;
        }

        __syncthreads();   // all threads done reading KPs as K
        // store P transposed: KPs[c][r]
#pragma unroll
        for (int j = 0; j < 4; ++j)
#pragma unroll
            for (int i = 0; i < 4; ++i)
                KPs[tx * 4 + j][ty * 4 + i] = S[i][j];
        __syncthreads();

        // O += P @ V, reduce over c
#pragma unroll 8
        for (int c = 0; c < 64; ++c) {
            float a[4], vv[4];
            *(float4*)a  = *(const float4*)&KPs[c][ty * 4];
            *(float4*)vv = *(const float4*)&Vs[c][tx * 4];
#pragma unroll
            for (int i = 0; i < 4; ++i)
#pragma unroll
                for (int j = 0; j < 4; ++j)
                    O[i][j] += a[i] * vv[j];
        }
    }

    // normalize + write heads output into concat layout [b, k, h*64 + v]
#pragma unroll
    for (int i = 0; i < 4; ++i) {
        const float inv = 1.f / l_i[i];
        float* o = g_ct + plane + (size_t)(qi * 64 + ty * 4 + i) * 512 + tx * 4;
        *(float4*)o = make_float4(O[i][0] * inv, O[i][1] * inv,
                                  O[i][2] * inv, O[i][3] * inv);
    }
}

// ---------------------------------------------------------------------------
// Launch: 3 projections -> attention -> output projection (one stream, serial)
// ---------------------------------------------------------------------------
extern "C" void kernel_launch(void* const* d_in, const int* in_sizes, int n_in,
                              void* d_out, int out_size)
{
    const float* query = (const float*)d_in[0];
    const float* key_  = (const float*)d_in[1];
    const float* value = (const float*)d_in[2];
    const float* W_q   = (const float*)d_in[3];
    const float* b_q   = (const float*)d_in[4];
    const float* W_k   = (const float*)d_in[5];
    const float* b_k   = (const float*)d_in[6];
    const float* W_v   = (const float*)d_in[7];
    const float* b_v   = (const float*)d_in[8];
    const float* W_o   = (const float*)d_in[9];
    const float* b_o   = (const float*)d_in[10];
    float* out = (float*)d_out;

    dim3 gg(64, 8);   // 8192/128 row tiles x 8 col tiles (heads / N-slices)

    // q/k/v projections: per-head weight blocks [512,64], ldb=64
    gemm512_kernel<<<gg, 128>>>(query, W_q, b_q, nullptr, 512 * 64, 64, 0, 1);
    gemm512_kernel<<<gg, 128>>>(key_,  W_k, b_k, nullptr, 512 * 64, 64, 0, 2);
    gemm512_kernel<<<gg, 128>>>(value, W_v, b_v, nullptr, 512 * 64, 64, 0, 3);

    // causal attention: 32 q-tiles x 32 (b,h) planes
    attn_kernel<<<dim3(32, 32), 256>>>();

    // output projection: concat [8192,512] @ W_o [512,512] + b_o
    gemm512_kernel<<<gg, 128>>>(nullptr, W_o, b_o, out, 64, 512, 1, 0);
}

// round 7
// speedup vs baseline: 1.0861x; 1.0861x over previous
#include <cuda_runtime.h>
#include <cstdint>

// Problem constants
#define NB     4
#define KWIN   2048
#define DMODEL 512
#define NHEAD  8
#define HDIM   64

// Scratch (allocation-free rule: __device__ globals).
// Layout for all four: [B, K, H*64] row-major == [8192, 512]
__device__ float g_qp[NB * KWIN * DMODEL];
__device__ float g_kp[NB * KWIN * DMODEL];
__device__ float g_vp[NB * KWIN * DMODEL];
__device__ float g_ct[NB * KWIN * DMODEL];

// ---------------------------------------------------------------------------
// Packed fp32x2 helpers (sm_103a FFMA2 path — ptxas never auto-generates it)
// ---------------------------------------------------------------------------
__device__ __forceinline__ unsigned long long dup2(float x) {
    unsigned long long r;
    asm("mov.b64 %0, {%1, %1};" : "=l"(r) : "r"(__float_as_uint(x)));
    return r;
}
__device__ __forceinline__ unsigned long long pack2(float x, float y) {
    unsigned long long r;
    asm("mov.b64 %0, {%1, %2};" : "=l"(r) : "r"(__float_as_uint(x)), "r"(__float_as_uint(y)));
    return r;
}
__device__ __forceinline__ void unpack2(unsigned long long v, float& lo, float& hi) {
    unsigned a, b;
    asm("mov.b64 {%0, %1}, %2;" : "=r"(a), "=r"(b) : "l"(v));
    lo = __uint_as_float(a);
    hi = __uint_as_float(b);
}
#define FMA2(d, a, b) asm("fma.rn.f32x2 %0, %1, %2, %0;" : "+l"(d) : "l"(a), "l"(b))
#define MUL2ACC(d, s)  asm("mul.rn.f32x2 %0, %0, %1;"     : "+l"(d) : "l"(s))

// ---------------------------------------------------------------------------
// Generic SGEMM (FFMA2 inner loop): C[m, nb*64 + n] = X[m,:] (512) @ Wt[:,n] + b
//   grid = (8192/128, 8), block = 128, 8x8 microtile as 4 row-pairs x 8 cols
// ---------------------------------------------------------------------------
__global__ __launch_bounds__(128)
void gemm512_kernel(const float* X, const float* __restrict__ W,
                    const float* __restrict__ bias, float* out,
                    int wstride_y, int ldb, int xsel, int osel)
{
    const float* Xp = (xsel == 1) ? (const float*)g_ct : X;
    float* op = out;
    if (osel == 1) op = g_qp;
    else if (osel == 2) op = g_kp;
    else if (osel == 3) op = g_vp;

    __shared__ __align__(16) float As[16][128];   // [k][m] transposed
    __shared__ __align__(16) float Bs[16][64];    // [k][n]

    const int tid = threadIdx.x;
    const int txc = tid & 7;        // col group: cols txc*8..+7
    const int tyr = tid >> 3;       // row group: rows tyr*8..+7
    const int m0  = blockIdx.x * 128;
    const int nb  = blockIdx.y;
    const float* Wt = W + (size_t)nb * wstride_y;

    unsigned long long Cp[4][8];    // row-pairs (2p, 2p+1) x 8 cols
#pragma unroll
    for (int p = 0; p < 4; ++p)
#pragma unroll
        for (int j = 0; j < 8; ++j) Cp[p][j] = 0ull;

    for (int k0 = 0; k0 < 512; k0 += 16) {
#pragma unroll
        for (int j = 0; j < 4; ++j) {
            int f   = tid + 128 * j;
            int row = f >> 2;
            int q4  = (f & 3) << 2;
            float4 v = *(const float4*)(Xp + (size_t)(m0 + row) * 512 + k0 + q4);
            As[q4 + 0][row] = v.x;
            As[q4 + 1][row] = v.y;
            As[q4 + 2][row] = v.z;
            As[q4 + 3][row] = v.w;
        }
#pragma unroll
        for (int j = 0; j < 2; ++j) {
            int f  = tid * 2 + j;
            int r  = f >> 4;
            int c4 = (f & 15) << 2;
            *(float4*)&Bs[r][c4] = *(const float4*)(Wt + (size_t)(k0 + r) * ldb + c4);
        }
        __syncthreads();

#pragma unroll
        for (int kk = 0; kk < 16; ++kk) {
            const ulonglong2* ap = (const ulonglong2*)&As[kk][tyr * 8];
            ulonglong2 a01 = ap[0];
            ulonglong2 a23 = ap[1];
            unsigned long long av[4] = { a01.x, a01.y, a23.x, a23.y };
            float4 b0 = *(const float4*)&Bs[kk][txc * 8];
            float4 b1 = *(const float4*)&Bs[kk][txc * 8 + 4];
            unsigned long long bd[8] = {
                dup2(b0.x), dup2(b0.y), dup2(b0.z), dup2(b0.w),
                dup2(b1.x), dup2(b1.y), dup2(b1.z), dup2(b1.w)
            };
#pragma unroll
            for (int p = 0; p < 4; ++p)
#pragma unroll
                for (int j = 0; j < 8; ++j)
                    FMA2(Cp[p][j], av[p], bd[j]);
        }
        __syncthreads();
    }

    float bb[8];
#pragma unroll
    for (int j = 0; j < 8; ++j) bb[j] = bias[nb * 64 + txc * 8 + j];

#pragma unroll
    for (int p = 0; p < 4; ++p) {
        float lo[8], hi[8];
#pragma unroll
        for (int j = 0; j < 8; ++j) unpack2(Cp[p][j], lo[j], hi[j]);
        float* o0 = op + (size_t)(m0 + tyr * 8 + 2 * p) * 512 + nb * 64 + txc * 8;
        float* o1 = o0 + 512;
        *(float4*)o0       = make_float4(lo[0] + bb[0], lo[1] + bb[1], lo[2] + bb[2], lo[3] + bb[3]);
        *(float4*)(o0 + 4) = make_float4(lo[4] + bb[4], lo[5] + bb[5], lo[6] + bb[6], lo[7] + bb[7]);
        *(float4*)o1       = make_float4(hi[0] + bb[0], hi[1] + bb[1], hi[2] + bb[2], hi[3] + bb[3]);
        *(float4*)(o1 + 4) = make_float4(hi[4] + bb[4], hi[5] + bb[5], hi[6] + bb[6], hi[7] + bb[7]);
    }
}

// ---------------------------------------------------------------------------
// Causal flash attention, fp32 with FFMA2 GEMM loops.
//   grid = (16 q-tiles, B*H = 32), block = 256 (16x16, 8x4 microtile)
//   Br = 128 Q rows per CTA, Bc = 64 keys per chunk.
//   Dynamic smem (99328 B): Qs[64][128] | Ks[64][64] | Vs[64][68] | Ps[64][128]
//   Ps is 16B-granular swizzled: word(c,r) = c*128 + ((r + ((c>>2)&7)*4) & 127)
// ---------------------------------------------------------------------------
#define ATTN_SMEM_BYTES ((64*128 + 64*64 + 64*68 + 64*128) * 4)

__global__ __launch_bounds__(256, 2)
void attn_kernel()
{
    extern __shared__ __align__(16) float sm[];
    float* Qs = sm;                    // [d][r]  stride 128
    float* Ks = sm + 64 * 128;         // [d][c]  stride 64
    float* Vs = Ks + 64 * 64;          // [c][v]  stride 68 (pad: bank spread)
    float* Ps = Vs + 64 * 68;          // [c][r]  stride 128, swizzled

    const int qi  = 15 - (int)blockIdx.x;   // big tiles first
    const int bh  = blockIdx.y;
    const int b   = bh >> 3;
    const int h   = bh & 7;
    const int tid = threadIdx.x;
    const int tx  = tid & 15;          // 4 key/value cols: tx*4..+3
    const int ty  = tid >> 4;          // 8 q rows: ty*8..+7
    const float scale   = 0.022097086912079608f;  // 1/sqrt(2048)
    const float NEG_INF = __int_as_float(0xff800000);

    const size_t plane = (size_t)b * (KWIN * DMODEL) + (size_t)h * 64;

    // Load Q tile transposed: Qs[d][r], rows qi*128..+127
    {
        int r  = tid >> 1;             // 0..127
        int d0 = (tid & 1) << 5;       // 0 or 32
        const float* src = g_qp + plane + (size_t)(qi * 128 + r) * 512 + d0;
#pragma unroll
        for (int k = 0; k < 8; ++k) {
            float4 v = *(const float4*)(src + k * 4);
            int d = d0 + k * 4;
            Qs[(d + 0) * 128 + r] = v.x;
            Qs[(d + 1) * 128 + r] = v.y;
            Qs[(d + 2) * 128 + r] = v.z;
            Qs[(d + 3) * 128 + r] = v.w;
        }
    }

    unsigned long long Op[4][4];       // row-pairs x 4 v-cols
    float m_i[8], l_i[8];
#pragma unroll
    for (int p = 0; p < 4; ++p)
#pragma unroll
        for (int j = 0; j < 4; ++j) Op[p][j] = 0ull;
#pragma unroll
    for (int i = 0; i < 8; ++i) { m_i[i] = NEG_INF; l_i[i] = 0.f; }

    const int ktmax = 2 * qi + 1;
    for (int kt = 0; kt <= ktmax; ++kt) {
        __syncthreads();   // prev chunk done reading Ks/Vs/Ps
        {
            int c  = tid & 63;
            int d0 = (tid >> 6) << 4;  // 0,16,32,48
            const float* ksrc = g_kp + plane + (size_t)(kt * 64 + c) * 512 + d0;
            const float* vsrc = g_vp + plane + (size_t)(kt * 64 + c) * 512 + d0;
#pragma unroll
            for (int k2 = 0; k2 < 4; ++k2) {
                float4 v = *(const float4*)(ksrc + k2 * 4);
                int d = d0 + k2 * 4;
                Ks[(d + 0) * 64 + c] = v.x;
                Ks[(d + 1) * 64 + c] = v.y;
                Ks[(d + 2) * 64 + c] = v.z;
                Ks[(d + 3) * 64 + c] = v.w;
            }
#pragma unroll
            for (int k2 = 0; k2 < 4; ++k2)
                *(float4*)&Vs[c * 68 + d0 + k2 * 4] = *(const float4*)(vsrc + k2 * 4);
        }
        __syncthreads();

        // S = Q^T K  (8x4 per thread as 4 row-pairs)
        unsigned long long Sp[4][4];
#pragma unroll
        for (int p = 0; p < 4; ++p)
#pragma unroll
            for (int j = 0; j < 4; ++j) Sp[p][j] = 0ull;

#pragma unroll 8
        for (int d = 0; d < 64; ++d) {
            const ulonglong2* ap = (const ulonglong2*)&Qs[d * 128 + ty * 8];
            ulonglong2 a01 = ap[0];
            ulonglong2 a23 = ap[1];
            unsigned long long av[4] = { a01.x, a01.y, a23.x, a23.y };
            float4 bf = *(const float4*)&Ks[d * 64 + tx * 4];
            unsigned long long bd[4] = { dup2(bf.x), dup2(bf.y), dup2(bf.z), dup2(bf.w) };
#pragma unroll
            for (int p = 0; p < 4; ++p)
#pragma unroll
                for (int j = 0; j < 4; ++j)
                    FMA2(Sp[p][j], av[p], bd[j]);
        }

        // unpack, scale + causal mask + online softmax (pairwise O rescale)
        float S[8][4];
#pragma unroll
        for (int p = 0; p < 4; ++p)
#pragma unroll
            for (int j = 0; j < 4; ++j)
                unpack2(Sp[p][j], S[2 * p][j], S[2 * p + 1][j]);

        const bool msk = (kt >= 2 * qi);
#pragma unroll
        for (int p = 0; p < 4; ++p) {
            float alpha2[2];
#pragma unroll
            for (int half = 0; half < 2; ++half) {
                const int i    = 2 * p + half;
                const int grow = qi * 128 + ty * 8 + i;
#pragma unroll
                for (int j = 0; j < 4; ++j) {
                    float s = S[i][j] * scale;
                    if (msk && (kt * 64 + tx * 4 + j > grow)) s = NEG_INF;
                    S[i][j] = s;
                }
                float mx = fmaxf(fmaxf(S[i][0], S[i][1]), fmaxf(S[i][2], S[i][3]));
#pragma unroll
                for (int off = 1; off < 16; off <<= 1)
                    mx = fmaxf(mx, __shfl_xor_sync(0xffffffffu, mx, off));
                const float mn = fmaxf(m_i[i], mx);
                float sum = 0.f;
#pragma unroll
                for (int j = 0; j < 4; ++j) {
                    float pv = __expf(S[i][j] - mn);
                    S[i][j] = pv;
                    sum += pv;
                }
#pragma unroll
                for (int off = 1; off < 16; off <<= 1)
                    sum += __shfl_xor_sync(0xffffffffu, sum, off);
                const float al = __expf(m_i[i] - mn);
                l_i[i] = l_i[i] * al + sum;
                m_i[i] = mn;
                alpha2[half] = al;
            }
            const unsigned long long ap2 = pack2(alpha2[0], alpha2[1]);
#pragma unroll
            for (int j = 0; j < 4; ++j) MUL2ACC(Op[p][j], ap2);
        }

        // store P transposed+swizzled: two STS.128 per column
#pragma unroll
        for (int j = 0; j < 4; ++j) {
            const int c    = tx * 4 + j;
            const int swz  = (tx & 7) << 2;          // ((c>>2)&7)*4
            const int base = ty * 8 + swz;
            *(float4*)&Ps[c * 128 + (base & 127)] =
                make_float4(S[0][j], S[1][j], S[2][j], S[3][j]);
            *(float4*)&Ps[c * 128 + ((base + 4) & 127)] =
                make_float4(S[4][j], S[5][j], S[6][j], S[7][j]);
        }
        __syncthreads();

        // O += P @ V
#pragma unroll 8
        for (int c = 0; c < 64; ++c) {
            const int swz  = ((c >> 2) & 7) << 2;
            const int base = ty * 8 + swz;
            ulonglong2 a01 = *(const ulonglong2*)&Ps[c * 128 + (base & 127)];
            ulonglong2 a23 = *(const ulonglong2*)&Ps[c * 128 + ((base + 4) & 127)];
            unsigned long long av[4] = { a01.x, a01.y, a23.x, a23.y };
            float4 vf = *(const float4*)&Vs[c * 68 + tx * 4];
            unsigned long long bd[4] = { dup2(vf.x), dup2(vf.y), dup2(vf.z), dup2(vf.w) };
#pragma unroll
            for (int p = 0; p < 4; ++p)
#pragma unroll
                for (int j = 0; j < 4; ++j)
                    FMA2(Op[p][j], av[p], bd[j]);
        }
    }

    // normalize + write heads output into concat layout [b, k, h*64 + v]
#pragma unroll
    for (int p = 0; p < 4; ++p) {
        float lo[4], hi[4];
#pragma unroll
        for (int j = 0; j < 4; ++j) unpack2(Op[p][j], lo[j], hi[j]);
        const float inv0 = 1.f / l_i[2 * p];
        const float inv1 = 1.f / l_i[2 * p + 1];
        float* o0 = g_ct + plane + (size_t)(qi * 128 + ty * 8 + 2 * p) * 512 + tx * 4;
        float* o1 = o0 + 512;
        *(float4*)o0 = make_float4(lo[0] * inv0, lo[1] * inv0, lo[2] * inv0, lo[3] * inv0);
        *(float4*)o1 = make_float4(hi[0] * inv1, hi[1] * inv1, hi[2] * inv1, hi[3] * inv1);
    }
}

// ---------------------------------------------------------------------------
// Launch: 3 projections -> attention -> output projection (one stream, serial)
// ---------------------------------------------------------------------------
extern "C" void kernel_launch(void* const* d_in, const int* in_sizes, int n_in,
                              void* d_out, int out_size)
{
    const float* query = (const float*)d_in[0];
    const float* key_  = (const float*)d_in[1];
    const float* value = (const float*)d_in[2];
    const float* W_q   = (const float*)d_in[3];
    const float* b_q   = (const float*)d_in[4];
    const float* W_k   = (const float*)d_in[5];
    const float* b_k   = (const float*)d_in[6];
    const float* W_v   = (const float*)d_in[7];
    const float* b_v   = (const float*)d_in[8];
    const float* W_o   = (const float*)d_in[9];
    const float* b_o   = (const float*)d_in[10];
    float* out = (float*)d_out;

    cudaFuncSetAttribute(attn_kernel, cudaFuncAttributeMaxDynamicSharedMemorySize,
                         ATTN_SMEM_BYTES);

    dim3 gg(64, 8);   // 8192/128 row tiles x 8 col tiles (heads / N-slices)

    // q/k/v projections: per-head weight blocks [512,64], ldb=64
    gemm512_kernel<<<gg, 128>>>(query, W_q, b_q, nullptr, 512 * 64, 64, 0, 1);
    gemm512_kernel<<<gg, 128>>>(key_,  W_k, b_k, nullptr, 512 * 64, 64, 0, 2);
    gemm512_kernel<<<gg, 128>>>(value, W_v, b_v, nullptr, 512 * 64, 64, 0, 3);

    // causal attention: 16 q-tiles (Br=128) x 32 (b,h) planes
    attn_kernel<<<dim3(16, 32), 256, ATTN_SMEM_BYTES>>>();

    // output projection: concat [8192,512] @ W_o [512,512] + b_o
    gemm512_kernel<<<gg, 128>>>(nullptr, W_o, b_o, out, 64, 512, 1, 0);
}

// round 9
// speedup vs baseline: 1.4358x; 1.3220x over previous
#include <cuda_runtime.h>
#include <cuda_bf16.h>
#include <cstdint>

// Problem constants
#define NB     4
#define KWIN   2048
#define DMODEL 512
#define NHEAD  8
#define HDIM   64

// Scratch (allocation-free rule: __device__ globals).
// Layout for all four: [B, K, H*64] row-major == [8192, 512]
__device__ float g_qp[NB * KWIN * DMODEL];
__device__ float g_kp[NB * KWIN * DMODEL];
__device__ float g_vp[NB * KWIN * DMODEL];
__device__ float g_ct[NB * KWIN * DMODEL];

// Pre-transposed, bf16-split weights: 32 blocks of [64 n][512 k]
//   blocks 0-7: W_q heads, 8-15: W_k, 16-23: W_v, 24-31: W_o n-column slices
__device__ __nv_bfloat16 g_wthi[32 * 64 * 512];
__device__ __nv_bfloat16 g_wtlo[32 * 64 * 512];

// ---------------------------------------------------------------------------
// Helpers
// ---------------------------------------------------------------------------
__device__ __forceinline__ uint32_t smem_u32(const void* p) {
    uint32_t a;
    asm("{ .reg .u64 t; cvta.to.shared.u64 t, %1; cvt.u32.u64 %0, t; }"
        : "=r"(a) : "l"(p));
    return a;
}
__device__ __forceinline__ uint32_t sw128(uint32_t off) {
    return off ^ ((off >> 3) & 0x70);
}
__device__ __forceinline__ void ldsm_x4(uint32_t& r0, uint32_t& r1,
                                        uint32_t& r2, uint32_t& r3, uint32_t addr) {
    asm volatile("ldmatrix.sync.aligned.m8n8.x4.shared.b16 {%0,%1,%2,%3}, [%4];"
                 : "=r"(r0), "=r"(r1), "=r"(r2), "=r"(r3) : "r"(addr));
}
__device__ __forceinline__ void mma_bf16(float* c, const uint32_t* a, const uint32_t* b) {
    asm volatile(
        "mma.sync.aligned.m16n8k16.row.col.f32.bf16.bf16.f32 "
        "{%0,%1,%2,%3}, {%4,%5,%6,%7}, {%8,%9}, {%0,%1,%2,%3};"
        : "+f"(c[0]), "+f"(c[1]), "+f"(c[2]), "+f"(c[3])
        : "r"(a[0]), "r"(a[1]), "r"(a[2]), "r"(a[3]), "r"(b[0]), "r"(b[1]));
}

// Packed fp32x2 helpers (attention kernel)
__device__ __forceinline__ unsigned long long dup2(float x) {
    unsigned long long r;
    asm("mov.b64 %0, {%1, %1};" : "=l"(r) : "r"(__float_as_uint(x)));
    return r;
}
__device__ __forceinline__ unsigned long long pack2(float x, float y) {
    unsigned long long r;
    asm("mov.b64 %0, {%1, %2};" : "=l"(r) : "r"(__float_as_uint(x)), "r"(__float_as_uint(y)));
    return r;
}
__device__ __forceinline__ void unpack2(unsigned long long v, float& lo, float& hi) {
    unsigned a, b;
    asm("mov.b64 {%0, %1}, %2;" : "=r"(a), "=r"(b) : "l"(v));
    lo = __uint_as_float(a);
    hi = __uint_as_float(b);
}
#define FMA2(d, a, b) asm("fma.rn.f32x2 %0, %1, %2, %0;" : "+l"(d) : "l"(a), "l"(b))
#define MUL2ACC(d, s)  asm("mul.rn.f32x2 %0, %0, %1;"     : "+l"(d) : "l"(s))

// ---------------------------------------------------------------------------
// Weight prep: W[k][n] fp32 (per block) -> [n][512 k] bf16 hi/lo, transposed.
//   grid = (8 k-tiles, 8 blocks), block = 256
// ---------------------------------------------------------------------------
__global__ __launch_bounds__(256)
void prep_w_kernel(const float* __restrict__ W, int wstride_y, int ldb, int blkbase)
{
    __shared__ float s[64][65];
    const int kt  = blockIdx.x;
    const int nb  = blockIdx.y;
    const int tid = threadIdx.x;
    const float* Wt = W + (size_t)nb * wstride_y;

#pragma unroll
    for (int j = 0; j < 16; ++j) {
        int f = tid + 256 * j;          // 0..4095
        int k = f >> 6, n = f & 63;
        s[k][n] = Wt[(size_t)(kt * 64 + k) * ldb + n];
    }
    __syncthreads();
#pragma unroll
    for (int j = 0; j < 16; ++j) {
        int f = tid + 256 * j;
        int n = f >> 6, k = f & 63;
        float x = s[k][n];
        __nv_bfloat16 hi = __float2bfloat16_rn(x);
        __nv_bfloat16 lo = __float2bfloat16_rn(x - __bfloat162float(hi));
        size_t o = (size_t)(blkbase + nb) * (64 * 512) + (size_t)n * 512 + kt * 64 + k;
        g_wthi[o] = hi;
        g_wtlo[o] = lo;
    }
}

// ---------------------------------------------------------------------------
// HMMA bf16-split GEMM (mma.sync, base-ISA -> compiles at .target sm_103):
//   C[m, nb*64+n] = X[m,:] (512) @ W + bias, fp32-accurate via 3-term split.
//   grid = (64, 8), block = 256 (8 warps, 4x2 warp grid, 32x32 per warp).
//   K in 8 chunks of 64; A converted fp32->bf16 hi/lo inline; B prepped.
//   Smem: Ahi/Alo [128][64] bf16 + Bhi/Blo [64][64] bf16 = 48 KB, sw128.
// ---------------------------------------------------------------------------
__global__ __launch_bounds__(256)
void gemm_mma_kernel(const float* X, int blkbase,
                     const float* __restrict__ bias, float* out,
                     int xsel, int osel)
{
    __shared__ __align__(1024) __nv_bfloat16 sAhi[128 * 64];
    __shared__ __align__(1024) __nv_bfloat16 sAlo[128 * 64];
    __shared__ __align__(1024) __nv_bfloat16 sBhi[64 * 64];
    __shared__ __align__(1024) __nv_bfloat16 sBlo[64 * 64];

    const float* Xp = xsel ? (const float*)g_ct : X;
    float* op = out;
    if (osel == 1) op = g_qp;
    else if (osel == 2) op = g_kp;
    else if (osel == 3) op = g_vp;

    const int tid  = threadIdx.x;
    const int lane = tid & 31;
    const int wid  = tid >> 5;
    const int wm   = wid >> 1;       // 0..3 -> rows wm*32..+31
    const int wn   = wid & 1;        // 0..1 -> cols wn*32..+31
    const int m0   = blockIdx.x * 128;
    const int nb   = blockIdx.y;
    const size_t wbase = (size_t)(blkbase + nb) * (64 * 512);

    const uint32_t aHiB = smem_u32(sAhi);
    const uint32_t aLoB = smem_u32(sAlo);
    const uint32_t bHiB = smem_u32(sBhi);
    const uint32_t bLoB = smem_u32(sBlo);

    float C[2][4][4];
#pragma unroll
    for (int mi = 0; mi < 2; ++mi)
#pragma unroll
        for (int ni = 0; ni < 4; ++ni)
#pragma unroll
            for (int q = 0; q < 4; ++q) C[mi][ni][q] = 0.f;

    for (int ck = 0; ck < 8; ++ck) {
        const int k0 = ck * 64;
        __syncthreads();   // previous chunk's compute done reading smem

        // ---- A: load X[128 x 64] fp32, split bf16 hi/lo, swizzled store
#pragma unroll
        for (int j = 0; j < 8; ++j) {
            int f   = tid + 256 * j;          // 0..2047
            int row = f >> 4;                 // 0..127
            int kq  = (f & 15) << 2;          // 0..60
            float4 v = *(const float4*)(Xp + (size_t)(m0 + row) * 512 + k0 + kq);
            __nv_bfloat16 hx = __float2bfloat16_rn(v.x);
            __nv_bfloat16 hy = __float2bfloat16_rn(v.y);
            __nv_bfloat16 hz = __float2bfloat16_rn(v.z);
            __nv_bfloat16 hw = __float2bfloat16_rn(v.w);
            __nv_bfloat16 lx = __float2bfloat16_rn(v.x - __bfloat162float(hx));
            __nv_bfloat16 ly = __float2bfloat16_rn(v.y - __bfloat162float(hy));
            __nv_bfloat16 lz = __float2bfloat16_rn(v.z - __bfloat162float(hz));
            __nv_bfloat16 lw = __float2bfloat16_rn(v.w - __bfloat162float(hw));
            __nv_bfloat162 h0, h1, l0, l1;
            h0.x = hx; h0.y = hy; h1.x = hz; h1.y = hw;
            l0.x = lx; l0.y = ly; l1.x = lz; l1.y = lw;
            uint2 uh, ul;
            uh.x = *reinterpret_cast<uint32_t*>(&h0);
            uh.y = *reinterpret_cast<uint32_t*>(&h1);
            ul.x = *reinterpret_cast<uint32_t*>(&l0);
            ul.y = *reinterpret_cast<uint32_t*>(&l1);
            uint32_t sw = sw128((uint32_t)(row * 128 + (kq << 1)));
            *(uint2*)((char*)sAhi + sw) = uh;
            *(uint2*)((char*)sAlo + sw) = ul;
        }
        // ---- B: prepped bf16 [64 n][512 k], load chunk, swizzled store
#pragma unroll
        for (int j = 0; j < 4; ++j) {
            int f  = tid + 256 * j;           // 0..1023
            int n  = f >> 4;                  // 0..63
            int kq = (f & 15) << 2;           // 0..60
            size_t src = wbase + (size_t)n * 512 + k0 + kq;
            uint2 vh = *(const uint2*)(g_wthi + src);
            uint2 vl = *(const uint2*)(g_wtlo + src);
            uint32_t sw = sw128((uint32_t)(n * 128 + (kq << 1)));
            *(uint2*)((char*)sBhi + sw) = vh;
            *(uint2*)((char*)sBlo + sw) = vl;
        }
        __syncthreads();

        // ---- 4 k16 steps of HMMA, 3-term split
#pragma unroll
        for (int ks = 0; ks < 4; ++ks) {
            const int kb = ks * 32 + ((lane >> 4) << 4);   // byte offset in row
            uint32_t ahi[2][4], alo[2][4];
            const int arow = wm * 32 + (lane & 15);
#pragma unroll
            for (int mi = 0; mi < 2; ++mi) {
                uint32_t off = sw128((uint32_t)((arow + mi * 16) * 128 + kb));
                ldsm_x4(ahi[mi][0], ahi[mi][1], ahi[mi][2], ahi[mi][3], aHiB + off);
                ldsm_x4(alo[mi][0], alo[mi][1], alo[mi][2], alo[mi][3], aLoB + off);
            }
            uint32_t bh[2][4], bl[2][4];
            const int brow = wn * 32 + (lane & 15);
#pragma unroll
            for (int half = 0; half < 2; ++half) {
                uint32_t off = sw128((uint32_t)((brow + half * 16) * 128 + kb));
                ldsm_x4(bh[half][0], bh[half][1], bh[half][2], bh[half][3], bHiB + off);
                ldsm_x4(bl[half][0], bl[half][1], bl[half][2], bl[half][3], bLoB + off);
            }
#pragma unroll
            for (int mi = 0; mi < 2; ++mi)
#pragma unroll
                for (int ni = 0; ni < 4; ++ni) {
                    uint32_t bfh[2] = { bh[ni >> 1][ni & 1], bh[ni >> 1][(ni & 1) + 2] };
                    uint32_t bfl[2] = { bl[ni >> 1][ni & 1], bl[ni >> 1][(ni & 1) + 2] };
                    mma_bf16(C[mi][ni], ahi[mi], bfh);
                    mma_bf16(C[mi][ni], ahi[mi], bfl);
                    mma_bf16(C[mi][ni], alo[mi], bfh);
                }
        }
    }

    // Epilogue: fragment rows groupID/+8, cols 2*(lane&3)/+1
#pragma unroll
    for (int mi = 0; mi < 2; ++mi) {
        const int r = m0 + wm * 32 + mi * 16 + (lane >> 2);
#pragma unroll
        for (int ni = 0; ni < 4; ++ni) {
            const int col = nb * 64 + wn * 32 + ni * 8 + ((lane & 3) << 1);
            float2 bb = *(const float2*)(bias + col);
            float2 v0, v1;
            v0.x = C[mi][ni][0] + bb.x; v0.y = C[mi][ni][1] + bb.y;
            v1.x = C[mi][ni][2] + bb.x; v1.y = C[mi][ni][3] + bb.y;
            *(float2*)(op + (size_t)r * 512 + col)       = v0;
            *(float2*)(op + (size_t)(r + 8) * 512 + col) = v1;
        }
    }
}

// ---------------------------------------------------------------------------
// Causal flash attention, fp32 with FFMA2 GEMM loops. (unchanged, Round 7)
// ---------------------------------------------------------------------------
#define ATTN_SMEM_BYTES ((64*128 + 64*64 + 64*68 + 64*128) * 4)

__global__ __launch_bounds__(256, 2)
void attn_kernel()
{
    extern __shared__ __align__(16) float sm[];
    float* Qs = sm;                    // [d][r]  stride 128
    float* Ks = sm + 64 * 128;         // [d][c]  stride 64
    float* Vs = Ks + 64 * 64;          // [c][v]  stride 68 (pad: bank spread)
    float* Ps = Vs + 64 * 68;          // [c][r]  stride 128, swizzled

    const int qi  = 15 - (int)blockIdx.x;   // big tiles first
    const int bh  = blockIdx.y;
    const int b   = bh >> 3;
    const int h   = bh & 7;
    const int tid = threadIdx.x;
    const int tx  = tid & 15;          // 4 key/value cols: tx*4..+3
    const int ty  = tid >> 4;          // 8 q rows: ty*8..+7
    const float scale   = 0.022097086912079608f;  // 1/sqrt(2048)
    const float NEG_INF = __int_as_float(0xff800000);

    const size_t plane = (size_t)b * (KWIN * DMODEL) + (size_t)h * 64;

    // Load Q tile transposed: Qs[d][r], rows qi*128..+127
    {
        int r  = tid >> 1;             // 0..127
        int d0 = (tid & 1) << 5;       // 0 or 32
        const float* src = g_qp + plane + (size_t)(qi * 128 + r) * 512 + d0;
#pragma unroll
        for (int k = 0; k < 8; ++k) {
            float4 v = *(const float4*)(src + k * 4);
            int d = d0 + k * 4;
            Qs[(d + 0) * 128 + r] = v.x;
            Qs[(d + 1) * 128 + r] = v.y;
            Qs[(d + 2) * 128 + r] = v.z;
            Qs[(d + 3) * 128 + r] = v.w;
        }
    }

    unsigned long long Op[4][4];       // row-pairs x 4 v-cols
    float m_i[8], l_i[8];
#pragma unroll
    for (int p = 0; p < 4; ++p)
#pragma unroll
        for (int j = 0; j < 4; ++j) Op[p][j] = 0ull;
#pragma unroll
    for (int i = 0; i < 8; ++i) { m_i[i] = NEG_INF; l_i[i] = 0.f; }

    const int ktmax = 2 * qi + 1;
    for (int kt = 0; kt <= ktmax; ++kt) {
        __syncthreads();   // prev chunk done reading Ks/Vs/Ps
        {
            int c  = tid & 63;
            int d0 = (tid >> 6) << 4;  // 0,16,32,48
            const float* ksrc = g_kp + plane + (size_t)(kt * 64 + c) * 512 + d0;
            const float* vsrc = g_vp + plane + (size_t)(kt * 64 + c) * 512 + d0;
#pragma unroll
            for (int k2 = 0; k2 < 4; ++k2) {
                float4 v = *(const float4*)(ksrc + k2 * 4);
                int d = d0 + k2 * 4;
                Ks[(d + 0) * 64 + c] = v.x;
                Ks[(d + 1) * 64 + c] = v.y;
                Ks[(d + 2) * 64 + c] = v.z;
                Ks[(d + 3) * 64 + c] = v.w;
            }
#pragma unroll
            for (int k2 = 0; k2 < 4; ++k2)
                *(float4*)&Vs[c * 68 + d0 + k2 * 4] = *(const float4*)(vsrc + k2 * 4);
        }
        __syncthreads();

        // S = Q^T K  (8x4 per thread as 4 row-pairs)
        unsigned long long Sp[4][4];
#pragma unroll
        for (int p = 0; p < 4; ++p)
#pragma unroll
            for (int j = 0; j < 4; ++j) Sp[p][j] = 0ull;

#pragma unroll 8
        for (int d = 0; d < 64; ++d) {
            const ulonglong2* ap = (const ulonglong2*)&Qs[d * 128 + ty * 8];
            ulonglong2 a01 = ap[0];
            ulonglong2 a23 = ap[1];
            unsigned long long av[4] = { a01.x, a01.y, a23.x, a23.y };
            float4 bf = *(const float4*)&Ks[d * 64 + tx * 4];
            unsigned long long bd[4] = { dup2(bf.x), dup2(bf.y), dup2(bf.z), dup2(bf.w) };
#pragma unroll
            for (int p = 0; p < 4; ++p)
#pragma unroll
                for (int j = 0; j < 4; ++j)
                    FMA2(Sp[p][j], av[p], bd[j]);
        }

        // unpack, scale + causal mask + online softmax (pairwise O rescale)
        float S[8][4];
#pragma unroll
        for (int p = 0; p < 4; ++p)
#pragma unroll
            for (int j = 0; j < 4; ++j)
                unpack2(Sp[p][j], S[2 * p][j], S[2 * p + 1][j]);

        const bool msk = (kt >= 2 * qi);
#pragma unroll
        for (int p = 0; p < 4; ++p) {
            float alpha2[2];
#pragma unroll
            for (int half = 0; half < 2; ++half) {
                const int i    = 2 * p + half;
                const int grow = qi * 128 + ty * 8 + i;
#pragma unroll
                for (int j = 0; j < 4; ++j) {
                    float s = S[i][j] * scale;
                    if (msk && (kt * 64 + tx * 4 + j > grow)) s = NEG_INF;
                    S[i][j] = s;
                }
                float mx = fmaxf(fmaxf(S[i][0], S[i][1]), fmaxf(S[i][2], S[i][3]));
#pragma unroll
                for (int off = 1; off < 16; off <<= 1)
                    mx = fmaxf(mx, __shfl_xor_sync(0xffffffffu, mx, off));
                const float mn = fmaxf(m_i[i], mx);
                float sum = 0.f;
#pragma unroll
                for (int j = 0; j < 4; ++j) {
                    float pv = __expf(S[i][j] - mn);
                    S[i][j] = pv;
                    sum += pv;
                }
#pragma unroll
                for (int off = 1; off < 16; off <<= 1)
                    sum += __shfl_xor_sync(0xffffffffu, sum, off);
                const float al = __expf(m_i[i] - mn);
                l_i[i] = l_i[i] * al + sum;
                m_i[i] = mn;
                alpha2[half] = al;
            }
            const unsigned long long ap2 = pack2(alpha2[0], alpha2[1]);
#pragma unroll
            for (int j = 0; j < 4; ++j) MUL2ACC(Op[p][j], ap2);
        }

        __syncthreads();   // all threads done reading Ps (prev) / Ks as K
        // store P transposed+swizzled: two STS.128 per column
#pragma unroll
        for (int j = 0; j < 4; ++j) {
            const int c    = tx * 4 + j;
            const int swz  = (tx & 7) << 2;          // ((c>>2)&7)*4
            const int base = ty * 8 + swz;
            *(float4*)&Ps[c * 128 + (base & 127)] =
                make_float4(S[0][j], S[1][j], S[2][j], S[3][j]);
            *(float4*)&Ps[c * 128 + ((base + 4) & 127)] =
                make_float4(S[4][j], S[5][j], S[6][j], S[7][j]);
        }
        __syncthreads();

        // O += P @ V
#pragma unroll 8
        for (int c = 0; c < 64; ++c) {
            const int swz  = ((c >> 2) & 7) << 2;
            const int base = ty * 8 + swz;
            ulonglong2 a01 = *(const ulonglong2*)&Ps[c * 128 + (base & 127)];
            ulonglong2 a23 = *(const ulonglong2*)&Ps[c * 128 + ((base + 4) & 127)];
            unsigned long long av[4] = { a01.x, a01.y, a23.x, a23.y };
            float4 vf = *(const float4*)&Vs[c * 68 + tx * 4];
            unsigned long long bd[4] = { dup2(vf.x), dup2(vf.y), dup2(vf.z), dup2(vf.w) };
#pragma unroll
            for (int p = 0; p < 4; ++p)
#pragma unroll
                for (int j = 0; j < 4; ++j)
                    FMA2(Op[p][j], av[p], bd[j]);
        }
    }

    // normalize + write heads output into concat layout [b, k, h*64 + v]
#pragma unroll
    for (int p = 0; p < 4; ++p) {
        float lo[4], hi[4];
#pragma unroll
        for (int j = 0; j < 4; ++j) unpack2(Op[p][j], lo[j], hi[j]);
        const float inv0 = 1.f / l_i[2 * p];
        const float inv1 = 1.f / l_i[2 * p + 1];
        float* o0 = g_ct + plane + (size_t)(qi * 128 + ty * 8 + 2 * p) * 512 + tx * 4;
        float* o1 = o0 + 512;
        *(float4*)o0 = make_float4(lo[0] * inv0, lo[1] * inv0, lo[2] * inv0, lo[3] * inv0);
        *(float4*)o1 = make_float4(hi[0] * inv1, hi[1] * inv1, hi[2] * inv1, hi[3] * inv1);
    }
}

// ---------------------------------------------------------------------------
// Launch: weight prep -> 3 HMMA projections -> attention -> HMMA output proj
// ---------------------------------------------------------------------------
extern "C" void kernel_launch(void* const* d_in, const int* in_sizes, int n_in,
                              void* d_out, int out_size)
{
    const float* query = (const float*)d_in[0];
    const float* key_  = (const float*)d_in[1];
    const float* value = (const float*)d_in[2];
    const float* W_q   = (const float*)d_in[3];
    const float* b_q   = (const float*)d_in[4];
    const float* W_k   = (const float*)d_in[5];
    const float* b_k   = (const float*)d_in[6];
    const float* W_v   = (const float*)d_in[7];
    const float* b_v   = (const float*)d_in[8];
    const float* W_o   = (const float*)d_in[9];
    const float* b_o   = (const float*)d_in[10];
    float* out = (float*)d_out;

    cudaFuncSetAttribute(attn_kernel, cudaFuncAttributeMaxDynamicSharedMemorySize,
                         ATTN_SMEM_BYTES);

    // Weight prep: transpose + bf16 split into g_wthi/g_wtlo (32 blocks)
    prep_w_kernel<<<dim3(8, 8), 256>>>(W_q, 512 * 64, 64, 0);
    prep_w_kernel<<<dim3(8, 8), 256>>>(W_k, 512 * 64, 64, 8);
    prep_w_kernel<<<dim3(8, 8), 256>>>(W_v, 512 * 64, 64, 16);
    prep_w_kernel<<<dim3(8, 8), 256>>>(W_o, 64, 512, 24);

    dim3 gg(64, 8);   // 8192/128 row tiles x 8 blocks (heads / N-slices)

    gemm_mma_kernel<<<gg, 256>>>(query, 0,  b_q, nullptr, 0, 1);
    gemm_mma_kernel<<<gg, 256>>>(key_,  8,  b_k, nullptr, 0, 2);
    gemm_mma_kernel<<<gg, 256>>>(value, 16, b_v, nullptr, 0, 3);

    // causal attention: 16 q-tiles (Br=128) x 32 (b,h) planes
    attn_kernel<<<dim3(16, 32), 256, ATTN_SMEM_BYTES>>>();

    // output projection: concat [8192,512] @ W_o [512,512] + b_o
    gemm_mma_kernel<<<gg, 256>>>(nullptr, 24, b_o, out, 1, 0);
}

// round 10
// speedup vs baseline: 2.6111x; 1.8186x over previous
#include <cuda_runtime.h>
#include <cuda_bf16.h>
#include <cstdint>

// Problem constants
#define NB     4
#define KWIN   2048
#define DMODEL 512
#define NHEAD  8
#define HDIM   64

// Scratch (allocation-free rule: __device__ globals).
// Layout for all four: [B, K, H*64] row-major == [8192, 512]
__device__ float g_qp[NB * KWIN * DMODEL];
__device__ float g_kp[NB * KWIN * DMODEL];
__device__ float g_vp[NB * KWIN * DMODEL];
__device__ float g_ct[NB * KWIN * DMODEL];

// Pre-transposed, bf16-split weights: 32 blocks of [64 n][512 k]
//   blocks 0-7: W_q heads, 8-15: W_k, 16-23: W_v, 24-31: W_o n-column slices
__device__ __nv_bfloat16 g_wthi[32 * 64 * 512];
__device__ __nv_bfloat16 g_wtlo[32 * 64 * 512];

// ---------------------------------------------------------------------------
// Helpers
// ---------------------------------------------------------------------------
__device__ __forceinline__ uint32_t smem_u32(const void* p) {
    uint32_t a;
    asm("{ .reg .u64 t; cvta.to.shared.u64 t, %1; cvt.u32.u64 %0, t; }"
        : "=r"(a) : "l"(p));
    return a;
}
__device__ __forceinline__ uint32_t sw128(uint32_t off) {
    return off ^ ((off >> 3) & 0x70);
}
__device__ __forceinline__ void ldsm_x4(uint32_t& r0, uint32_t& r1,
                                        uint32_t& r2, uint32_t& r3, uint32_t addr) {
    asm volatile("ldmatrix.sync.aligned.m8n8.x4.shared.b16 {%0,%1,%2,%3}, [%4];"
                 : "=r"(r0), "=r"(r1), "=r"(r2), "=r"(r3) : "r"(addr));
}
__device__ __forceinline__ void ldsm_x4_t(uint32_t& r0, uint32_t& r1,
                                          uint32_t& r2, uint32_t& r3, uint32_t addr) {
    asm volatile("ldmatrix.sync.aligned.m8n8.x4.trans.shared.b16 {%0,%1,%2,%3}, [%4];"
                 : "=r"(r0), "=r"(r1), "=r"(r2), "=r"(r3) : "r"(addr));
}
__device__ __forceinline__ void mma_bf16(float* c, const uint32_t* a, const uint32_t* b) {
    asm volatile(
        "mma.sync.aligned.m16n8k16.row.col.f32.bf16.bf16.f32 "
        "{%0,%1,%2,%3}, {%4,%5,%6,%7}, {%8,%9}, {%0,%1,%2,%3};"
        : "+f"(c[0]), "+f"(c[1]), "+f"(c[2]), "+f"(c[3])
        : "r"(a[0]), "r"(a[1]), "r"(a[2]), "r"(a[3]), "r"(b[0]), "r"(b[1]));
}
// pack two fp32 -> bf16x2 reg: low half = p0, high half = p1
__device__ __forceinline__ uint32_t pack_bf16x2(float p0, float p1) {
    uint32_t d;
    asm("cvt.rn.bf16x2.f32 %0, %1, %2;" : "=r"(d) : "f"(p1), "f"(p0));
    return d;
}

// ---------------------------------------------------------------------------
// Weight prep: W[k][n] fp32 (per block) -> [n][512 k] bf16 hi/lo, transposed.
//   grid = (8 k-tiles, 8 blocks), block = 256
// ---------------------------------------------------------------------------
__global__ __launch_bounds__(256)
void prep_w_kernel(const float* __restrict__ W, int wstride_y, int ldb, int blkbase)
{
    __shared__ float s[64][65];
    const int kt  = blockIdx.x;
    const int nb  = blockIdx.y;
    const int tid = threadIdx.x;
    const float* Wt = W + (size_t)nb * wstride_y;

#pragma unroll
    for (int j = 0; j < 16; ++j) {
        int f = tid + 256 * j;          // 0..4095
        int k = f >> 6, n = f & 63;
        s[k][n] = Wt[(size_t)(kt * 64 + k) * ldb + n];
    }
    __syncthreads();
#pragma unroll
    for (int j = 0; j < 16; ++j) {
        int f = tid + 256 * j;
        int n = f >> 6, k = f & 63;
        float x = s[k][n];
        __nv_bfloat16 hi = __float2bfloat16_rn(x);
        __nv_bfloat16 lo = __float2bfloat16_rn(x - __bfloat162float(hi));
        size_t o = (size_t)(blkbase + nb) * (64 * 512) + (size_t)n * 512 + kt * 64 + k;
        g_wthi[o] = hi;
        g_wtlo[o] = lo;
    }
}

// ---------------------------------------------------------------------------
// HMMA bf16-split GEMM (unchanged from Round 9 passing version)
// ---------------------------------------------------------------------------
__global__ __launch_bounds__(256)
void gemm_mma_kernel(const float* X, int blkbase,
                     const float* __restrict__ bias, float* out,
                     int xsel, int osel)
{
    __shared__ __align__(1024) __nv_bfloat16 sAhi[128 * 64];
    __shared__ __align__(1024) __nv_bfloat16 sAlo[128 * 64];
    __shared__ __align__(1024) __nv_bfloat16 sBhi[64 * 64];
    __shared__ __align__(1024) __nv_bfloat16 sBlo[64 * 64];

    const float* Xp = xsel ? (const float*)g_ct : X;
    float* op = out;
    if (osel == 1) op = g_qp;
    else if (osel == 2) op = g_kp;
    else if (osel == 3) op = g_vp;

    const int tid  = threadIdx.x;
    const int lane = tid & 31;
    const int wid  = tid >> 5;
    const int wm   = wid >> 1;       // 0..3 -> rows wm*32..+31
    const int wn   = wid & 1;        // 0..1 -> cols wn*32..+31
    const int m0   = blockIdx.x * 128;
    const int nb   = blockIdx.y;
    const size_t wbase = (size_t)(blkbase + nb) * (64 * 512);

    const uint32_t aHiB = smem_u32(sAhi);
    const uint32_t aLoB = smem_u32(sAlo);
    const uint32_t bHiB = smem_u32(sBhi);
    const uint32_t bLoB = smem_u32(sBlo);

    float C[2][4][4];
#pragma unroll
    for (int mi = 0; mi < 2; ++mi)
#pragma unroll
        for (int ni = 0; ni < 4; ++ni)
#pragma unroll
            for (int q = 0; q < 4; ++q) C[mi][ni][q] = 0.f;

    for (int ck = 0; ck < 8; ++ck) {
        const int k0 = ck * 64;
        __syncthreads();   // previous chunk's compute done reading smem

        // ---- A: load X[128 x 64] fp32, split bf16 hi/lo, swizzled store
#pragma unroll
        for (int j = 0; j < 8; ++j) {
            int f   = tid + 256 * j;          // 0..2047
            int row = f >> 4;                 // 0..127
            int kq  = (f & 15) << 2;          // 0..60
            float4 v = *(const float4*)(Xp + (size_t)(m0 + row) * 512 + k0 + kq);
            __nv_bfloat16 hx = __float2bfloat16_rn(v.x);
            __nv_bfloat16 hy = __float2bfloat16_rn(v.y);
            __nv_bfloat16 hz = __float2bfloat16_rn(v.z);
            __nv_bfloat16 hw = __float2bfloat16_rn(v.w);
            __nv_bfloat16 lx = __float2bfloat16_rn(v.x - __bfloat162float(hx));
            __nv_bfloat16 ly = __float2bfloat16_rn(v.y - __bfloat162float(hy));
            __nv_bfloat16 lz = __float2bfloat16_rn(v.z - __bfloat162float(hz));
            __nv_bfloat16 lw = __float2bfloat16_rn(v.w - __bfloat162float(hw));
            __nv_bfloat162 h0, h1, l0, l1;
            h0.x = hx; h0.y = hy; h1.x = hz; h1.y = hw;
            l0.x = lx; l0.y = ly; l1.x = lz; l1.y = lw;
            uint2 uh, ul;
            uh.x = *reinterpret_cast<uint32_t*>(&h0);
            uh.y = *reinterpret_cast<uint32_t*>(&h1);
            ul.x = *reinterpret_cast<uint32_t*>(&l0);
            ul.y = *reinterpret_cast<uint32_t*>(&l1);
            uint32_t sw = sw128((uint32_t)(row * 128 + (kq << 1)));
            *(uint2*)((char*)sAhi + sw) = uh;
            *(uint2*)((char*)sAlo + sw) = ul;
        }
        // ---- B: prepped bf16 [64 n][512 k], load chunk, swizzled store
#pragma unroll
        for (int j = 0; j < 4; ++j) {
            int f  = tid + 256 * j;           // 0..1023
            int n  = f >> 4;                  // 0..63
            int kq = (f & 15) << 2;           // 0..60
            size_t src = wbase + (size_t)n * 512 + k0 + kq;
            uint2 vh = *(const uint2*)(g_wthi + src);
            uint2 vl = *(const uint2*)(g_wtlo + src);
            uint32_t sw = sw128((uint32_t)(n * 128 + (kq << 1)));
            *(uint2*)((char*)sBhi + sw) = vh;
            *(uint2*)((char*)sBlo + sw) = vl;
        }
        __syncthreads();

        // ---- 4 k16 steps of HMMA, 3-term split
#pragma unroll
        for (int ks = 0; ks < 4; ++ks) {
            const int kb = ks * 32 + ((lane >> 4) << 4);   // byte offset in row
            uint32_t ahi[2][4], alo[2][4];
            const int arow = wm * 32 + (lane & 15);
#pragma unroll
            for (int mi = 0; mi < 2; ++mi) {
                uint32_t off = sw128((uint32_t)((arow + mi * 16) * 128 + kb));
                ldsm_x4(ahi[mi][0], ahi[mi][1], ahi[mi][2], ahi[mi][3], aHiB + off);
                ldsm_x4(alo[mi][0], alo[mi][1], alo[mi][2], alo[mi][3], aLoB + off);
            }
            uint32_t bh[2][4], bl[2][4];
            const int brow = wn * 32 + (lane & 15);
#pragma unroll
            for (int half = 0; half < 2; ++half) {
                uint32_t off = sw128((uint32_t)((brow + half * 16) * 128 + kb));
                ldsm_x4(bh[half][0], bh[half][1], bh[half][2], bh[half][3], bHiB + off);
                ldsm_x4(bl[half][0], bl[half][1], bl[half][2], bl[half][3], bLoB + off);
            }
#pragma unroll
            for (int mi = 0; mi < 2; ++mi)
#pragma unroll
                for (int ni = 0; ni < 4; ++ni) {
                    uint32_t bfh[2] = { bh[ni >> 1][ni & 1], bh[ni >> 1][(ni & 1) + 2] };
                    uint32_t bfl[2] = { bl[ni >> 1][ni & 1], bl[ni >> 1][(ni & 1) + 2] };
                    mma_bf16(C[mi][ni], ahi[mi], bfh);
                    mma_bf16(C[mi][ni], ahi[mi], bfl);
                    mma_bf16(C[mi][ni], alo[mi], bfh);
                }
        }
    }

    // Epilogue: fragment rows groupID/+8, cols 2*(lane&3)/+1
#pragma unroll
    for (int mi = 0; mi < 2; ++mi) {
        const int r = m0 + wm * 32 + mi * 16 + (lane >> 2);
#pragma unroll
        for (int ni = 0; ni < 4; ++ni) {
            const int col = nb * 64 + wn * 32 + ni * 8 + ((lane & 3) << 1);
            float2 bb = *(const float2*)(bias + col);
            float2 v0, v1;
            v0.x = C[mi][ni][0] + bb.x; v0.y = C[mi][ni][1] + bb.y;
            v1.x = C[mi][ni][2] + bb.x; v1.y = C[mi][ni][3] + bb.y;
            *(float2*)(op + (size_t)r * 512 + col)       = v0;
            *(float2*)(op + (size_t)(r + 8) * 512 + col) = v1;
        }
    }
}

// ---------------------------------------------------------------------------
// Causal flash attention on HMMA (mma.sync bf16, split precision).
//   grid = (16 q-tiles, 32 bh), block = 256 (8 warps; warp w = q rows w*16..+15)
//   Br=128, Bc=64. S: 3-term bf16 split. P@V: phi*Vhi + phi*Vlo + plo*Vhi.
//   P stays in registers (C-fragment == A-fragment layout after bf16x2 pack).
//   Dyn smem 64KB: Qhi/Qlo [128][64]bf16, Khi/Klo [64][64], Vhi/Vlo [64][64].
// ---------------------------------------------------------------------------
#define ATTN_SMEM_BYTES 65536

__global__ __launch_bounds__(256, 2)
void attn_kernel()
{
    extern __shared__ __align__(1024) char smb[];
    const uint32_t QhiB = smem_u32(smb);
    const uint32_t QloB = QhiB + 16384;
    const uint32_t KhiB = QhiB + 32768;
    const uint32_t KloB = QhiB + 40960;
    const uint32_t VhiB = QhiB + 49152;
    const uint32_t VloB = QhiB + 57344;

    const int qi   = 15 - (int)blockIdx.x;   // big tiles first
    const int bh_  = blockIdx.y;
    const int b    = bh_ >> 3;
    const int h    = bh_ & 7;
    const int tid  = threadIdx.x;
    const int lane = tid & 31;
    const int w    = tid >> 5;               // warp: q rows w*16..+15
    const int g    = lane >> 2;              // fragment row group
    const int t2   = (lane & 3) << 1;        // fragment col pair
    const float scale   = 0.022097086912079608f;  // 1/sqrt(2048)
    const float NEG_INF = __int_as_float(0xff800000);

    const size_t plane = (size_t)b * (KWIN * DMODEL) + (size_t)h * 64;

    // ---- Q: load [128 x 64] fp32, split bf16 hi/lo, swizzled store (once)
#pragma unroll
    for (int j = 0; j < 8; ++j) {
        int f   = tid + 256 * j;          // 0..2047 float4 slots
        int row = f >> 4;                 // 0..127
        int kq  = (f & 15) << 2;          // 0..60
        float4 v = *(const float4*)(g_qp + plane + (size_t)(qi * 128 + row) * 512 + kq);
        __nv_bfloat16 hx = __float2bfloat16_rn(v.x);
        __nv_bfloat16 hy = __float2bfloat16_rn(v.y);
        __nv_bfloat16 hz = __float2bfloat16_rn(v.z);
        __nv_bfloat16 hw = __float2bfloat16_rn(v.w);
        __nv_bfloat16 lx = __float2bfloat16_rn(v.x - __bfloat162float(hx));
        __nv_bfloat16 ly = __float2bfloat16_rn(v.y - __bfloat162float(hy));
        __nv_bfloat16 lz = __float2bfloat16_rn(v.z - __bfloat162float(hz));
        __nv_bfloat16 lw = __float2bfloat16_rn(v.w - __bfloat162float(hw));
        __nv_bfloat162 h0, h1, l0, l1;
        h0.x = hx; h0.y = hy; h1.x = hz; h1.y = hw;
        l0.x = lx; l0.y = ly; l1.x = lz; l1.y = lw;
        uint2 uh, ul;
        uh.x = *reinterpret_cast<uint32_t*>(&h0);
        uh.y = *reinterpret_cast<uint32_t*>(&h1);
        ul.x = *reinterpret_cast<uint32_t*>(&l0);
        ul.y = *reinterpret_cast<uint32_t*>(&l1);
        uint32_t sw = sw128((uint32_t)(row * 128 + (kq << 1)));
        *(uint2*)(smb + (QhiB - QhiB) + sw)       = uh;   // sQhi
        *(uint2*)(smb + 16384 + sw)               = ul;   // sQlo
    }

    float O[8][4];
#pragma unroll
    for (int ni = 0; ni < 8; ++ni)
#pragma unroll
        for (int q = 0; q < 4; ++q) O[ni][q] = 0.f;
    float m0 = NEG_INF, m1 = NEG_INF, l0 = 0.f, l1 = 0.f;

    const int ktmax = 2 * qi + 1;
    for (int kt = 0; kt <= ktmax; ++kt) {
        __syncthreads();   // prev chunk compute done reading K/V (and Q stores on kt=0)

        // ---- K,V: load [64 x 64] fp32 each, split bf16 hi/lo, swizzled store
#pragma unroll
        for (int j = 0; j < 4; ++j) {
            int f  = tid + 256 * j;           // 0..1023 float4 slots
            int c  = f >> 4;                  // 0..63
            int kq = (f & 15) << 2;           // 0..60
            uint32_t sw = sw128((uint32_t)(c * 128 + (kq << 1)));
            {
                float4 v = *(const float4*)(g_kp + plane + (size_t)(kt * 64 + c) * 512 + kq);
                __nv_bfloat16 hx = __float2bfloat16_rn(v.x);
                __nv_bfloat16 hy = __float2bfloat16_rn(v.y);
                __nv_bfloat16 hz = __float2bfloat16_rn(v.z);
                __nv_bfloat16 hw = __float2bfloat16_rn(v.w);
                __nv_bfloat16 lx = __float2bfloat16_rn(v.x - __bfloat162float(hx));
                __nv_bfloat16 ly = __float2bfloat16_rn(v.y - __bfloat162float(hy));
                __nv_bfloat16 lz = __float2bfloat16_rn(v.z - __bfloat162float(hz));
                __nv_bfloat16 lw = __float2bfloat16_rn(v.w - __bfloat162float(hw));
                __nv_bfloat162 h0, h1, l0v, l1v;
                h0.x = hx; h0.y = hy; h1.x = hz; h1.y = hw;
                l0v.x = lx; l0v.y = ly; l1v.x = lz; l1v.y = lw;
                uint2 uh, ul;
                uh.x = *reinterpret_cast<uint32_t*>(&h0);
                uh.y = *reinterpret_cast<uint32_t*>(&h1);
                ul.x = *reinterpret_cast<uint32_t*>(&l0v);
                ul.y = *reinterpret_cast<uint32_t*>(&l1v);
                *(uint2*)(smb + 32768 + sw) = uh;   // sKhi
                *(uint2*)(smb + 40960 + sw) = ul;   // sKlo
            }
            {
                float4 v = *(const float4*)(g_vp + plane + (size_t)(kt * 64 + c) * 512 + kq);
                __nv_bfloat16 hx = __float2bfloat16_rn(v.x);
                __nv_bfloat16 hy = __float2bfloat16_rn(v.y);
                __nv_bfloat16 hz = __float2bfloat16_rn(v.z);
                __nv_bfloat16 hw = __float2bfloat16_rn(v.w);
                __nv_bfloat16 lx = __float2bfloat16_rn(v.x - __bfloat162float(hx));
                __nv_bfloat16 ly = __float2bfloat16_rn(v.y - __bfloat162float(hy));
                __nv_bfloat16 lz = __float2bfloat16_rn(v.z - __bfloat162float(hz));
                __nv_bfloat16 lw = __float2bfloat16_rn(v.w - __bfloat162float(hw));
                __nv_bfloat162 h0, h1, l0v, l1v;
                h0.x = hx; h0.y = hy; h1.x = hz; h1.y = hw;
                l0v.x = lx; l0v.y = ly; l1v.x = lz; l1v.y = lw;
                uint2 uh, ul;
                uh.x = *reinterpret_cast<uint32_t*>(&h0);
                uh.y = *reinterpret_cast<uint32_t*>(&h1);
                ul.x = *reinterpret_cast<uint32_t*>(&l0v);
                ul.y = *reinterpret_cast<uint32_t*>(&l1v);
                *(uint2*)(smb + 49152 + sw) = uh;   // sVhi
                *(uint2*)(smb + 57344 + sw) = ul;   // sVlo
            }
        }
        __syncthreads();

        // ---- S = Q K^T : warp computes 16 rows x 64 cols (8 n8 blocks)
        float S[8][4];
#pragma unroll
        for (int ni = 0; ni < 8; ++ni)
#pragma unroll
            for (int q = 0; q < 4; ++q) S[ni][q] = 0.f;

#pragma unroll
        for (int ks = 0; ks < 4; ++ks) {
            const int kb = ks * 32 + ((lane >> 4) << 4);
            uint32_t ahi[4], alo[4];
            {
                uint32_t off = sw128((uint32_t)((w * 16 + (lane & 15)) * 128 + kb));
                ldsm_x4(ahi[0], ahi[1], ahi[2], ahi[3], QhiB + off);
                ldsm_x4(alo[0], alo[1], alo[2], alo[3], QloB + off);
            }
            uint32_t kh[4][4], kl[4][4];
#pragma unroll
            for (int cb = 0; cb < 4; ++cb) {
                uint32_t off = sw128((uint32_t)((cb * 16 + (lane & 15)) * 128 + kb));
                ldsm_x4(kh[cb][0], kh[cb][1], kh[cb][2], kh[cb][3], KhiB + off);
                ldsm_x4(kl[cb][0], kl[cb][1], kl[cb][2], kl[cb][3], KloB + off);
            }
#pragma unroll
            for (int ni = 0; ni < 8; ++ni) {
                uint32_t bfh[2] = { kh[ni >> 1][ni & 1], kh[ni >> 1][(ni & 1) + 2] };
                uint32_t bfl[2] = { kl[ni >> 1][ni & 1], kl[ni >> 1][(ni & 1) + 2] };
                mma_bf16(S[ni], ahi, bfh);
                mma_bf16(S[ni], ahi, bfl);
                mma_bf16(S[ni], alo, bfh);
            }
        }

        // ---- scale + causal mask + online softmax (rows g and g+8)
        const bool msk  = (kt >= 2 * qi);
        const int grow0 = qi * 128 + w * 16 + g;
        const int grow1 = grow0 + 8;
        const int colb  = kt * 64 + t2;
#pragma unroll
        for (int ni = 0; ni < 8; ++ni) {
            const int c0 = colb + ni * 8;
            S[ni][0] *= scale;
            S[ni][1] *= scale;
            S[ni][2] *= scale;
            S[ni][3] *= scale;
            if (msk) {
                if (c0     > grow0) S[ni][0] = NEG_INF;
                if (c0 + 1 > grow0) S[ni][1] = NEG_INF;
                if (c0     > grow1) S[ni][2] = NEG_INF;
                if (c0 + 1 > grow1) S[ni][3] = NEG_INF;
            }
        }
        float mx0 = NEG_INF, mx1 = NEG_INF;
#pragma unroll
        for (int ni = 0; ni < 8; ++ni) {
            mx0 = fmaxf(mx0, fmaxf(S[ni][0], S[ni][1]));
            mx1 = fmaxf(mx1, fmaxf(S[ni][2], S[ni][3]));
        }
        mx0 = fmaxf(mx0, __shfl_xor_sync(0xffffffffu, mx0, 1));
        mx0 = fmaxf(mx0, __shfl_xor_sync(0xffffffffu, mx0, 2));
        mx1 = fmaxf(mx1, __shfl_xor_sync(0xffffffffu, mx1, 1));
        mx1 = fmaxf(mx1, __shfl_xor_sync(0xffffffffu, mx1, 2));
        const float mn0 = fmaxf(m0, mx0);
        const float mn1 = fmaxf(m1, mx1);
        float sum0 = 0.f, sum1 = 0.f;
#pragma unroll
        for (int ni = 0; ni < 8; ++ni) {
            S[ni][0] = __expf(S[ni][0] - mn0); sum0 += S[ni][0];
            S[ni][1] = __expf(S[ni][1] - mn0); sum0 += S[ni][1];
            S[ni][2] = __expf(S[ni][2] - mn1); sum1 += S[ni][2];
            S[ni][3] = __expf(S[ni][3] - mn1); sum1 += S[ni][3];
        }
        sum0 += __shfl_xor_sync(0xffffffffu, sum0, 1);
        sum0 += __shfl_xor_sync(0xffffffffu, sum0, 2);
        sum1 += __shfl_xor_sync(0xffffffffu, sum1, 1);
        sum1 += __shfl_xor_sync(0xffffffffu, sum1, 2);
        const float al0 = __expf(m0 - mn0);
        const float al1 = __expf(m1 - mn1);
        l0 = l0 * al0 + sum0;
        l1 = l1 * al1 + sum1;
        m0 = mn0;
        m1 = mn1;
#pragma unroll
        for (int ni = 0; ni < 8; ++ni) {
            O[ni][0] *= al0; O[ni][1] *= al0;
            O[ni][2] *= al1; O[ni][3] *= al1;
        }

        // ---- O += P @ V : P packed from S fragments (2-term), V hi/lo trans
#pragma unroll
        for (int ks = 0; ks < 4; ++ks) {
            // A fragments for k = c in [ks*16, ks*16+16): from S blocks 2ks, 2ks+1
            uint32_t aph[4], apl[4];
            {
                const float p00 = S[2 * ks][0],     p01 = S[2 * ks][1];
                const float p10 = S[2 * ks][2],     p11 = S[2 * ks][3];
                const float p20 = S[2 * ks + 1][0], p21 = S[2 * ks + 1][1];
                const float p30 = S[2 * ks + 1][2], p31 = S[2 * ks + 1][3];
                aph[0] = pack_bf16x2(p00, p01);
                aph[1] = pack_bf16x2(p10, p11);
                aph[2] = pack_bf16x2(p20, p21);
                aph[3] = pack_bf16x2(p30, p31);
                // lo residuals
                float r00 = p00 - __bfloat162float(__float2bfloat16_rn(p00));
                float r01 = p01 - __bfloat162float(__float2bfloat16_rn(p01));
                float r10 = p10 - __bfloat162float(__float2bfloat16_rn(p10));
                float r11 = p11 - __bfloat162float(__float2bfloat16_rn(p11));
                float r20 = p20 - __bfloat162float(__float2bfloat16_rn(p20));
                float r21 = p21 - __bfloat162float(__float2bfloat16_rn(p21));
                float r30 = p30 - __bfloat162float(__float2bfloat16_rn(p30));
                float r31 = p31 - __bfloat162float(__float2bfloat16_rn(p31));
                apl[0] = pack_bf16x2(r00, r01);
                apl[1] = pack_bf16x2(r10, r11);
                apl[2] = pack_bf16x2(r20, r21);
                apl[3] = pack_bf16x2(r30, r31);
            }
            // B fragments: V rows c = ks*16..+15, n = 64 in 4 ldsm (hi) + 4 (lo)
            uint32_t vh[4][4], vl[4][4];
#pragma unroll
            for (int nb2 = 0; nb2 < 4; ++nb2) {
                uint32_t off = sw128((uint32_t)((ks * 16 + (lane & 15)) * 128
                                                + nb2 * 32 + ((lane >> 4) << 4)));
                ldsm_x4_t(vh[nb2][0], vh[nb2][1], vh[nb2][2], vh[nb2][3], VhiB + off);
                ldsm_x4_t(vl[nb2][0], vl[nb2][1], vl[nb2][2], vl[nb2][3], VloB + off);
            }
#pragma unroll
            for (int ni = 0; ni < 8; ++ni) {
                uint32_t bfh[2] = { vh[ni >> 1][(ni & 1) * 2], vh[ni >> 1][(ni & 1) * 2 + 1] };
                uint32_t bfl[2] = { vl[ni >> 1][(ni & 1) * 2], vl[ni >> 1][(ni & 1) * 2 + 1] };
                mma_bf16(O[ni], aph, bfh);
                mma_bf16(O[ni], aph, bfl);
                mma_bf16(O[ni], apl, bfh);
            }
        }
    }

    // ---- normalize + write heads output into concat layout [b, k, h*64 + v]
    const float inv0 = 1.f / l0;
    const float inv1 = 1.f / l1;
    const int row0 = qi * 128 + w * 16 + g;
#pragma unroll
    for (int ni = 0; ni < 8; ++ni) {
        const int coff = ni * 8 + t2;
        float2 v0, v1;
        v0.x = O[ni][0] * inv0; v0.y = O[ni][1] * inv0;
        v1.x = O[ni][2] * inv1; v1.y = O[ni][3] * inv1;
        *(float2*)(g_ct + plane + (size_t)row0 * 512 + coff)       = v0;
        *(float2*)(g_ct + plane + (size_t)(row0 + 8) * 512 + coff) = v1;
    }
}

// ---------------------------------------------------------------------------
// Launch: weight prep -> 3 HMMA projections -> HMMA attention -> HMMA out proj
// ---------------------------------------------------------------------------
extern "C" void kernel_launch(void* const* d_in, const int* in_sizes, int n_in,
                              void* d_out, int out_size)
{
    const float* query = (const float*)d_in[0];
    const float* key_  = (const float*)d_in[1];
    const float* value = (const float*)d_in[2];
    const float* W_q   = (const float*)d_in[3];
    const float* b_q   = (const float*)d_in[4];
    const float* W_k   = (const float*)d_in[5];
    const float* b_k   = (const float*)d_in[6];
    const float* W_v   = (const float*)d_in[7];
    const float* b_v   = (const float*)d_in[8];
    const float* W_o   = (const float*)d_in[9];
    const float* b_o   = (const float*)d_in[10];
    float* out = (float*)d_out;

    cudaFuncSetAttribute(attn_kernel, cudaFuncAttributeMaxDynamicSharedMemorySize,
                         ATTN_SMEM_BYTES);

    // Weight prep: transpose + bf16 split into g_wthi/g_wtlo (32 blocks)
    prep_w_kernel<<<dim3(8, 8), 256>>>(W_q, 512 * 64, 64, 0);
    prep_w_kernel<<<dim3(8, 8), 256>>>(W_k, 512 * 64, 64, 8);
    prep_w_kernel<<<dim3(8, 8), 256>>>(W_v, 512 * 64, 64, 16);
    prep_w_kernel<<<dim3(8, 8), 256>>>(W_o, 64, 512, 24);

    dim3 gg(64, 8);   // 8192/128 row tiles x 8 blocks (heads / N-slices)

    gemm_mma_kernel<<<gg, 256>>>(query, 0,  b_q, nullptr, 0, 1);
    gemm_mma_kernel<<<gg, 256>>>(key_,  8,  b_k, nullptr, 0, 2);
    gemm_mma_kernel<<<gg, 256>>>(value, 16, b_v, nullptr, 0, 3);

    // causal attention: 16 q-tiles (Br=128) x 32 (b,h) planes
    attn_kernel<<<dim3(16, 32), 256, ATTN_SMEM_BYTES>>>();

    // output projection: concat [8192,512] @ W_o [512,512] + b_o
    gemm_mma_kernel<<<gg, 256>>>(nullptr, 24, b_o, out, 1, 0);
}

// round 11
// speedup vs baseline: 2.8575x; 1.0943x over previous
#include <cuda_runtime.h>
#include <cuda_bf16.h>
#include <cstdint>

// Problem constants
#define NB     4
#define KWIN   2048
#define DMODEL 512
#define NHEAD  8
#define HDIM   64
#define NELEM  (NB * KWIN * DMODEL)

// ---------------------------------------------------------------------------
// Scratch (allocation-free rule: __device__ globals). All interchange in
// bf16 hi/lo split pairs (hi = rn(x), lo = rn(x - hi); sum ~= fp32 exact).
// Layout for all: [B, K, H*64] row-major == [8192, 512]
// ---------------------------------------------------------------------------
__device__ __nv_bfloat16 g_xqhi[NELEM], g_xqlo[NELEM];   // input query split
__device__ __nv_bfloat16 g_xkhi[NELEM], g_xklo[NELEM];   // input key split
__device__ __nv_bfloat16 g_xvhi[NELEM], g_xvlo[NELEM];   // input value split
__device__ __nv_bfloat16 g_qphi[NELEM], g_qplo[NELEM];   // projected q
__device__ __nv_bfloat16 g_kphi[NELEM], g_kplo[NELEM];   // projected k
__device__ __nv_bfloat16 g_vphi[NELEM], g_vplo[NELEM];   // projected v
__device__ __nv_bfloat16 g_cthi[NELEM], g_ctlo[NELEM];   // attn concat out

// Pre-transposed, bf16-split weights: 32 blocks of [64 n][512 k]
__device__ __nv_bfloat16 g_wthi[32 * 64 * 512];
__device__ __nv_bfloat16 g_wtlo[32 * 64 * 512];

// ---------------------------------------------------------------------------
// Helpers
// ---------------------------------------------------------------------------
__device__ __forceinline__ uint32_t smem_u32(const void* p) {
    uint32_t a;
    asm("{ .reg .u64 t; cvta.to.shared.u64 t, %1; cvt.u32.u64 %0, t; }"
        : "=r"(a) : "l"(p));
    return a;
}
__device__ __forceinline__ uint32_t sw128(uint32_t off) {
    return off ^ ((off >> 3) & 0x70);
}
__device__ __forceinline__ void cp16(uint32_t smem, const void* g) {
    asm volatile("cp.async.cg.shared.global [%0], [%1], 16;"
                 :: "r"(smem), "l"(g) : "memory");
}
#define CP_COMMIT() asm volatile("cp.async.commit_group;" ::: "memory")
#define CP_WAIT1()  asm volatile("cp.async.wait_group 1;" ::: "memory")
#define CP_WAIT0()  asm volatile("cp.async.wait_group 0;" ::: "memory")

__device__ __forceinline__ void ldsm_x4(uint32_t& r0, uint32_t& r1,
                                        uint32_t& r2, uint32_t& r3, uint32_t addr) {
    asm volatile("ldmatrix.sync.aligned.m8n8.x4.shared.b16 {%0,%1,%2,%3}, [%4];"
                 : "=r"(r0), "=r"(r1), "=r"(r2), "=r"(r3) : "r"(addr));
}
__device__ __forceinline__ void ldsm_x4_t(uint32_t& r0, uint32_t& r1,
                                          uint32_t& r2, uint32_t& r3, uint32_t addr) {
    asm volatile("ldmatrix.sync.aligned.m8n8.x4.trans.shared.b16 {%0,%1,%2,%3}, [%4];"
                 : "=r"(r0), "=r"(r1), "=r"(r2), "=r"(r3) : "r"(addr));
}
__device__ __forceinline__ void mma_bf16(float* c, const uint32_t* a, const uint32_t* b) {
    asm volatile(
        "mma.sync.aligned.m16n8k16.row.col.f32.bf16.bf16.f32 "
        "{%0,%1,%2,%3}, {%4,%5,%6,%7}, {%8,%9}, {%0,%1,%2,%3};"
        : "+f"(c[0]), "+f"(c[1]), "+f"(c[2]), "+f"(c[3])
        : "r"(a[0]), "r"(a[1]), "r"(a[2]), "r"(a[3]), "r"(b[0]), "r"(b[1]));
}
// pack two fp32 -> bf16x2 reg: low half = p0, high half = p1
__device__ __forceinline__ uint32_t pack_bf16x2(float p0, float p1) {
    uint32_t d;
    asm("cvt.rn.bf16x2.f32 %0, %1, %2;" : "=r"(d) : "f"(p1), "f"(p0));
    return d;
}
// split float4 -> hi uint2 (4 bf16), lo uint2
__device__ __forceinline__ void split4(float4 v, uint2& uh, uint2& ul) {
    float hx = __bfloat162float(__float2bfloat16_rn(v.x));
    float hy = __bfloat162float(__float2bfloat16_rn(v.y));
    float hz = __bfloat162float(__float2bfloat16_rn(v.z));
    float hw = __bfloat162float(__float2bfloat16_rn(v.w));
    uh.x = pack_bf16x2(hx, hy);
    uh.y = pack_bf16x2(hz, hw);
    ul.x = pack_bf16x2(v.x - hx, v.y - hy);
    ul.y = pack_bf16x2(v.z - hz, v.w - hw);
}

// ---------------------------------------------------------------------------
// prep_x: fp32 inputs -> bf16 hi/lo split. grid (1024,1,3), block 256.
// ---------------------------------------------------------------------------
__global__ __launch_bounds__(256)
void prep_x_kernel(const float* __restrict__ q, const float* __restrict__ k,
                   const float* __restrict__ v)
{
    const int slot = blockIdx.z;
    const float* X = (slot == 0) ? q : (slot == 1) ? k : v;
    __nv_bfloat16* hi = (slot == 0) ? g_xqhi : (slot == 1) ? g_xkhi : g_xvhi;
    __nv_bfloat16* lo = (slot == 0) ? g_xqlo : (slot == 1) ? g_xklo : g_xvlo;

    const int idx0 = blockIdx.x * 256 + threadIdx.x;   // 0..262143
#pragma unroll
    for (int r = 0; r < 4; ++r) {
        const int i = idx0 + r * 262144;               // float4 index, < 1048576
        float4 val = ((const float4*)X)[i];
        uint2 uh, ul;
        split4(val, uh, ul);
        ((uint2*)hi)[i] = uh;
        ((uint2*)lo)[i] = ul;
    }
}

// ---------------------------------------------------------------------------
// Weight prep (fused): W[k][n] fp32 -> [n][512 k] bf16 hi/lo, transposed.
//   grid = (8 k-tiles, 8 blocks, 4 which), block = 256
// ---------------------------------------------------------------------------
__global__ __launch_bounds__(256)
void prep_w_kernel(const float* __restrict__ Wq, const float* __restrict__ Wk,
                   const float* __restrict__ Wv, const float* __restrict__ Wo)
{
    __shared__ float s[64][65];
    const int which = blockIdx.z;
    const float* W = (which == 0) ? Wq : (which == 1) ? Wk : (which == 2) ? Wv : Wo;
    const int wstride = (which < 3) ? 512 * 64 : 64;
    const int ldb     = (which < 3) ? 64 : 512;
    const int blkbase = which * 8;

    const int kt  = blockIdx.x;
    const int nb  = blockIdx.y;
    const int tid = threadIdx.x;
    const float* Wt = W + (size_t)nb * wstride;

#pragma unroll
    for (int j = 0; j < 16; ++j) {
        int f = tid + 256 * j;          // 0..4095
        int k = f >> 6, n = f & 63;
        s[k][n] = Wt[(size_t)(kt * 64 + k) * ldb + n];
    }
    __syncthreads();
#pragma unroll
    for (int j = 0; j < 16; ++j) {
        int f = tid + 256 * j;
        int n = f >> 6, k = f & 63;
        float x = s[k][n];
        __nv_bfloat16 hi = __float2bfloat16_rn(x);
        __nv_bfloat16 lo = __float2bfloat16_rn(x - __bfloat162float(hi));
        size_t o = (size_t)(blkbase + nb) * (64 * 512) + (size_t)n * 512 + kt * 64 + k;
        g_wthi[o] = hi;
        g_wtlo[o] = lo;
    }
}

// ---------------------------------------------------------------------------
// HMMA bf16-split GEMM, cp.async double-buffered.
//   C[m, nb*64+n] = sum_split A@B + bias. grid (64,8), block 256.
//   A from bf16 hi/lo globals (slot 0..2 = inputs, 3 = attn concat).
//   osel: 0 -> fp32 `out` (+bias); 1..3 -> bf16 hi/lo q/k/v arrays (+bias).
//   Dyn smem 96KB: 2 buffers x (Ahi 16K | Alo 16K | Bhi 8K | Blo 8K).
// ---------------------------------------------------------------------------
#define GEMM_SMEM (2 * 49152)

__global__ __launch_bounds__(256)
void gemm_mma_kernel(int slot, int blkbase, const float* __restrict__ bias,
                     float* out, int osel)
{
    extern __shared__ __align__(1024) char gsm[];
    const uint32_t sb = smem_u32(gsm);

    const __nv_bfloat16* Ahi_g = (slot == 0) ? g_xqhi : (slot == 1) ? g_xkhi
                               : (slot == 2) ? g_xvhi : g_cthi;
    const __nv_bfloat16* Alo_g = (slot == 0) ? g_xqlo : (slot == 1) ? g_xklo
                               : (slot == 2) ? g_xvlo : g_ctlo;
    __nv_bfloat16* ophi = (osel == 1) ? g_qphi : (osel == 2) ? g_kphi : g_vphi;
    __nv_bfloat16* oplo = (osel == 1) ? g_qplo : (osel == 2) ? g_kplo : g_vplo;

    const int tid  = threadIdx.x;
    const int lane = tid & 31;
    const int wid  = tid >> 5;
    const int wm   = wid >> 1;       // 0..3 -> rows wm*32..+31
    const int wn   = wid & 1;        // 0..1 -> cols wn*32..+31
    const int m0   = blockIdx.x * 128;
    const int nb   = blockIdx.y;
    const size_t wbase = (size_t)(blkbase + nb) * (64 * 512);

    // per-chunk async load into buffer bb (12 cp.async of 16B per thread)
    auto load_chunk = [&](int ck, int bb) {
        const int k0 = ck * 64;
        const uint32_t base = sb + bb * 49152;
#pragma unroll
        for (int j = 0; j < 4; ++j) {
            int f   = tid + 256 * j;        // 0..1023
            int row = f >> 3;               // 0..127
            int kq  = (f & 7) << 3;         // element offset 0..56
            uint32_t sw = sw128((uint32_t)(row * 128 + (kq << 1)));
            const size_t src = (size_t)(m0 + row) * 512 + k0 + kq;
            cp16(base + sw,         Ahi_g + src);
            cp16(base + 16384 + sw, Alo_g + src);
        }
#pragma unroll
        for (int j = 0; j < 2; ++j) {
            int f  = tid + 256 * j;         // 0..511
            int n  = f >> 3;                // 0..63
            int kq = (f & 7) << 3;
            uint32_t sw = sw128((uint32_t)(n * 128 + (kq << 1)));
            const size_t src = wbase + (size_t)n * 512 + k0 + kq;
            cp16(base + 32768 + sw, g_wthi + src);
            cp16(base + 40960 + sw, g_wtlo + src);
        }
    };

    float C[2][4][4];
#pragma unroll
    for (int mi = 0; mi < 2; ++mi)
#pragma unroll
        for (int ni = 0; ni < 4; ++ni)
#pragma unroll
            for (int q = 0; q < 4; ++q) C[mi][ni][q] = 0.f;

    load_chunk(0, 0);
    CP_COMMIT();

    for (int ck = 0; ck < 8; ++ck) {
        if (ck < 7) {
            load_chunk(ck + 1, (ck + 1) & 1);
            CP_COMMIT();
            CP_WAIT1();
        } else {
            CP_WAIT0();
        }
        __syncthreads();

        const uint32_t base = sb + (ck & 1) * 49152;
        const uint32_t aHiB = base, aLoB = base + 16384;
        const uint32_t bHiB = base + 32768, bLoB = base + 40960;

#pragma unroll
        for (int ks = 0; ks < 4; ++ks) {
            const int kb = ks * 32 + ((lane >> 4) << 4);   // byte offset in row
            uint32_t ahi[2][4], alo[2][4];
            const int arow = wm * 32 + (lane & 15);
#pragma unroll
            for (int mi = 0; mi < 2; ++mi) {
                uint32_t off = sw128((uint32_t)((arow + mi * 16) * 128 + kb));
                ldsm_x4(ahi[mi][0], ahi[mi][1], ahi[mi][2], ahi[mi][3], aHiB + off);
                ldsm_x4(alo[mi][0], alo[mi][1], alo[mi][2], alo[mi][3], aLoB + off);
            }
            uint32_t bh[2][4], bl[2][4];
            const int brow = wn * 32 + (lane & 15);
#pragma unroll
            for (int half = 0; half < 2; ++half) {
                uint32_t off = sw128((uint32_t)((brow + half * 16) * 128 + kb));
                ldsm_x4(bh[half][0], bh[half][1], bh[half][2], bh[half][3], bHiB + off);
                ldsm_x4(bl[half][0], bl[half][1], bl[half][2], bl[half][3], bLoB + off);
            }
#pragma unroll
            for (int mi = 0; mi < 2; ++mi)
#pragma unroll
                for (int ni = 0; ni < 4; ++ni) {
                    uint32_t bfh[2] = { bh[ni >> 1][ni & 1], bh[ni >> 1][(ni & 1) + 2] };
                    uint32_t bfl[2] = { bl[ni >> 1][ni & 1], bl[ni >> 1][(ni & 1) + 2] };
                    mma_bf16(C[mi][ni], ahi[mi], bfh);
                    mma_bf16(C[mi][ni], ahi[mi], bfl);
                    mma_bf16(C[mi][ni], alo[mi], bfh);
                }
        }
        __syncthreads();   // all reads done before next cp.async overwrites
    }

    // Epilogue: fragment rows groupID/+8, cols 2*(lane&3)/+1
#pragma unroll
    for (int mi = 0; mi < 2; ++mi) {
        const int r = m0 + wm * 32 + mi * 16 + (lane >> 2);
#pragma unroll
        for (int ni = 0; ni < 4; ++ni) {
            const int col = nb * 64 + wn * 32 + ni * 8 + ((lane & 3) << 1);
            float2 bb = *(const float2*)(bias + col);
            float c00 = C[mi][ni][0] + bb.x, c01 = C[mi][ni][1] + bb.y;
            float c10 = C[mi][ni][2] + bb.x, c11 = C[mi][ni][3] + bb.y;
            if (osel == 0) {
                *(float2*)(out + (size_t)r * 512 + col)       = make_float2(c00, c01);
                *(float2*)(out + (size_t)(r + 8) * 512 + col) = make_float2(c10, c11);
            } else {
                float h00 = __bfloat162float(__float2bfloat16_rn(c00));
                float h01 = __bfloat162float(__float2bfloat16_rn(c01));
                float h10 = __bfloat162float(__float2bfloat16_rn(c10));
                float h11 = __bfloat162float(__float2bfloat16_rn(c11));
                *(uint32_t*)(ophi + (size_t)r * 512 + col)       = pack_bf16x2(h00, h01);
                *(uint32_t*)(oplo + (size_t)r * 512 + col)       = pack_bf16x2(c00 - h00, c01 - h01);
                *(uint32_t*)(ophi + (size_t)(r + 8) * 512 + col) = pack_bf16x2(h10, h11);
                *(uint32_t*)(oplo + (size_t)(r + 8) * 512 + col) = pack_bf16x2(c10 - h10, c11 - h11);
            }
        }
    }
}

// ---------------------------------------------------------------------------
// Causal flash attention on HMMA — pure-copy smem fills (bf16 interchange).
//   grid = (16 q-tiles, 32 bh), block = 256 (8 warps; warp w = q rows w*16..+15)
//   Dyn smem 64KB: Qhi/Qlo [128][64]bf16, Khi/Klo [64][64], Vhi/Vlo [64][64].
//   Output written bf16 hi/lo to g_cthi/g_ctlo.
// ---------------------------------------------------------------------------
#define ATTN_SMEM_BYTES 65536

__global__ __launch_bounds__(256, 2)
void attn_kernel()
{
    extern __shared__ __align__(1024) char smb[];
    const uint32_t QhiB = smem_u32(smb);
    const uint32_t QloB = QhiB + 16384;
    const uint32_t KhiB = QhiB + 32768;
    const uint32_t KloB = QhiB + 40960;
    const uint32_t VhiB = QhiB + 49152;
    const uint32_t VloB = QhiB + 57344;

    const int qi   = 15 - (int)blockIdx.x;   // big tiles first
    const int bh_  = blockIdx.y;
    const int b    = bh_ >> 3;
    const int h    = bh_ & 7;
    const int tid  = threadIdx.x;
    const int lane = tid & 31;
    const int w    = tid >> 5;               // warp: q rows w*16..+15
    const int g    = lane >> 2;              // fragment row group
    const int t2   = (lane & 3) << 1;        // fragment col pair
    const float scale   = 0.022097086912079608f;  // 1/sqrt(2048)
    const float NEG_INF = __int_as_float(0xff800000);

    const size_t plane = (size_t)b * (KWIN * DMODEL) + (size_t)h * 64;

    // ---- Q fill: pure copy bf16 hi/lo, swizzled (once per CTA)
#pragma unroll
    for (int j = 0; j < 4; ++j) {
        int f   = tid + 256 * j;          // 0..1023 16B slots
        int row = f >> 3;                 // 0..127
        int kq  = (f & 7) << 3;           // element 0..56
        const size_t src = plane + (size_t)(qi * 128 + row) * 512 + kq;
        uint32_t sw = sw128((uint32_t)(row * 128 + (kq << 1)));
        *(uint4*)(smb + sw)          = *(const uint4*)(g_qphi + src);
        *(uint4*)(smb + 16384 + sw)  = *(const uint4*)(g_qplo + src);
    }

    float O[8][4];
#pragma unroll
    for (int ni = 0; ni < 8; ++ni)
#pragma unroll
        for (int q = 0; q < 4; ++q) O[ni][q] = 0.f;
    float m0 = NEG_INF, m1 = NEG_INF, l0 = 0.f, l1 = 0.f;

    const int ktmax = 2 * qi + 1;
    for (int kt = 0; kt <= ktmax; ++kt) {
        __syncthreads();   // prev chunk compute done (and Q stores on kt=0)

        // ---- K,V fill: pure copy bf16 hi/lo, swizzled
#pragma unroll
        for (int j = 0; j < 2; ++j) {
            int f  = tid + 256 * j;           // 0..511 16B slots
            int c  = f >> 3;                  // 0..63
            int kq = (f & 7) << 3;
            const size_t src = plane + (size_t)(kt * 64 + c) * 512 + kq;
            uint32_t sw = sw128((uint32_t)(c * 128 + (kq << 1)));
            *(uint4*)(smb + 32768 + sw) = *(const uint4*)(g_kphi + src);
            *(uint4*)(smb + 40960 + sw) = *(const uint4*)(g_kplo + src);
            *(uint4*)(smb + 49152 + sw) = *(const uint4*)(g_vphi + src);
            *(uint4*)(smb + 57344 + sw) = *(const uint4*)(g_vplo + src);
        }
        __syncthreads();

        // ---- S = Q K^T : warp computes 16 rows x 64 cols (8 n8 blocks)
        float S[8][4];
#pragma unroll
        for (int ni = 0; ni < 8; ++ni)
#pragma unroll
            for (int q = 0; q < 4; ++q) S[ni][q] = 0.f;

#pragma unroll
        for (int ks = 0; ks < 4; ++ks) {
            const int kb = ks * 32 + ((lane >> 4) << 4);
            uint32_t ahi[4], alo[4];
            {
                uint32_t off = sw128((uint32_t)((w * 16 + (lane & 15)) * 128 + kb));
                ldsm_x4(ahi[0], ahi[1], ahi[2], ahi[3], QhiB + off);
                ldsm_x4(alo[0], alo[1], alo[2], alo[3], QloB + off);
            }
            uint32_t kh[4][4], kl[4][4];
#pragma unroll
            for (int cb = 0; cb < 4; ++cb) {
                uint32_t off = sw128((uint32_t)((cb * 16 + (lane & 15)) * 128 + kb));
                ldsm_x4(kh[cb][0], kh[cb][1], kh[cb][2], kh[cb][3], KhiB + off);
                ldsm_x4(kl[cb][0], kl[cb][1], kl[cb][2], kl[cb][3], KloB + off);
            }
#pragma unroll
            for (int ni = 0; ni < 8; ++ni) {
                uint32_t bfh[2] = { kh[ni >> 1][ni & 1], kh[ni >> 1][(ni & 1) + 2] };
                uint32_t bfl[2] = { kl[ni >> 1][ni & 1], kl[ni >> 1][(ni & 1) + 2] };
                mma_bf16(S[ni], ahi, bfh);
                mma_bf16(S[ni], ahi, bfl);
                mma_bf16(S[ni], alo, bfh);
            }
        }

        // ---- scale + causal mask + online softmax (rows g and g+8)
        const bool msk  = (kt >= 2 * qi);
        const int grow0 = qi * 128 + w * 16 + g;
        const int grow1 = grow0 + 8;
        const int colb  = kt * 64 + t2;
#pragma unroll
        for (int ni = 0; ni < 8; ++ni) {
            const int c0 = colb + ni * 8;
            S[ni][0] *= scale;
            S[ni][1] *= scale;
            S[ni][2] *= scale;
            S[ni][3] *= scale;
            if (msk) {
                if (c0     > grow0) S[ni][0] = NEG_INF;
                if (c0 + 1 > grow0) S[ni][1] = NEG_INF;
                if (c0     > grow1) S[ni][2] = NEG_INF;
                if (c0 + 1 > grow1) S[ni][3] = NEG_INF;
            }
        }
        float mx0 = NEG_INF, mx1 = NEG_INF;
#pragma unroll
        for (int ni = 0; ni < 8; ++ni) {
            mx0 = fmaxf(mx0, fmaxf(S[ni][0], S[ni][1]));
            mx1 = fmaxf(mx1, fmaxf(S[ni][2], S[ni][3]));
        }
        mx0 = fmaxf(mx0, __shfl_xor_sync(0xffffffffu, mx0, 1));
        mx0 = fmaxf(mx0, __shfl_xor_sync(0xffffffffu, mx0, 2));
        mx1 = fmaxf(mx1, __shfl_xor_sync(0xffffffffu, mx1, 1));
        mx1 = fmaxf(mx1, __shfl_xor_sync(0xffffffffu, mx1, 2));
        const float mn0 = fmaxf(m0, mx0);
        const float mn1 = fmaxf(m1, mx1);
        float sum0 = 0.f, sum1 = 0.f;
#pragma unroll
        for (int ni = 0; ni < 8; ++ni) {
            S[ni][0] = __expf(S[ni][0] - mn0); sum0 += S[ni][0];
            S[ni][1] = __expf(S[ni][1] - mn0); sum0 += S[ni][1];
            S[ni][2] = __expf(S[ni][2] - mn1); sum1 += S[ni][2];
            S[ni][3] = __expf(S[ni][3] - mn1); sum1 += S[ni][3];
        }
        sum0 += __shfl_xor_sync(0xffffffffu, sum0, 1);
        sum0 += __shfl_xor_sync(0xffffffffu, sum0, 2);
        sum1 += __shfl_xor_sync(0xffffffffu, sum1, 1);
        sum1 += __shfl_xor_sync(0xffffffffu, sum1, 2);
        const float al0 = __expf(m0 - mn0);
        const float al1 = __expf(m1 - mn1);
        l0 = l0 * al0 + sum0;
        l1 = l1 * al1 + sum1;
        m0 = mn0;
        m1 = mn1;
#pragma unroll
        for (int ni = 0; ni < 8; ++ni) {
            O[ni][0] *= al0; O[ni][1] *= al0;
            O[ni][2] *= al1; O[ni][3] *= al1;
        }

        // ---- O += P @ V : P packed from S fragments (2-term), V hi/lo trans
#pragma unroll
        for (int ks = 0; ks < 4; ++ks) {
            uint32_t aph[4], apl[4];
            {
                const float p00 = S[2 * ks][0],     p01 = S[2 * ks][1];
                const float p10 = S[2 * ks][2],     p11 = S[2 * ks][3];
                const float p20 = S[2 * ks + 1][0], p21 = S[2 * ks + 1][1];
                const float p30 = S[2 * ks + 1][2], p31 = S[2 * ks + 1][3];
                aph[0] = pack_bf16x2(p00, p01);
                aph[1] = pack_bf16x2(p10, p11);
                aph[2] = pack_bf16x2(p20, p21);
                aph[3] = pack_bf16x2(p30, p31);
                float r00 = p00 - __bfloat162float(__float2bfloat16_rn(p00));
                float r01 = p01 - __bfloat162float(__float2bfloat16_rn(p01));
                float r10 = p10 - __bfloat162float(__float2bfloat16_rn(p10));
                float r11 = p11 - __bfloat162float(__float2bfloat16_rn(p11));
                float r20 = p20 - __bfloat162float(__float2bfloat16_rn(p20));
                float r21 = p21 - __bfloat162float(__float2bfloat16_rn(p21));
                float r30 = p30 - __bfloat162float(__float2bfloat16_rn(p30));
                float r31 = p31 - __bfloat162float(__float2bfloat16_rn(p31));
                apl[0] = pack_bf16x2(r00, r01);
                apl[1] = pack_bf16x2(r10, r11);
                apl[2] = pack_bf16x2(r20, r21);
                apl[3] = pack_bf16x2(r30, r31);
            }
            uint32_t vh[4][4], vl[4][4];
#pragma unroll
            for (int nb2 = 0; nb2 < 4; ++nb2) {
                uint32_t off = sw128((uint32_t)((ks * 16 + (lane & 15)) * 128
                                                + nb2 * 32 + ((lane >> 4) << 4)));
                ldsm_x4_t(vh[nb2][0], vh[nb2][1], vh[nb2][2], vh[nb2][3], VhiB + off);
                ldsm_x4_t(vl[nb2][0], vl[nb2][1], vl[nb2][2], vl[nb2][3], VloB + off);
            }
#pragma unroll
            for (int ni = 0; ni < 8; ++ni) {
                uint32_t bfh[2] = { vh[ni >> 1][(ni & 1) * 2], vh[ni >> 1][(ni & 1) * 2 + 1] };
                uint32_t bfl[2] = { vl[ni >> 1][(ni & 1) * 2], vl[ni >> 1][(ni & 1) * 2 + 1] };
                mma_bf16(O[ni], aph, bfh);
                mma_bf16(O[ni], aph, bfl);
                mma_bf16(O[ni], apl, bfh);
            }
        }
    }

    // ---- normalize + split bf16 + write concat layout [b, k, h*64 + v]
    const float inv0 = 1.f / l0;
    const float inv1 = 1.f / l1;
    const int row0 = qi * 128 + w * 16 + g;
#pragma unroll
    for (int ni = 0; ni < 8; ++ni) {
        const int coff = ni * 8 + t2;
        float v00 = O[ni][0] * inv0, v01 = O[ni][1] * inv0;
        float v10 = O[ni][2] * inv1, v11 = O[ni][3] * inv1;
        float h00 = __bfloat162float(__float2bfloat16_rn(v00));
        float h01 = __bfloat162float(__float2bfloat16_rn(v01));
        float h10 = __bfloat162float(__float2bfloat16_rn(v10));
        float h11 = __bfloat162float(__float2bfloat16_rn(v11));
        const size_t o0 = plane + (size_t)row0 * 512 + coff;
        const size_t o1 = plane + (size_t)(row0 + 8) * 512 + coff;
        *(uint32_t*)(g_cthi + o0) = pack_bf16x2(h00, h01);
        *(uint32_t*)(g_ctlo + o0) = pack_bf16x2(v00 - h00, v01 - h01);
        *(uint32_t*)(g_cthi + o1) = pack_bf16x2(h10, h11);
        *(uint32_t*)(g_ctlo + o1) = pack_bf16x2(v10 - h10, v11 - h11);
    }
}

// ---------------------------------------------------------------------------
// Launch: prep_x + prep_w -> 3 HMMA projections -> HMMA attention -> out proj
// ---------------------------------------------------------------------------
extern "C" void kernel_launch(void* const* d_in, const int* in_sizes, int n_in,
                              void* d_out, int out_size)
{
    const float* query = (const float*)d_in[0];
    const float* key_  = (const float*)d_in[1];
    const float* value = (const float*)d_in[2];
    const float* W_q   = (const float*)d_in[3];
    const float* b_q   = (const float*)d_in[4];
    const float* W_k   = (const float*)d_in[5];
    const float* b_k   = (const float*)d_in[6];
    const float* W_v   = (const float*)d_in[7];
    const float* b_v   = (const float*)d_in[8];
    const float* W_o   = (const float*)d_in[9];
    const float* b_o   = (const float*)d_in[10];
    float* out = (float*)d_out;

    cudaFuncSetAttribute(attn_kernel, cudaFuncAttributeMaxDynamicSharedMemorySize,
                         ATTN_SMEM_BYTES);
    cudaFuncSetAttribute(gemm_mma_kernel, cudaFuncAttributeMaxDynamicSharedMemorySize,
                         GEMM_SMEM);

    // Input + weight prep (bf16 hi/lo interchange)
    prep_x_kernel<<<dim3(1024, 1, 3), 256>>>(query, key_, value);
    prep_w_kernel<<<dim3(8, 8, 4), 256>>>(W_q, W_k, W_v, W_o);

    dim3 gg(64, 8);   // 8192/128 row tiles x 8 blocks (heads / N-slices)

    gemm_mma_kernel<<<gg, 256, GEMM_SMEM>>>(0, 0,  b_q, nullptr, 1);
    gemm_mma_kernel<<<gg, 256, GEMM_SMEM>>>(1, 8,  b_k, nullptr, 2);
    gemm_mma_kernel<<<gg, 256, GEMM_SMEM>>>(2, 16, b_v, nullptr, 3);

    // causal attention: 16 q-tiles (Br=128) x 32 (b,h) planes
    attn_kernel<<<dim3(16, 32), 256, ATTN_SMEM_BYTES>>>();

    // output projection: concat [8192,512] @ W_o [512,512] + b_o -> fp32 out
    gemm_mma_kernel<<<gg, 256, GEMM_SMEM>>>(3, 24, b_o, out, 0);
}

// round 12
// speedup vs baseline: 3.6967x; 1.2937x over previous
#include <cuda_runtime.h>
#include <cuda_bf16.h>
#include <cstdint>

// Problem constants
#define NB     4
#define KWIN   2048
#define DMODEL 512
#define NHEAD  8
#define HDIM   64
#define NELEM  (NB * KWIN * DMODEL)

// ---------------------------------------------------------------------------
// Scratch (allocation-free rule: __device__ globals). All interchange in
// bf16 hi/lo split pairs (hi = rn(x), lo = rn(x - hi); sum ~= fp32 exact).
// Layout for all: [B, K, H*64] row-major == [8192, 512]
// ---------------------------------------------------------------------------
__device__ __nv_bfloat16 g_xqhi[NELEM], g_xqlo[NELEM];   // input query split
__device__ __nv_bfloat16 g_xkhi[NELEM], g_xklo[NELEM];   // input key split
__device__ __nv_bfloat16 g_xvhi[NELEM], g_xvlo[NELEM];   // input value split
__device__ __nv_bfloat16 g_qphi[NELEM], g_qplo[NELEM];   // projected q
__device__ __nv_bfloat16 g_kphi[NELEM], g_kplo[NELEM];   // projected k
__device__ __nv_bfloat16 g_vphi[NELEM], g_vplo[NELEM];   // projected v
__device__ __nv_bfloat16 g_cthi[NELEM], g_ctlo[NELEM];   // attn concat out

// Pre-transposed, bf16-split weights: 32 blocks of [64 n][512 k]
__device__ __nv_bfloat16 g_wthi[32 * 64 * 512];
__device__ __nv_bfloat16 g_wtlo[32 * 64 * 512];

// ---------------------------------------------------------------------------
// Helpers
// ---------------------------------------------------------------------------
__device__ __forceinline__ uint32_t smem_u32(const void* p) {
    uint32_t a;
    asm("{ .reg .u64 t; cvta.to.shared.u64 t, %1; cvt.u32.u64 %0, t; }"
        : "=r"(a) : "l"(p));
    return a;
}
__device__ __forceinline__ uint32_t sw128(uint32_t off) {
    return off ^ ((off >> 3) & 0x70);
}
__device__ __forceinline__ void cp16(uint32_t smem, const void* g) {
    asm volatile("cp.async.cg.shared.global [%0], [%1], 16;"
                 :: "r"(smem), "l"(g) : "memory");
}
#define CP_COMMIT() asm volatile("cp.async.commit_group;" ::: "memory")
#define CP_WAIT1()  asm volatile("cp.async.wait_group 1;" ::: "memory")
#define CP_WAIT0()  asm volatile("cp.async.wait_group 0;" ::: "memory")

__device__ __forceinline__ void ldsm_x4(uint32_t& r0, uint32_t& r1,
                                        uint32_t& r2, uint32_t& r3, uint32_t addr) {
    asm volatile("ldmatrix.sync.aligned.m8n8.x4.shared.b16 {%0,%1,%2,%3}, [%4];"
                 : "=r"(r0), "=r"(r1), "=r"(r2), "=r"(r3) : "r"(addr));
}
__device__ __forceinline__ void ldsm_x4_t(uint32_t& r0, uint32_t& r1,
                                          uint32_t& r2, uint32_t& r3, uint32_t addr) {
    asm volatile("ldmatrix.sync.aligned.m8n8.x4.trans.shared.b16 {%0,%1,%2,%3}, [%4];"
                 : "=r"(r0), "=r"(r1), "=r"(r2), "=r"(r3) : "r"(addr));
}
__device__ __forceinline__ void mma_bf16(float* c, const uint32_t* a, const uint32_t* b) {
    asm volatile(
        "mma.sync.aligned.m16n8k16.row.col.f32.bf16.bf16.f32 "
        "{%0,%1,%2,%3}, {%4,%5,%6,%7}, {%8,%9}, {%0,%1,%2,%3};"
        : "+f"(c[0]), "+f"(c[1]), "+f"(c[2]), "+f"(c[3])
        : "r"(a[0]), "r"(a[1]), "r"(a[2]), "r"(a[3]), "r"(b[0]), "r"(b[1]));
}
// pack two fp32 -> bf16x2 reg: low half = p0, high half = p1
__device__ __forceinline__ uint32_t pack_bf16x2(float p0, float p1) {
    uint32_t d;
    asm("cvt.rn.bf16x2.f32 %0, %1, %2;" : "=r"(d) : "f"(p1), "f"(p0));
    return d;
}
// split float4 -> hi uint2 (4 bf16), lo uint2
__device__ __forceinline__ void split4(float4 v, uint2& uh, uint2& ul) {
    float hx = __bfloat162float(__float2bfloat16_rn(v.x));
    float hy = __bfloat162float(__float2bfloat16_rn(v.y));
    float hz = __bfloat162float(__float2bfloat16_rn(v.z));
    float hw = __bfloat162float(__float2bfloat16_rn(v.w));
    uh.x = pack_bf16x2(hx, hy);
    uh.y = pack_bf16x2(hz, hw);
    ul.x = pack_bf16x2(v.x - hx, v.y - hy);
    ul.y = pack_bf16x2(v.z - hz, v.w - hw);
}

// ---------------------------------------------------------------------------
// prep_x: fp32 inputs -> bf16 hi/lo split. grid (1024,1,3), block 256.
// ---------------------------------------------------------------------------
__global__ __launch_bounds__(256)
void prep_x_kernel(const float* __restrict__ q, const float* __restrict__ k,
                   const float* __restrict__ v)
{
    const int slot = blockIdx.z;
    const float* X = (slot == 0) ? q : (slot == 1) ? k : v;
    __nv_bfloat16* hi = (slot == 0) ? g_xqhi : (slot == 1) ? g_xkhi : g_xvhi;
    __nv_bfloat16* lo = (slot == 0) ? g_xqlo : (slot == 1) ? g_xklo : g_xvlo;

    const int idx0 = blockIdx.x * 256 + threadIdx.x;   // 0..262143
#pragma unroll
    for (int r = 0; r < 4; ++r) {
        const int i = idx0 + r * 262144;               // float4 index, < 1048576
        float4 val = ((const float4*)X)[i];
        uint2 uh, ul;
        split4(val, uh, ul);
        ((uint2*)hi)[i] = uh;
        ((uint2*)lo)[i] = ul;
    }
}

// ---------------------------------------------------------------------------
// Weight prep (fused): W[k][n] fp32 -> [n][512 k] bf16 hi/lo, transposed.
//   grid = (8 k-tiles, 8 blocks, 4 which), block = 256
// ---------------------------------------------------------------------------
__global__ __launch_bounds__(256)
void prep_w_kernel(const float* __restrict__ Wq, const float* __restrict__ Wk,
                   const float* __restrict__ Wv, const float* __restrict__ Wo)
{
    __shared__ float s[64][65];
    const int which = blockIdx.z;
    const float* W = (which == 0) ? Wq : (which == 1) ? Wk : (which == 2) ? Wv : Wo;
    const int wstride = (which < 3) ? 512 * 64 : 64;
    const int ldb     = (which < 3) ? 64 : 512;
    const int blkbase = which * 8;

    const int kt  = blockIdx.x;
    const int nb  = blockIdx.y;
    const int tid = threadIdx.x;
    const float* Wt = W + (size_t)nb * wstride;

#pragma unroll
    for (int j = 0; j < 16; ++j) {
        int f = tid + 256 * j;          // 0..4095
        int k = f >> 6, n = f & 63;
        s[k][n] = Wt[(size_t)(kt * 64 + k) * ldb + n];
    }
    __syncthreads();
#pragma unroll
    for (int j = 0; j < 16; ++j) {
        int f = tid + 256 * j;
        int n = f >> 6, k = f & 63;
        float x = s[k][n];
        __nv_bfloat16 hi = __float2bfloat16_rn(x);
        __nv_bfloat16 lo = __float2bfloat16_rn(x - __bfloat162float(hi));
        size_t o = (size_t)(blkbase + nb) * (64 * 512) + (size_t)n * 512 + kt * 64 + k;
        g_wthi[o] = hi;
        g_wtlo[o] = lo;
    }
}

// ---------------------------------------------------------------------------
// HMMA bf16-split GEMM core, cp.async double-buffered (shared by both launches)
//   Dyn smem 96KB: 2 buffers x (Ahi 16K | Alo 16K | Bhi 8K | Blo 8K).
// ---------------------------------------------------------------------------
#define GEMM_SMEM (2 * 49152)

__device__ __forceinline__ void gemm_core(
    const __nv_bfloat16* __restrict__ Ahi_g,
    const __nv_bfloat16* __restrict__ Alo_g,
    int blkbase, const float* __restrict__ bias,
    float* out, __nv_bfloat16* ophi, __nv_bfloat16* oplo, int osel, char* gsm)
{
    const uint32_t sb = smem_u32(gsm);
    const int tid  = threadIdx.x;
    const int lane = tid & 31;
    const int wid  = tid >> 5;
    const int wm   = wid >> 1;       // 0..3 -> rows wm*32..+31
    const int wn   = wid & 1;        // 0..1 -> cols wn*32..+31
    const int m0   = blockIdx.x * 128;
    const int nb   = blockIdx.y;
    const size_t wbase = (size_t)(blkbase + nb) * (64 * 512);

    auto load_chunk = [&](int ck, int bb) {
        const int k0 = ck * 64;
        const uint32_t base = sb + bb * 49152;
#pragma unroll
        for (int j = 0; j < 4; ++j) {
            int f   = tid + 256 * j;        // 0..1023
            int row = f >> 3;               // 0..127
            int kq  = (f & 7) << 3;         // element offset 0..56
            uint32_t sw = sw128((uint32_t)(row * 128 + (kq << 1)));
            const size_t src = (size_t)(m0 + row) * 512 + k0 + kq;
            cp16(base + sw,         Ahi_g + src);
            cp16(base + 16384 + sw, Alo_g + src);
        }
#pragma unroll
        for (int j = 0; j < 2; ++j) {
            int f  = tid + 256 * j;         // 0..511
            int n  = f >> 3;                // 0..63
            int kq = (f & 7) << 3;
            uint32_t sw = sw128((uint32_t)(n * 128 + (kq << 1)));
            const size_t src = wbase + (size_t)n * 512 + k0 + kq;
            cp16(base + 32768 + sw, g_wthi + src);
            cp16(base + 40960 + sw, g_wtlo + src);
        }
    };

    float C[2][4][4];
#pragma unroll
    for (int mi = 0; mi < 2; ++mi)
#pragma unroll
        for (int ni = 0; ni < 4; ++ni)
#pragma unroll
            for (int q = 0; q < 4; ++q) C[mi][ni][q] = 0.f;

    load_chunk(0, 0);
    CP_COMMIT();

    for (int ck = 0; ck < 8; ++ck) {
        if (ck < 7) {
            load_chunk(ck + 1, (ck + 1) & 1);
            CP_COMMIT();
            CP_WAIT1();
        } else {
            CP_WAIT0();
        }
        __syncthreads();

        const uint32_t base = sb + (ck & 1) * 49152;
        const uint32_t aHiB = base, aLoB = base + 16384;
        const uint32_t bHiB = base + 32768, bLoB = base + 40960;

#pragma unroll
        for (int ks = 0; ks < 4; ++ks) {
            const int kb = ks * 32 + ((lane >> 4) << 4);   // byte offset in row
            uint32_t ahi[2][4], alo[2][4];
            const int arow = wm * 32 + (lane & 15);
#pragma unroll
            for (int mi = 0; mi < 2; ++mi) {
                uint32_t off = sw128((uint32_t)((arow + mi * 16) * 128 + kb));
                ldsm_x4(ahi[mi][0], ahi[mi][1], ahi[mi][2], ahi[mi][3], aHiB + off);
                ldsm_x4(alo[mi][0], alo[mi][1], alo[mi][2], alo[mi][3], aLoB + off);
            }
            uint32_t bh[2][4], bl[2][4];
            const int brow = wn * 32 + (lane & 15);
#pragma unroll
            for (int half = 0; half < 2; ++half) {
                uint32_t off = sw128((uint32_t)((brow + half * 16) * 128 + kb));
                ldsm_x4(bh[half][0], bh[half][1], bh[half][2], bh[half][3], bHiB + off);
                ldsm_x4(bl[half][0], bl[half][1], bl[half][2], bl[half][3], bLoB + off);
            }
#pragma unroll
            for (int mi = 0; mi < 2; ++mi)
#pragma unroll
                for (int ni = 0; ni < 4; ++ni) {
                    uint32_t bfh[2] = { bh[ni >> 1][ni & 1], bh[ni >> 1][(ni & 1) + 2] };
                    uint32_t bfl[2] = { bl[ni >> 1][ni & 1], bl[ni >> 1][(ni & 1) + 2] };
                    mma_bf16(C[mi][ni], ahi[mi], bfh);
                    mma_bf16(C[mi][ni], ahi[mi], bfl);
                    mma_bf16(C[mi][ni], alo[mi], bfh);
                }
        }
        __syncthreads();   // all reads done before next cp.async overwrites
    }

    // Epilogue: fragment rows groupID/+8, cols 2*(lane&3)/+1
#pragma unroll
    for (int mi = 0; mi < 2; ++mi) {
        const int r = m0 + wm * 32 + mi * 16 + (lane >> 2);
#pragma unroll
        for (int ni = 0; ni < 4; ++ni) {
            const int col = nb * 64 + wn * 32 + ni * 8 + ((lane & 3) << 1);
            float2 bb = *(const float2*)(bias + col);
            float c00 = C[mi][ni][0] + bb.x, c01 = C[mi][ni][1] + bb.y;
            float c10 = C[mi][ni][2] + bb.x, c11 = C[mi][ni][3] + bb.y;
            if (osel == 0) {
                *(float2*)(out + (size_t)r * 512 + col)       = make_float2(c00, c01);
                *(float2*)(out + (size_t)(r + 8) * 512 + col) = make_float2(c10, c11);
            } else {
                float h00 = __bfloat162float(__float2bfloat16_rn(c00));
                float h01 = __bfloat162float(__float2bfloat16_rn(c01));
                float h10 = __bfloat162float(__float2bfloat16_rn(c10));
                float h11 = __bfloat162float(__float2bfloat16_rn(c11));
                *(uint32_t*)(ophi + (size_t)r * 512 + col)       = pack_bf16x2(h00, h01);
                *(uint32_t*)(oplo + (size_t)r * 512 + col)       = pack_bf16x2(c00 - h00, c01 - h01);
                *(uint32_t*)(ophi + (size_t)(r + 8) * 512 + col) = pack_bf16x2(h10, h11);
                *(uint32_t*)(oplo + (size_t)(r + 8) * 512 + col) = pack_bf16x2(c10 - h10, c11 - h11);
            }
        }
    }
}

// Fused q/k/v projections: grid (64, 8, 3)
__global__ __launch_bounds__(256)
void gemm_proj_kernel(const float* __restrict__ bq, const float* __restrict__ bk,
                      const float* __restrict__ bv)
{
    extern __shared__ __align__(1024) char gsm[];
    const int z = blockIdx.z;
    const __nv_bfloat16* Ahi = (z == 0) ? g_xqhi : (z == 1) ? g_xkhi : g_xvhi;
    const __nv_bfloat16* Alo = (z == 0) ? g_xqlo : (z == 1) ? g_xklo : g_xvlo;
    const float* bias        = (z == 0) ? bq     : (z == 1) ? bk     : bv;
    __nv_bfloat16* ophi      = (z == 0) ? g_qphi : (z == 1) ? g_kphi : g_vphi;
    __nv_bfloat16* oplo      = (z == 0) ? g_qplo : (z == 1) ? g_kplo : g_vplo;
    gemm_core(Ahi, Alo, z * 8, bias, nullptr, ophi, oplo, 1, gsm);
}

// Output projection: grid (64, 8)
__global__ __launch_bounds__(256)
void gemm_out_kernel(const float* __restrict__ bias, float* out)
{
    extern __shared__ __align__(1024) char gsm[];
    gemm_core(g_cthi, g_ctlo, 24, bias, out, nullptr, nullptr, 0, gsm);
}

// ---------------------------------------------------------------------------
// Causal flash attention on HMMA — cp.async double-buffered K/V stages.
//   grid = 512 (1D, longest-first: qi = 15 - bid/32, bh = bid & 31), block 256.
//   Dyn smem 96KB: Qhi/Qlo [128][64]bf16 (32K) + 2 KV stages x 32K
//   (stage: Khi 8K | Klo 8K | Vhi 8K | Vlo 8K).
// ---------------------------------------------------------------------------
#define ATTN_SMEM_BYTES 98304

__global__ __launch_bounds__(256, 2)
void attn_kernel()
{
    extern __shared__ __align__(1024) char smb[];
    const uint32_t smB  = smem_u32(smb);
    const uint32_t QhiB = smB;
    const uint32_t QloB = smB + 16384;

    const int bid  = blockIdx.x;
    const int qi   = 15 - (bid >> 5);        // longest-first
    const int bh_  = bid & 31;
    const int b    = bh_ >> 3;
    const int h    = bh_ & 7;
    const int tid  = threadIdx.x;
    const int lane = tid & 31;
    const int w    = tid >> 5;               // warp: q rows w*16..+15
    const int g    = lane >> 2;              // fragment row group
    const int t2   = (lane & 3) << 1;        // fragment col pair
    const float scale   = 0.022097086912079608f;  // 1/sqrt(2048)
    const float NEG_INF = __int_as_float(0xff800000);

    const size_t plane = (size_t)b * (KWIN * DMODEL) + (size_t)h * 64;

    // async fill of KV stage s with chunk kt
    auto load_kv = [&](int kt, int s) {
        const uint32_t base = smB + 32768 + s * 32768;
#pragma unroll
        for (int j = 0; j < 2; ++j) {
            int f  = tid + 256 * j;           // 0..511 16B slots
            int c  = f >> 3;                  // 0..63
            int kq = (f & 7) << 3;
            const size_t src = plane + (size_t)(kt * 64 + c) * 512 + kq;
            uint32_t sw = sw128((uint32_t)(c * 128 + (kq << 1)));
            cp16(base + sw,         g_kphi + src);
            cp16(base + 8192 + sw,  g_kplo + src);
            cp16(base + 16384 + sw, g_vphi + src);
            cp16(base + 24576 + sw, g_vplo + src);
        }
    };

    // ---- Q fill: pure copy bf16 hi/lo, swizzled (once per CTA)
#pragma unroll
    for (int j = 0; j < 4; ++j) {
        int f   = tid + 256 * j;          // 0..1023 16B slots
        int row = f >> 3;                 // 0..127
        int kq  = (f & 7) << 3;           // element 0..56
        const size_t src = plane + (size_t)(qi * 128 + row) * 512 + kq;
        uint32_t sw = sw128((uint32_t)(row * 128 + (kq << 1)));
        *(uint4*)(smb + sw)          = *(const uint4*)(g_qphi + src);
        *(uint4*)(smb + 16384 + sw)  = *(const uint4*)(g_qplo + src);
    }

    float O[8][4];
#pragma unroll
    for (int ni = 0; ni < 8; ++ni)
#pragma unroll
        for (int q = 0; q < 4; ++q) O[ni][q] = 0.f;
    float m0 = NEG_INF, m1 = NEG_INF, l0 = 0.f, l1 = 0.f;

    const int ktmax = 2 * qi + 1;
    load_kv(0, 0);
    CP_COMMIT();

    for (int kt = 0; kt <= ktmax; ++kt) {
        __syncthreads();   // compute of kt-1 done -> stage (kt+1)&1 free
        if (kt < ktmax) {
            load_kv(kt + 1, (kt + 1) & 1);
            CP_COMMIT();
            CP_WAIT1();    // chunk kt's group complete (issued last iteration)
        } else {
            CP_WAIT0();
        }
        __syncthreads();   // stage kt&1 visible to all warps

        const uint32_t sbase = smB + 32768 + (kt & 1) * 32768;
        const uint32_t KhiB = sbase,        KloB = sbase + 8192;
        const uint32_t VhiB = sbase + 16384, VloB = sbase + 24576;

        // ---- S = Q K^T : warp computes 16 rows x 64 cols (8 n8 blocks)
        float S[8][4];
#pragma unroll
        for (int ni = 0; ni < 8; ++ni)
#pragma unroll
            for (int q = 0; q < 4; ++q) S[ni][q] = 0.f;

#pragma unroll
        for (int ks = 0; ks < 4; ++ks) {
            const int kb = ks * 32 + ((lane >> 4) << 4);
            uint32_t ahi[4], alo[4];
            {
                uint32_t off = sw128((uint32_t)((w * 16 + (lane & 15)) * 128 + kb));
                ldsm_x4(ahi[0], ahi[1], ahi[2], ahi[3], QhiB + off);
                ldsm_x4(alo[0], alo[1], alo[2], alo[3], QloB + off);
            }
            uint32_t kh[4][4], kl[4][4];
#pragma unroll
            for (int cb = 0; cb < 4; ++cb) {
                uint32_t off = sw128((uint32_t)((cb * 16 + (lane & 15)) * 128 + kb));
                ldsm_x4(kh[cb][0], kh[cb][1], kh[cb][2], kh[cb][3], KhiB + off);
                ldsm_x4(kl[cb][0], kl[cb][1], kl[cb][2], kl[cb][3], KloB + off);
            }
#pragma unroll
            for (int ni = 0; ni < 8; ++ni) {
                uint32_t bfh[2] = { kh[ni >> 1][ni & 1], kh[ni >> 1][(ni & 1) + 2] };
                uint32_t bfl[2] = { kl[ni >> 1][ni & 1], kl[ni >> 1][(ni & 1) + 2] };
                mma_bf16(S[ni], ahi, bfh);
                mma_bf16(S[ni], ahi, bfl);
                mma_bf16(S[ni], alo, bfh);
            }
        }

        // ---- scale + causal mask + online softmax (rows g and g+8)
        const bool msk  = (kt >= 2 * qi);
        const int grow0 = qi * 128 + w * 16 + g;
        const int grow1 = grow0 + 8;
        const int colb  = kt * 64 + t2;
#pragma unroll
        for (int ni = 0; ni < 8; ++ni) {
            const int c0 = colb + ni * 8;
            S[ni][0] *= scale;
            S[ni][1] *= scale;
            S[ni][2] *= scale;
            S[ni][3] *= scale;
            if (msk) {
                if (c0     > grow0) S[ni][0] = NEG_INF;
                if (c0 + 1 > grow0) S[ni][1] = NEG_INF;
                if (c0     > grow1) S[ni][2] = NEG_INF;
                if (c0 + 1 > grow1) S[ni][3] = NEG_INF;
            }
        }
        float mx0 = NEG_INF, mx1 = NEG_INF;
#pragma unroll
        for (int ni = 0; ni < 8; ++ni) {
            mx0 = fmaxf(mx0, fmaxf(S[ni][0], S[ni][1]));
            mx1 = fmaxf(mx1, fmaxf(S[ni][2], S[ni][3]));
        }
        mx0 = fmaxf(mx0, __shfl_xor_sync(0xffffffffu, mx0, 1));
        mx0 = fmaxf(mx0, __shfl_xor_sync(0xffffffffu, mx0, 2));
        mx1 = fmaxf(mx1, __shfl_xor_sync(0xffffffffu, mx1, 1));
        mx1 = fmaxf(mx1, __shfl_xor_sync(0xffffffffu, mx1, 2));
        const float mn0 = fmaxf(m0, mx0);
        const float mn1 = fmaxf(m1, mx1);
        float sum0 = 0.f, sum1 = 0.f;
#pragma unroll
        for (int ni = 0; ni < 8; ++ni) {
            S[ni][0] = __expf(S[ni][0] - mn0); sum0 += S[ni][0];
            S[ni][1] = __expf(S[ni][1] - mn0); sum0 += S[ni][1];
            S[ni][2] = __expf(S[ni][2] - mn1); sum1 += S[ni][2];
            S[ni][3] = __expf(S[ni][3] - mn1); sum1 += S[ni][3];
        }
        sum0 += __shfl_xor_sync(0xffffffffu, sum0, 1);
        sum0 += __shfl_xor_sync(0xffffffffu, sum0, 2);
        sum1 += __shfl_xor_sync(0xffffffffu, sum1, 1);
        sum1 += __shfl_xor_sync(0xffffffffu, sum1, 2);
        const float al0 = __expf(m0 - mn0);
        const float al1 = __expf(m1 - mn1);
        l0 = l0 * al0 + sum0;
        l1 = l1 * al1 + sum1;
        m0 = mn0;
        m1 = mn1;
#pragma unroll
        for (int ni = 0; ni < 8; ++ni) {
            O[ni][0] *= al0; O[ni][1] *= al0;
            O[ni][2] *= al1; O[ni][3] *= al1;
        }

        // ---- O += P @ V : P packed from S fragments (2-term), V hi/lo trans
#pragma unroll
        for (int ks = 0; ks < 4; ++ks) {
            uint32_t aph[4], apl[4];
            {
                const float p00 = S[2 * ks][0],     p01 = S[2 * ks][1];
                const float p10 = S[2 * ks][2],     p11 = S[2 * ks][3];
                const float p20 = S[2 * ks + 1][0], p21 = S[2 * ks + 1][1];
                const float p30 = S[2 * ks + 1][2], p31 = S[2 * ks + 1][3];
                aph[0] = pack_bf16x2(p00, p01);
                aph[1] = pack_bf16x2(p10, p11);
                aph[2] = pack_bf16x2(p20, p21);
                aph[3] = pack_bf16x2(p30, p31);
                float r00 = p00 - __bfloat162float(__float2bfloat16_rn(p00));
                float r01 = p01 - __bfloat162float(__float2bfloat16_rn(p01));
                float r10 = p10 - __bfloat162float(__float2bfloat16_rn(p10));
                float r11 = p11 - __bfloat162float(__float2bfloat16_rn(p11));
                float r20 = p20 - __bfloat162float(__float2bfloat16_rn(p20));
                float r21 = p21 - __bfloat162float(__float2bfloat16_rn(p21));
                float r30 = p30 - __bfloat162float(__float2bfloat16_rn(p30));
                float r31 = p31 - __bfloat162float(__float2bfloat16_rn(p31));
                apl[0] = pack_bf16x2(r00, r01);
                apl[1] = pack_bf16x2(r10, r11);
                apl[2] = pack_bf16x2(r20, r21);
                apl[3] = pack_bf16x2(r30, r31);
            }
            uint32_t vh[4][4], vl[4][4];
#pragma unroll
            for (int nb2 = 0; nb2 < 4; ++nb2) {
                uint32_t off = sw128((uint32_t)((ks * 16 + (lane & 15)) * 128
                                                + nb2 * 32 + ((lane >> 4) << 4)));
                ldsm_x4_t(vh[nb2][0], vh[nb2][1], vh[nb2][2], vh[nb2][3], VhiB + off);
                ldsm_x4_t(vl[nb2][0], vl[nb2][1], vl[nb2][2], vl[nb2][3], VloB + off);
            }
#pragma unroll
            for (int ni = 0; ni < 8; ++ni) {
                uint32_t bfh[2] = { vh[ni >> 1][(ni & 1) * 2], vh[ni >> 1][(ni & 1) * 2 + 1] };
                uint32_t bfl[2] = { vl[ni >> 1][(ni & 1) * 2], vl[ni >> 1][(ni & 1) * 2 + 1] };
                mma_bf16(O[ni], aph, bfh);
                mma_bf16(O[ni], aph, bfl);
                mma_bf16(O[ni], apl, bfh);
            }
        }
    }

    // ---- normalize + split bf16 + write concat layout [b, k, h*64 + v]
    const float inv0 = 1.f / l0;
    const float inv1 = 1.f / l1;
    const int row0 = qi * 128 + w * 16 + g;
#pragma unroll
    for (int ni = 0; ni < 8; ++ni) {
        const int coff = ni * 8 + t2;
        float v00 = O[ni][0] * inv0, v01 = O[ni][1] * inv0;
        float v10 = O[ni][2] * inv1, v11 = O[ni][3] * inv1;
        float h00 = __bfloat162float(__float2bfloat16_rn(v00));
        float h01 = __bfloat162float(__float2bfloat16_rn(v01));
        float h10 = __bfloat162float(__float2bfloat16_rn(v10));
        float h11 = __bfloat162float(__float2bfloat16_rn(v11));
        const size_t o0 = plane + (size_t)row0 * 512 + coff;
        const size_t o1 = plane + (size_t)(row0 + 8) * 512 + coff;
        *(uint32_t*)(g_cthi + o0) = pack_bf16x2(h00, h01);
        *(uint32_t*)(g_ctlo + o0) = pack_bf16x2(v00 - h00, v01 - h01);
        *(uint32_t*)(g_cthi + o1) = pack_bf16x2(h10, h11);
        *(uint32_t*)(g_ctlo + o1) = pack_bf16x2(v10 - h10, v11 - h11);
    }
}

// ---------------------------------------------------------------------------
// Launch: prep_x + prep_w -> fused q/k/v projections -> attention -> out proj
// ---------------------------------------------------------------------------
extern "C" void kernel_launch(void* const* d_in, const int* in_sizes, int n_in,
                              void* d_out, int out_size)
{
    const float* query = (const float*)d_in[0];
    const float* key_  = (const float*)d_in[1];
    const float* value = (const float*)d_in[2];
    const float* W_q   = (const float*)d_in[3];
    const float* b_q   = (const float*)d_in[4];
    const float* W_k   = (const float*)d_in[5];
    const float* b_k   = (const float*)d_in[6];
    const float* W_v   = (const float*)d_in[7];
    const float* b_v   = (const float*)d_in[8];
    const float* W_o   = (const float*)d_in[9];
    const float* b_o   = (const float*)d_in[10];
    float* out = (float*)d_out;

    cudaFuncSetAttribute(attn_kernel, cudaFuncAttributeMaxDynamicSharedMemorySize,
                         ATTN_SMEM_BYTES);
    cudaFuncSetAttribute(gemm_proj_kernel, cudaFuncAttributeMaxDynamicSharedMemorySize,
                         GEMM_SMEM);
    cudaFuncSetAttribute(gemm_out_kernel, cudaFuncAttributeMaxDynamicSharedMemorySize,
                         GEMM_SMEM);

    // Input + weight prep (bf16 hi/lo interchange)
    prep_x_kernel<<<dim3(1024, 1, 3), 256>>>(query, key_, value);
    prep_w_kernel<<<dim3(8, 8, 4), 256>>>(W_q, W_k, W_v, W_o);

    // Fused q/k/v projections: one launch, 1536 CTAs
    gemm_proj_kernel<<<dim3(64, 8, 3), 256, GEMM_SMEM>>>(b_q, b_k, b_v);

    // causal attention: 512 CTAs, longest-first 1D order
    attn_kernel<<<512, 256, ATTN_SMEM_BYTES>>>();

    // output projection: concat [8192,512] @ W_o [512,512] + b_o -> fp32 out
    gemm_out_kernel<<<dim3(64, 8), 256, GEMM_SMEM>>>(b_o, out);
}

// round 13
// speedup vs baseline: 3.7892x; 1.0250x over previous
#include <cuda_runtime.h>
#include <cuda_bf16.h>
#include <cstdint>

// Problem constants
#define NB     4
#define KWIN   2048
#define DMODEL 512
#define NHEAD  8
#define HDIM   64
#define NELEM  (NB * KWIN * DMODEL)

// ---------------------------------------------------------------------------
// Scratch (allocation-free rule: __device__ globals). All interchange in
// bf16 hi/lo split pairs (hi ~ bf16(x), lo = x - hi; sum ~= fp32 exact).
// Layout for all: [B, K, H*64] row-major == [8192, 512]
// ---------------------------------------------------------------------------
__device__ __nv_bfloat16 g_xqhi[NELEM], g_xqlo[NELEM];   // input query split
__device__ __nv_bfloat16 g_xkhi[NELEM], g_xklo[NELEM];   // input key split
__device__ __nv_bfloat16 g_xvhi[NELEM], g_xvlo[NELEM];   // input value split
__device__ __nv_bfloat16 g_qphi[NELEM], g_qplo[NELEM];   // projected q
__device__ __nv_bfloat16 g_kphi[NELEM], g_kplo[NELEM];   // projected k
__device__ __nv_bfloat16 g_vphi[NELEM], g_vplo[NELEM];   // projected v
__device__ __nv_bfloat16 g_cthi[NELEM], g_ctlo[NELEM];   // attn concat out

// Pre-transposed, bf16-split weights: 32 blocks of [64 n][512 k]
__device__ __nv_bfloat16 g_wthi[32 * 64 * 512];
__device__ __nv_bfloat16 g_wtlo[32 * 64 * 512];

// ---------------------------------------------------------------------------
// Helpers
// ---------------------------------------------------------------------------
__device__ __forceinline__ uint32_t smem_u32(const void* p) {
    uint32_t a;
    asm("{ .reg .u64 t; cvta.to.shared.u64 t, %1; cvt.u32.u64 %0, t; }"
        : "=r"(a) : "l"(p));
    return a;
}
__device__ __forceinline__ uint32_t sw128(uint32_t off) {
    return off ^ ((off >> 3) & 0x70);
}
__device__ __forceinline__ void cp16(uint32_t smem, const void* g) {
    asm volatile("cp.async.cg.shared.global [%0], [%1], 16;"
                 :: "r"(smem), "l"(g) : "memory");
}
#define CP_COMMIT() asm volatile("cp.async.commit_group;" ::: "memory")
#define CP_WAIT1()  asm volatile("cp.async.wait_group 1;" ::: "memory")
#define CP_WAIT0()  asm volatile("cp.async.wait_group 0;" ::: "memory")

__device__ __forceinline__ void ldsm_x4(uint32_t& r0, uint32_t& r1,
                                        uint32_t& r2, uint32_t& r3, uint32_t addr) {
    asm volatile("ldmatrix.sync.aligned.m8n8.x4.shared.b16 {%0,%1,%2,%3}, [%4];"
                 : "=r"(r0), "=r"(r1), "=r"(r2), "=r"(r3) : "r"(addr));
}
__device__ __forceinline__ void ldsm_x4_t(uint32_t& r0, uint32_t& r1,
                                          uint32_t& r2, uint32_t& r3, uint32_t addr) {
    asm volatile("ldmatrix.sync.aligned.m8n8.x4.trans.shared.b16 {%0,%1,%2,%3}, [%4];"
                 : "=r"(r0), "=r"(r1), "=r"(r2), "=r"(r3) : "r"(addr));
}
__device__ __forceinline__ void mma_bf16(float* c, const uint32_t* a, const uint32_t* b) {
    asm volatile(
        "mma.sync.aligned.m16n8k16.row.col.f32.bf16.bf16.f32 "
        "{%0,%1,%2,%3}, {%4,%5,%6,%7}, {%8,%9}, {%0,%1,%2,%3};"
        : "+f"(c[0]), "+f"(c[1]), "+f"(c[2]), "+f"(c[3])
        : "r"(a[0]), "r"(a[1]), "r"(a[2]), "r"(a[3]), "r"(b[0]), "r"(b[1]));
}
// pack two fp32 -> bf16x2 reg: low half = p0, high half = p1
__device__ __forceinline__ uint32_t pack_bf16x2(float p0, float p1) {
    uint32_t d;
    asm("cvt.rn.bf16x2.f32 %0, %1, %2;" : "=r"(d) : "f"(p1), "f"(p0));
    return d;
}
// trunc split of a pair: hi = upper-16-bit truncation (exact bf16, 1 PRMT),
// lo = exact residual, packed with one cvt. |p - (hi+lo)| <= 2^-16 |p|.
__device__ __forceinline__ void trunc_split_pack(float p0, float p1,
                                                 uint32_t& hi, uint32_t& lo) {
    uint32_t b0 = __float_as_uint(p0), b1 = __float_as_uint(p1);
    hi = __byte_perm(b0, b1, 0x7632);
    float h0 = __uint_as_float(b0 & 0xffff0000u);
    float h1 = __uint_as_float(b1 & 0xffff0000u);
    lo = pack_bf16x2(p0 - h0, p1 - h1);
}
// split float4 -> hi uint2 (4 bf16), lo uint2 (rn split, used in prep)
__device__ __forceinline__ void split4(float4 v, uint2& uh, uint2& ul) {
    float hx = __bfloat162float(__float2bfloat16_rn(v.x));
    float hy = __bfloat162float(__float2bfloat16_rn(v.y));
    float hz = __bfloat162float(__float2bfloat16_rn(v.z));
    float hw = __bfloat162float(__float2bfloat16_rn(v.w));
    uh.x = pack_bf16x2(hx, hy);
    uh.y = pack_bf16x2(hz, hw);
    ul.x = pack_bf16x2(v.x - hx, v.y - hy);
    ul.y = pack_bf16x2(v.z - hz, v.w - hw);
}

// ---------------------------------------------------------------------------
// prep (fused): z<3 -> input fp32 -> bf16 hi/lo split (1024 blocks each);
//               z=3 -> weight transpose + split (blocks 0..255).
//   grid = (1024, 1, 4), block = 256
// ---------------------------------------------------------------------------
__global__ __launch_bounds__(256)
void prep_all_kernel(const float* __restrict__ q, const float* __restrict__ k,
                     const float* __restrict__ v,
                     const float* __restrict__ Wq, const float* __restrict__ Wk,
                     const float* __restrict__ Wv, const float* __restrict__ Wo)
{
    __shared__ float s[64][65];
    const int slot = blockIdx.z;
    const int tid  = threadIdx.x;

    if (slot == 3) {
        const int x = blockIdx.x;
        if (x >= 256) return;
        const int which = x >> 6;          // 0..3
        const int kt    = (x >> 3) & 7;
        const int nb    = x & 7;
        const float* W = (which == 0) ? Wq : (which == 1) ? Wk
                       : (which == 2) ? Wv : Wo;
        const int wstride = (which < 3) ? 512 * 64 : 64;
        const int ldb     = (which < 3) ? 64 : 512;
        const int blkbase = which * 8;
        const float* Wt = W + (size_t)nb * wstride;

#pragma unroll
        for (int j = 0; j < 16; ++j) {
            int f = tid + 256 * j;          // 0..4095
            int kk = f >> 6, n = f & 63;
            s[kk][n] = Wt[(size_t)(kt * 64 + kk) * ldb + n];
        }
        __syncthreads();
#pragma unroll
        for (int j = 0; j < 16; ++j) {
            int f = tid + 256 * j;
            int n = f >> 6, kk = f & 63;
            float x2 = s[kk][n];
            __nv_bfloat16 hi = __float2bfloat16_rn(x2);
            __nv_bfloat16 lo = __float2bfloat16_rn(x2 - __bfloat162float(hi));
            size_t o = (size_t)(blkbase + nb) * (64 * 512) + (size_t)n * 512 + kt * 64 + kk;
            g_wthi[o] = hi;
            g_wtlo[o] = lo;
        }
        return;
    }

    const float* X = (slot == 0) ? q : (slot == 1) ? k : v;
    __nv_bfloat16* hi = (slot == 0) ? g_xqhi : (slot == 1) ? g_xkhi : g_xvhi;
    __nv_bfloat16* lo = (slot == 0) ? g_xqlo : (slot == 1) ? g_xklo : g_xvlo;

    const int idx0 = blockIdx.x * 256 + tid;           // 0..262143
#pragma unroll
    for (int r = 0; r < 4; ++r) {
        const int i = idx0 + r * 262144;               // float4 index, < 1048576
        float4 val = ((const float4*)X)[i];
        uint2 uh, ul;
        split4(val, uh, ul);
        ((uint2*)hi)[i] = uh;
        ((uint2*)lo)[i] = ul;
    }
}

// ---------------------------------------------------------------------------
// HMMA bf16-split GEMM core, cp.async double-buffered (shared by both launches)
//   Dyn smem 96KB: 2 buffers x (Ahi 16K | Alo 16K | Bhi 8K | Blo 8K).
// ---------------------------------------------------------------------------
#define GEMM_SMEM (2 * 49152)

__device__ __forceinline__ void gemm_core(
    const __nv_bfloat16* __restrict__ Ahi_g,
    const __nv_bfloat16* __restrict__ Alo_g,
    int blkbase, const float* __restrict__ bias,
    float* out, __nv_bfloat16* ophi, __nv_bfloat16* oplo, int osel, char* gsm)
{
    const uint32_t sb = smem_u32(gsm);
    const int tid  = threadIdx.x;
    const int lane = tid & 31;
    const int wid  = tid >> 5;
    const int wm   = wid >> 1;       // 0..3 -> rows wm*32..+31
    const int wn   = wid & 1;        // 0..1 -> cols wn*32..+31
    const int m0   = blockIdx.x * 128;
    const int nb   = blockIdx.y;
    const size_t wbase = (size_t)(blkbase + nb) * (64 * 512);

    auto load_chunk = [&](int ck, int bb) {
        const int k0 = ck * 64;
        const uint32_t base = sb + bb * 49152;
#pragma unroll
        for (int j = 0; j < 4; ++j) {
            int f   = tid + 256 * j;        // 0..1023
            int row = f >> 3;               // 0..127
            int kq  = (f & 7) << 3;         // element offset 0..56
            uint32_t sw = sw128((uint32_t)(row * 128 + (kq << 1)));
            const size_t src = (size_t)(m0 + row) * 512 + k0 + kq;
            cp16(base + sw,         Ahi_g + src);
            cp16(base + 16384 + sw, Alo_g + src);
        }
#pragma unroll
        for (int j = 0; j < 2; ++j) {
            int f  = tid + 256 * j;         // 0..511
            int n  = f >> 3;                // 0..63
            int kq = (f & 7) << 3;
            uint32_t sw = sw128((uint32_t)(n * 128 + (kq << 1)));
            const size_t src = wbase + (size_t)n * 512 + k0 + kq;
            cp16(base + 32768 + sw, g_wthi + src);
            cp16(base + 40960 + sw, g_wtlo + src);
        }
    };

    float C[2][4][4];
#pragma unroll
    for (int mi = 0; mi < 2; ++mi)
#pragma unroll
        for (int ni = 0; ni < 4; ++ni)
#pragma unroll
            for (int q = 0; q < 4; ++q) C[mi][ni][q] = 0.f;

    load_chunk(0, 0);
    CP_COMMIT();

    for (int ck = 0; ck < 8; ++ck) {
        if (ck < 7) {
            load_chunk(ck + 1, (ck + 1) & 1);
            CP_COMMIT();
            CP_WAIT1();
        } else {
            CP_WAIT0();
        }
        __syncthreads();

        const uint32_t base = sb + (ck & 1) * 49152;
        const uint32_t aHiB = base, aLoB = base + 16384;
        const uint32_t bHiB = base + 32768, bLoB = base + 40960;

#pragma unroll
        for (int ks = 0; ks < 4; ++ks) {
            const int kb = ks * 32 + ((lane >> 4) << 4);   // byte offset in row
            uint32_t ahi[2][4], alo[2][4];
            const int arow = wm * 32 + (lane & 15);
#pragma unroll
            for (int mi = 0; mi < 2; ++mi) {
                uint32_t off = sw128((uint32_t)((arow + mi * 16) * 128 + kb));
                ldsm_x4(ahi[mi][0], ahi[mi][1], ahi[mi][2], ahi[mi][3], aHiB + off);
                ldsm_x4(alo[mi][0], alo[mi][1], alo[mi][2], alo[mi][3], aLoB + off);
            }
            const int brow = wn * 32 + (lane & 15);
            // per-half: load 8 B frag regs, consume immediately (small live set)
#pragma unroll
            for (int half = 0; half < 2; ++half) {
                uint32_t off = sw128((uint32_t)((brow + half * 16) * 128 + kb));
                uint32_t bh[4], bl[4];
                ldsm_x4(bh[0], bh[1], bh[2], bh[3], bHiB + off);
                ldsm_x4(bl[0], bl[1], bl[2], bl[3], bLoB + off);
#pragma unroll
                for (int q2 = 0; q2 < 2; ++q2) {
                    const int ni = half * 2 + q2;
                    uint32_t bfh[2] = { bh[q2], bh[q2 + 2] };
                    uint32_t bfl[2] = { bl[q2], bl[q2 + 2] };
#pragma unroll
                    for (int mi = 0; mi < 2; ++mi) {
                        mma_bf16(C[mi][ni], ahi[mi], bfh);
                        mma_bf16(C[mi][ni], ahi[mi], bfl);
                        mma_bf16(C[mi][ni], alo[mi], bfh);
                    }
                }
            }
        }
        __syncthreads();   // all reads done before next cp.async overwrites
    }

    // Epilogue: fragment rows groupID/+8, cols 2*(lane&3)/+1
#pragma unroll
    for (int mi = 0; mi < 2; ++mi) {
        const int r = m0 + wm * 32 + mi * 16 + (lane >> 2);
#pragma unroll
        for (int ni = 0; ni < 4; ++ni) {
            const int col = nb * 64 + wn * 32 + ni * 8 + ((lane & 3) << 1);
            float2 bb = *(const float2*)(bias + col);
            float c00 = C[mi][ni][0] + bb.x, c01 = C[mi][ni][1] + bb.y;
            float c10 = C[mi][ni][2] + bb.x, c11 = C[mi][ni][3] + bb.y;
            if (osel == 0) {
                *(float2*)(out + (size_t)r * 512 + col)       = make_float2(c00, c01);
                *(float2*)(out + (size_t)(r + 8) * 512 + col) = make_float2(c10, c11);
            } else {
                uint32_t h0, l0v, h1, l1v;
                trunc_split_pack(c00, c01, h0, l0v);
                trunc_split_pack(c10, c11, h1, l1v);
                *(uint32_t*)(ophi + (size_t)r * 512 + col)       = h0;
                *(uint32_t*)(oplo + (size_t)r * 512 + col)       = l0v;
                *(uint32_t*)(ophi + (size_t)(r + 8) * 512 + col) = h1;
                *(uint32_t*)(oplo + (size_t)(r + 8) * 512 + col) = l1v;
            }
        }
    }
}

// Fused q/k/v projections: grid (64, 8, 3)
__global__ __launch_bounds__(256)
void gemm_proj_kernel(const float* __restrict__ bq, const float* __restrict__ bk,
                      const float* __restrict__ bv)
{
    extern __shared__ __align__(1024) char gsm[];
    const int z = blockIdx.z;
    const __nv_bfloat16* Ahi = (z == 0) ? g_xqhi : (z == 1) ? g_xkhi : g_xvhi;
    const __nv_bfloat16* Alo = (z == 0) ? g_xqlo : (z == 1) ? g_xklo : g_xvlo;
    const float* bias        = (z == 0) ? bq     : (z == 1) ? bk     : bv;
    __nv_bfloat16* ophi      = (z == 0) ? g_qphi : (z == 1) ? g_kphi : g_vphi;
    __nv_bfloat16* oplo      = (z == 0) ? g_qplo : (z == 1) ? g_kplo : g_vplo;
    gemm_core(Ahi, Alo, z * 8, bias, nullptr, ophi, oplo, 1, gsm);
}

// Output projection: grid (64, 8)
__global__ __launch_bounds__(256)
void gemm_out_kernel(const float* __restrict__ bias, float* out)
{
    extern __shared__ __align__(1024) char gsm[];
    gemm_core(g_cthi, g_ctlo, 24, bias, out, nullptr, nullptr, 0, gsm);
}

// ---------------------------------------------------------------------------
// Causal flash attention on HMMA — cp.async double-buffered K/V stages.
//   grid = 512 (1D, longest-first: qi = 15 - bid/32, bh = bid & 31), block 256.
//   Dyn smem 96KB: Qhi/Qlo [128][64]bf16 (32K) + 2 KV stages x 32K
//   (stage: Khi 8K | Klo 8K | Vhi 8K | Vlo 8K).
// ---------------------------------------------------------------------------
#define ATTN_SMEM_BYTES 98304

__global__ __launch_bounds__(256, 2)
void attn_kernel()
{
    extern __shared__ __align__(1024) char smb[];
    const uint32_t smB  = smem_u32(smb);
    const uint32_t QhiB = smB;
    const uint32_t QloB = smB + 16384;

    const int bid  = blockIdx.x;
    const int qi   = 15 - (bid >> 5);        // longest-first
    const int bh_  = bid & 31;
    const int b    = bh_ >> 3;
    const int h    = bh_ & 7;
    const int tid  = threadIdx.x;
    const int lane = tid & 31;
    const int w    = tid >> 5;               // warp: q rows w*16..+15
    const int g    = lane >> 2;              // fragment row group
    const int t2   = (lane & 3) << 1;        // fragment col pair
    const float scale   = 0.022097086912079608f;  // 1/sqrt(2048)
    const float NEG_INF = __int_as_float(0xff800000);

    const size_t plane = (size_t)b * (KWIN * DMODEL) + (size_t)h * 64;

    // async fill of KV stage s with chunk kt
    auto load_kv = [&](int kt, int s) {
        const uint32_t base = smB + 32768 + s * 32768;
#pragma unroll
        for (int j = 0; j < 2; ++j) {
            int f  = tid + 256 * j;           // 0..511 16B slots
            int c  = f >> 3;                  // 0..63
            int kq = (f & 7) << 3;
            const size_t src = plane + (size_t)(kt * 64 + c) * 512 + kq;
            uint32_t sw = sw128((uint32_t)(c * 128 + (kq << 1)));
            cp16(base + sw,         g_kphi + src);
            cp16(base + 8192 + sw,  g_kplo + src);
            cp16(base + 16384 + sw, g_vphi + src);
            cp16(base + 24576 + sw, g_vplo + src);
        }
    };

    // ---- Q fill: pure copy bf16 hi/lo, swizzled (once per CTA)
#pragma unroll
    for (int j = 0; j < 4; ++j) {
        int f   = tid + 256 * j;          // 0..1023 16B slots
        int row = f >> 3;                 // 0..127
        int kq  = (f & 7) << 3;           // element 0..56
        const size_t src = plane + (size_t)(qi * 128 + row) * 512 + kq;
        uint32_t sw = sw128((uint32_t)(row * 128 + (kq << 1)));
        *(uint4*)(smb + sw)          = *(const uint4*)(g_qphi + src);
        *(uint4*)(smb + 16384 + sw)  = *(const uint4*)(g_qplo + src);
    }

    float O[8][4];
#pragma unroll
    for (int ni = 0; ni < 8; ++ni)
#pragma unroll
        for (int q = 0; q < 4; ++q) O[ni][q] = 0.f;
    float m0 = NEG_INF, m1 = NEG_INF, l0 = 0.f, l1 = 0.f;

    const int ktmax = 2 * qi + 1;
    load_kv(0, 0);
    CP_COMMIT();

    for (int kt = 0; kt <= ktmax; ++kt) {
        __syncthreads();   // compute of kt-1 done -> stage (kt+1)&1 free
        if (kt < ktmax) {
            load_kv(kt + 1, (kt + 1) & 1);
            CP_COMMIT();
            CP_WAIT1();    // chunk kt's group complete (issued last iteration)
        } else {
            CP_WAIT0();
        }
        __syncthreads();   // stage kt&1 visible to all warps

        const uint32_t sbase = smB + 32768 + (kt & 1) * 32768;
        const uint32_t KhiB = sbase,         KloB = sbase + 8192;
        const uint32_t VhiB = sbase + 16384, VloB = sbase + 24576;

        // ---- S = Q K^T : warp computes 16 rows x 64 cols (8 n8 blocks)
        float S[8][4];
#pragma unroll
        for (int ni = 0; ni < 8; ++ni)
#pragma unroll
            for (int q = 0; q < 4; ++q) S[ni][q] = 0.f;

#pragma unroll
        for (int ks = 0; ks < 4; ++ks) {
            const int kb = ks * 32 + ((lane >> 4) << 4);
            uint32_t ahi[4], alo[4];
            {
                uint32_t off = sw128((uint32_t)((w * 16 + (lane & 15)) * 128 + kb));
                ldsm_x4(ahi[0], ahi[1], ahi[2], ahi[3], QhiB + off);
                ldsm_x4(alo[0], alo[1], alo[2], alo[3], QloB + off);
            }
            // per-cb: load 8 K frag regs, consume immediately (small live set)
#pragma unroll
            for (int cb = 0; cb < 4; ++cb) {
                uint32_t off = sw128((uint32_t)((cb * 16 + (lane & 15)) * 128 + kb));
                uint32_t kh[4], kl[4];
                ldsm_x4(kh[0], kh[1], kh[2], kh[3], KhiB + off);
                ldsm_x4(kl[0], kl[1], kl[2], kl[3], KloB + off);
#pragma unroll
                for (int q2 = 0; q2 < 2; ++q2) {
                    const int ni = cb * 2 + q2;
                    uint32_t bfh[2] = { kh[q2], kh[q2 + 2] };
                    uint32_t bfl[2] = { kl[q2], kl[q2 + 2] };
                    mma_bf16(S[ni], ahi, bfh);
                    mma_bf16(S[ni], ahi, bfl);
                    mma_bf16(S[ni], alo, bfh);
                }
            }
        }

        // ---- scale + causal mask + online softmax (rows g and g+8)
        const bool msk  = (kt >= 2 * qi);
        const int grow0 = qi * 128 + w * 16 + g;
        const int grow1 = grow0 + 8;
        const int colb  = kt * 64 + t2;
#pragma unroll
        for (int ni = 0; ni < 8; ++ni) {
            const int c0 = colb + ni * 8;
            S[ni][0] *= scale;
            S[ni][1] *= scale;
            S[ni][2] *= scale;
            S[ni][3] *= scale;
            if (msk) {
                if (c0     > grow0) S[ni][0] = NEG_INF;
                if (c0 + 1 > grow0) S[ni][1] = NEG_INF;
                if (c0     > grow1) S[ni][2] = NEG_INF;
                if (c0 + 1 > grow1) S[ni][3] = NEG_INF;
            }
        }
        float mx0 = NEG_INF, mx1 = NEG_INF;
#pragma unroll
        for (int ni = 0; ni < 8; ++ni) {
            mx0 = fmaxf(mx0, fmaxf(S[ni][0], S[ni][1]));
            mx1 = fmaxf(mx1, fmaxf(S[ni][2], S[ni][3]));
        }
        mx0 = fmaxf(mx0, __shfl_xor_sync(0xffffffffu, mx0, 1));
        mx0 = fmaxf(mx0, __shfl_xor_sync(0xffffffffu, mx0, 2));
        mx1 = fmaxf(mx1, __shfl_xor_sync(0xffffffffu, mx1, 1));
        mx1 = fmaxf(mx1, __shfl_xor_sync(0xffffffffu, mx1, 2));
        const float mn0 = fmaxf(m0, mx0);
        const float mn1 = fmaxf(m1, mx1);
        float sum0 = 0.f, sum1 = 0.f;
#pragma unroll
        for (int ni = 0; ni < 8; ++ni) {
            S[ni][0] = __expf(S[ni][0] - mn0); sum0 += S[ni][0];
            S[ni][1] = __expf(S[ni][1] - mn0); sum0 += S[ni][1];
            S[ni][2] = __expf(S[ni][2] - mn1); sum1 += S[ni][2];
            S[ni][3] = __expf(S[ni][3] - mn1); sum1 += S[ni][3];
        }
        sum0 += __shfl_xor_sync(0xffffffffu, sum0, 1);
        sum0 += __shfl_xor_sync(0xffffffffu, sum0, 2);
        sum1 += __shfl_xor_sync(0xffffffffu, sum1, 1);
        sum1 += __shfl_xor_sync(0xffffffffu, sum1, 2);
        const float al0 = __expf(m0 - mn0);
        const float al1 = __expf(m1 - mn1);
        l0 = l0 * al0 + sum0;
        l1 = l1 * al1 + sum1;
        m0 = mn0;
        m1 = mn1;
#pragma unroll
        for (int ni = 0; ni < 8; ++ni) {
            O[ni][0] *= al0; O[ni][1] *= al0;
            O[ni][2] *= al1; O[ni][3] *= al1;
        }

        // ---- O += P @ V : P trunc-split from S fragments, V hi/lo trans
#pragma unroll
        for (int ks = 0; ks < 4; ++ks) {
            uint32_t aph[4], apl[4];
            trunc_split_pack(S[2 * ks][0],     S[2 * ks][1],     aph[0], apl[0]);
            trunc_split_pack(S[2 * ks][2],     S[2 * ks][3],     aph[1], apl[1]);
            trunc_split_pack(S[2 * ks + 1][0], S[2 * ks + 1][1], aph[2], apl[2]);
            trunc_split_pack(S[2 * ks + 1][2], S[2 * ks + 1][3], aph[3], apl[3]);

            // per-nb2: load 8 V frag regs, consume immediately (small live set)
#pragma unroll
            for (int nb2 = 0; nb2 < 4; ++nb2) {
                uint32_t off = sw128((uint32_t)((ks * 16 + (lane & 15)) * 128
                                                + nb2 * 32 + ((lane >> 4) << 4)));
                uint32_t vh[4], vl[4];
                ldsm_x4_t(vh[0], vh[1], vh[2], vh[3], VhiB + off);
                ldsm_x4_t(vl[0], vl[1], vl[2], vl[3], VloB + off);
#pragma unroll
                for (int q2 = 0; q2 < 2; ++q2) {
                    const int ni = nb2 * 2 + q2;
                    uint32_t bfh[2] = { vh[q2 * 2], vh[q2 * 2 + 1] };
                    uint32_t bfl[2] = { vl[q2 * 2], vl[q2 * 2 + 1] };
                    mma_bf16(O[ni], aph, bfh);
                    mma_bf16(O[ni], aph, bfl);
                    mma_bf16(O[ni], apl, bfh);
                }
            }
        }
    }

    // ---- normalize + trunc split + write concat layout [b, k, h*64 + v]
    const float inv0 = 1.f / l0;
    const float inv1 = 1.f / l1;
    const int row0 = qi * 128 + w * 16 + g;
#pragma unroll
    for (int ni = 0; ni < 8; ++ni) {
        const int coff = ni * 8 + t2;
        float v00 = O[ni][0] * inv0, v01 = O[ni][1] * inv0;
        float v10 = O[ni][2] * inv1, v11 = O[ni][3] * inv1;
        uint32_t h0, l0v, h1, l1v;
        trunc_split_pack(v00, v01, h0, l0v);
        trunc_split_pack(v10, v11, h1, l1v);
        const size_t o0 = plane + (size_t)row0 * 512 + coff;
        const size_t o1 = plane + (size_t)(row0 + 8) * 512 + coff;
        *(uint32_t*)(g_cthi + o0) = h0;
        *(uint32_t*)(g_ctlo + o0) = l0v;
        *(uint32_t*)(g_cthi + o1) = h1;
        *(uint32_t*)(g_ctlo + o1) = l1v;
    }
}

// ---------------------------------------------------------------------------
// Launch: fused prep -> fused q/k/v projections -> attention -> out proj
// ---------------------------------------------------------------------------
extern "C" void kernel_launch(void* const* d_in, const int* in_sizes, int n_in,
                              void* d_out, int out_size)
{
    const float* query = (const float*)d_in[0];
    const float* key_  = (const float*)d_in[1];
    const float* value = (const float*)d_in[2];
    const float* W_q   = (const float*)d_in[3];
    const float* b_q   = (const float*)d_in[4];
    const float* W_k   = (const float*)d_in[5];
    const float* b_k   = (const float*)d_in[6];
    const float* W_v   = (const float*)d_in[7];
    const float* b_v   = (const float*)d_in[8];
    const float* W_o   = (const float*)d_in[9];
    const float* b_o   = (const float*)d_in[10];
    float* out = (float*)d_out;

    cudaFuncSetAttribute(attn_kernel, cudaFuncAttributeMaxDynamicSharedMemorySize,
                         ATTN_SMEM_BYTES);
    cudaFuncSetAttribute(gemm_proj_kernel, cudaFuncAttributeMaxDynamicSharedMemorySize,
                         GEMM_SMEM);
    cudaFuncSetAttribute(gemm_out_kernel, cudaFuncAttributeMaxDynamicSharedMemorySize,
                         GEMM_SMEM);

    // Fused input + weight prep (bf16 hi/lo interchange)
    prep_all_kernel<<<dim3(1024, 1, 4), 256>>>(query, key_, value,
                                               W_q, W_k, W_v, W_o);

    // Fused q/k/v projections: one launch, 1536 CTAs
    gemm_proj_kernel<<<dim3(64, 8, 3), 256, GEMM_SMEM>>>(b_q, b_k, b_v);

    // causal attention: 512 CTAs, longest-first 1D order
    attn_kernel<<<512, 256, ATTN_SMEM_BYTES>>>();

    // output projection: concat [8192,512] @ W_o [512,512] + b_o -> fp32 out
    gemm_out_kernel<<<dim3(64, 8), 256, GEMM_SMEM>>>(b_o, out);
}

// round 14
// speedup vs baseline: 3.8154x; 1.0069x over previous
#include <cuda_runtime.h>
#include <cuda_bf16.h>
#include <cstdint>

// Problem constants
#define NB     4
#define KWIN   2048
#define DMODEL 512
#define NHEAD  8
#define HDIM   64
#define NELEM  (NB * KWIN * DMODEL)

// ---------------------------------------------------------------------------
// Scratch (allocation-free rule: __device__ globals). All interchange in
// bf16 hi/lo split pairs (hi ~ bf16(x), lo = x - hi; sum ~= fp32 exact).
// Layout for all: [B, K, H*64] row-major == [8192, 512]
// ---------------------------------------------------------------------------
__device__ __nv_bfloat16 g_xqhi[NELEM], g_xqlo[NELEM];   // input query split
__device__ __nv_bfloat16 g_xkhi[NELEM], g_xklo[NELEM];   // input key split
__device__ __nv_bfloat16 g_xvhi[NELEM], g_xvlo[NELEM];   // input value split
__device__ __nv_bfloat16 g_qphi[NELEM], g_qplo[NELEM];   // projected q
__device__ __nv_bfloat16 g_kphi[NELEM], g_kplo[NELEM];   // projected k
__device__ __nv_bfloat16 g_vphi[NELEM], g_vplo[NELEM];   // projected v
__device__ __nv_bfloat16 g_cthi[NELEM], g_ctlo[NELEM];   // attn concat out

// Pre-transposed, bf16-split weights: 32 blocks of [64 n][512 k]
__device__ __nv_bfloat16 g_wthi[32 * 64 * 512];
__device__ __nv_bfloat16 g_wtlo[32 * 64 * 512];

// ---------------------------------------------------------------------------
// Helpers
// ---------------------------------------------------------------------------
__device__ __forceinline__ uint32_t smem_u32(const void* p) {
    uint32_t a;
    asm("{ .reg .u64 t; cvta.to.shared.u64 t, %1; cvt.u32.u64 %0, t; }"
        : "=r"(a) : "l"(p));
    return a;
}
__device__ __forceinline__ uint32_t sw128(uint32_t off) {
    return off ^ ((off >> 3) & 0x70);
}
__device__ __forceinline__ void cp16(uint32_t smem, const void* g) {
    asm volatile("cp.async.cg.shared.global [%0], [%1], 16;"
                 :: "r"(smem), "l"(g) : "memory");
}
#define CP_COMMIT() asm volatile("cp.async.commit_group;" ::: "memory")
#define CP_WAIT0()  asm volatile("cp.async.wait_group 0;" ::: "memory")

__device__ __forceinline__ void ldsm_x4(uint32_t& r0, uint32_t& r1,
                                        uint32_t& r2, uint32_t& r3, uint32_t addr) {
    asm volatile("ldmatrix.sync.aligned.m8n8.x4.shared.b16 {%0,%1,%2,%3}, [%4];"
                 : "=r"(r0), "=r"(r1), "=r"(r2), "=r"(r3) : "r"(addr));
}
__device__ __forceinline__ void ldsm_x4_t(uint32_t& r0, uint32_t& r1,
                                          uint32_t& r2, uint32_t& r3, uint32_t addr) {
    asm volatile("ldmatrix.sync.aligned.m8n8.x4.trans.shared.b16 {%0,%1,%2,%3}, [%4];"
                 : "=r"(r0), "=r"(r1), "=r"(r2), "=r"(r3) : "r"(addr));
}
__device__ __forceinline__ void mma_bf16(float* c, const uint32_t* a, const uint32_t* b) {
    asm volatile(
        "mma.sync.aligned.m16n8k16.row.col.f32.bf16.bf16.f32 "
        "{%0,%1,%2,%3}, {%4,%5,%6,%7}, {%8,%9}, {%0,%1,%2,%3};"
        : "+f"(c[0]), "+f"(c[1]), "+f"(c[2]), "+f"(c[3])
        : "r"(a[0]), "r"(a[1]), "r"(a[2]), "r"(a[3]), "r"(b[0]), "r"(b[1]));
}
// raw MUFU exp2 (what __expf hides behind an extra FMUL)
__device__ __forceinline__ float ex2(float x) {
    float y;
    asm("ex2.approx.f32 %0, %1;" : "=f"(y) : "f"(x));
    return y;
}
// pack two fp32 -> bf16x2 reg: low half = p0, high half = p1
__device__ __forceinline__ uint32_t pack_bf16x2(float p0, float p1) {
    uint32_t d;
    asm("cvt.rn.bf16x2.f32 %0, %1, %2;" : "=r"(d) : "f"(p1), "f"(p0));
    return d;
}
// trunc split of a pair: hi = upper-16-bit truncation (exact bf16, 1 PRMT),
// lo = exact residual, packed with one cvt. |p - (hi+lo)| <= 2^-16 |p|.
__device__ __forceinline__ void trunc_split_pack(float p0, float p1,
                                                 uint32_t& hi, uint32_t& lo) {
    uint32_t b0 = __float_as_uint(p0), b1 = __float_as_uint(p1);
    hi = __byte_perm(b0, b1, 0x7632);
    float h0 = __uint_as_float(b0 & 0xffff0000u);
    float h1 = __uint_as_float(b1 & 0xffff0000u);
    lo = pack_bf16x2(p0 - h0, p1 - h1);
}
// split float4 -> hi uint2 (4 bf16), lo uint2 (rn split, used in prep)
__device__ __forceinline__ void split4(float4 v, uint2& uh, uint2& ul) {
    float hx = __bfloat162float(__float2bfloat16_rn(v.x));
    float hy = __bfloat162float(__float2bfloat16_rn(v.y));
    float hz = __bfloat162float(__float2bfloat16_rn(v.z));
    float hw = __bfloat162float(__float2bfloat16_rn(v.w));
    uh.x = pack_bf16x2(hx, hy);
    uh.y = pack_bf16x2(hz, hw);
    ul.x = pack_bf16x2(v.x - hx, v.y - hy);
    ul.y = pack_bf16x2(v.z - hz, v.w - hw);
}

// ---------------------------------------------------------------------------
// prep (fused): z<3 -> input fp32 -> bf16 hi/lo split (1024 blocks each);
//               z=3 -> weight transpose + split (blocks 0..255).
//   grid = (1024, 1, 4), block = 256
// ---------------------------------------------------------------------------
__global__ __launch_bounds__(256)
void prep_all_kernel(const float* __restrict__ q, const float* __restrict__ k,
                     const float* __restrict__ v,
                     const float* __restrict__ Wq, const float* __restrict__ Wk,
                     const float* __restrict__ Wv, const float* __restrict__ Wo)
{
    __shared__ float s[64][65];
    const int slot = blockIdx.z;
    const int tid  = threadIdx.x;

    if (slot == 3) {
        const int x = blockIdx.x;
        if (x >= 256) return;
        const int which = x >> 6;          // 0..3
        const int kt    = (x >> 3) & 7;
        const int nb    = x & 7;
        const float* W = (which == 0) ? Wq : (which == 1) ? Wk
                       : (which == 2) ? Wv : Wo;
        const int wstride = (which < 3) ? 512 * 64 : 64;
        const int ldb     = (which < 3) ? 64 : 512;
        const int blkbase = which * 8;
        const float* Wt = W + (size_t)nb * wstride;

#pragma unroll
        for (int j = 0; j < 16; ++j) {
            int f = tid + 256 * j;          // 0..4095
            int kk = f >> 6, n = f & 63;
            s[kk][n] = Wt[(size_t)(kt * 64 + kk) * ldb + n];
        }
        __syncthreads();
#pragma unroll
        for (int j = 0; j < 16; ++j) {
            int f = tid + 256 * j;
            int n = f >> 6, kk = f & 63;
            float x2 = s[kk][n];
            __nv_bfloat16 hi = __float2bfloat16_rn(x2);
            __nv_bfloat16 lo = __float2bfloat16_rn(x2 - __bfloat162float(hi));
            size_t o = (size_t)(blkbase + nb) * (64 * 512) + (size_t)n * 512 + kt * 64 + kk;
            g_wthi[o] = hi;
            g_wtlo[o] = lo;
        }
        return;
    }

    const float* X = (slot == 0) ? q : (slot == 1) ? k : v;
    __nv_bfloat16* hi = (slot == 0) ? g_xqhi : (slot == 1) ? g_xkhi : g_xvhi;
    __nv_bfloat16* lo = (slot == 0) ? g_xqlo : (slot == 1) ? g_xklo : g_xvlo;

    const int idx0 = blockIdx.x * 256 + tid;           // 0..262143
#pragma unroll
    for (int r = 0; r < 4; ++r) {
        const int i = idx0 + r * 262144;               // float4 index, < 1048576
        float4 val = ((const float4*)X)[i];
        uint2 uh, ul;
        split4(val, uh, ul);
        ((uint2*)hi)[i] = uh;
        ((uint2*)lo)[i] = ul;
    }
}

// ---------------------------------------------------------------------------
// HMMA bf16-split GEMM core, cp.async pipelined, ONE barrier per chunk.
//   Dyn smem 96KB: 2 buffers x (Ahi 16K | Alo 16K | Bhi 8K | Blo 8K).
//   Pipeline: WAIT0 -> barrier -> issue loads(ck+1) -> compute(ck).
//   The single barrier proves both "data(ck) visible" and "buffer (ck+1)&1
//   free" (its readers finished in iteration ck-1, before this barrier).
// ---------------------------------------------------------------------------
#define GEMM_SMEM (2 * 49152)

__device__ __forceinline__ void gemm_core(
    const __nv_bfloat16* __restrict__ Ahi_g,
    const __nv_bfloat16* __restrict__ Alo_g,
    int blkbase, const float* __restrict__ bias,
    float* out, __nv_bfloat16* ophi, __nv_bfloat16* oplo, int osel, char* gsm)
{
    const uint32_t sb = smem_u32(gsm);
    const int tid  = threadIdx.x;
    const int lane = tid & 31;
    const int wid  = tid >> 5;
    const int wm   = wid >> 1;       // 0..3 -> rows wm*32..+31
    const int wn   = wid & 1;        // 0..1 -> cols wn*32..+31
    const int m0   = blockIdx.x * 128;
    const int nb   = blockIdx.y;
    const size_t wbase = (size_t)(blkbase + nb) * (64 * 512);

    auto load_chunk = [&](int ck, int bb) {
        const int k0 = ck * 64;
        const uint32_t base = sb + bb * 49152;
#pragma unroll
        for (int j = 0; j < 4; ++j) {
            int f   = tid + 256 * j;        // 0..1023
            int row = f >> 3;               // 0..127
            int kq  = (f & 7) << 3;         // element offset 0..56
            uint32_t sw = sw128((uint32_t)(row * 128 + (kq << 1)));
            const size_t src = (size_t)(m0 + row) * 512 + k0 + kq;
            cp16(base + sw,         Ahi_g + src);
            cp16(base + 16384 + sw, Alo_g + src);
        }
#pragma unroll
        for (int j = 0; j < 2; ++j) {
            int f  = tid + 256 * j;         // 0..511
            int n  = f >> 3;                // 0..63
            int kq = (f & 7) << 3;
            uint32_t sw = sw128((uint32_t)(n * 128 + (kq << 1)));
            const size_t src = wbase + (size_t)n * 512 + k0 + kq;
            cp16(base + 32768 + sw, g_wthi + src);
            cp16(base + 40960 + sw, g_wtlo + src);
        }
    };

    float C[2][4][4];
#pragma unroll
    for (int mi = 0; mi < 2; ++mi)
#pragma unroll
        for (int ni = 0; ni < 4; ++ni)
#pragma unroll
            for (int q = 0; q < 4; ++q) C[mi][ni][q] = 0.f;

    load_chunk(0, 0);
    CP_COMMIT();

    for (int ck = 0; ck < 8; ++ck) {
        CP_WAIT0();            // only one group in flight: chunk ck
        __syncthreads();       // data(ck) visible; buffer (ck+1)&1 free
        if (ck < 7) {
            load_chunk(ck + 1, (ck + 1) & 1);
            CP_COMMIT();       // flies under compute(ck)
        }

        const uint32_t base = sb + (ck & 1) * 49152;
        const uint32_t aHiB = base, aLoB = base + 16384;
        const uint32_t bHiB = base + 32768, bLoB = base + 40960;

#pragma unroll
        for (int ks = 0; ks < 4; ++ks) {
            const int kb = ks * 32 + ((lane >> 4) << 4);   // byte offset in row
            uint32_t ahi[2][4], alo[2][4];
            const int arow = wm * 32 + (lane & 15);
#pragma unroll
            for (int mi = 0; mi < 2; ++mi) {
                uint32_t off = sw128((uint32_t)((arow + mi * 16) * 128 + kb));
                ldsm_x4(ahi[mi][0], ahi[mi][1], ahi[mi][2], ahi[mi][3], aHiB + off);
                ldsm_x4(alo[mi][0], alo[mi][1], alo[mi][2], alo[mi][3], aLoB + off);
            }
            const int brow = wn * 32 + (lane & 15);
            // per-half: load 8 B frag regs, consume immediately (small live set)
#pragma unroll
            for (int half = 0; half < 2; ++half) {
                uint32_t off = sw128((uint32_t)((brow + half * 16) * 128 + kb));
                uint32_t bh[4], bl[4];
                ldsm_x4(bh[0], bh[1], bh[2], bh[3], bHiB + off);
                ldsm_x4(bl[0], bl[1], bl[2], bl[3], bLoB + off);
#pragma unroll
                for (int q2 = 0; q2 < 2; ++q2) {
                    const int ni = half * 2 + q2;
                    uint32_t bfh[2] = { bh[q2], bh[q2 + 2] };
                    uint32_t bfl[2] = { bl[q2], bl[q2 + 2] };
#pragma unroll
                    for (int mi = 0; mi < 2; ++mi) {
                        mma_bf16(C[mi][ni], ahi[mi], bfh);
                        mma_bf16(C[mi][ni], ahi[mi], bfl);
                        mma_bf16(C[mi][ni], alo[mi], bfh);
                    }
                }
            }
        }
    }

    // Epilogue: fragment rows groupID/+8, cols 2*(lane&3)/+1
#pragma unroll
    for (int mi = 0; mi < 2; ++mi) {
        const int r = m0 + wm * 32 + mi * 16 + (lane >> 2);
#pragma unroll
        for (int ni = 0; ni < 4; ++ni) {
            const int col = nb * 64 + wn * 32 + ni * 8 + ((lane & 3) << 1);
            float2 bb = *(const float2*)(bias + col);
            float c00 = C[mi][ni][0] + bb.x, c01 = C[mi][ni][1] + bb.y;
            float c10 = C[mi][ni][2] + bb.x, c11 = C[mi][ni][3] + bb.y;
            if (osel == 0) {
                *(float2*)(out + (size_t)r * 512 + col)       = make_float2(c00, c01);
                *(float2*)(out + (size_t)(r + 8) * 512 + col) = make_float2(c10, c11);
            } else {
                uint32_t h0, l0v, h1, l1v;
                trunc_split_pack(c00, c01, h0, l0v);
                trunc_split_pack(c10, c11, h1, l1v);
                *(uint32_t*)(ophi + (size_t)r * 512 + col)       = h0;
                *(uint32_t*)(oplo + (size_t)r * 512 + col)       = l0v;
                *(uint32_t*)(ophi + (size_t)(r + 8) * 512 + col) = h1;
                *(uint32_t*)(oplo + (size_t)(r + 8) * 512 + col) = l1v;
            }
        }
    }
}

// Fused q/k/v projections: grid (64, 8, 3)
__global__ __launch_bounds__(256)
void gemm_proj_kernel(const float* __restrict__ bq, const float* __restrict__ bk,
                      const float* __restrict__ bv)
{
    extern __shared__ __align__(1024) char gsm[];
    const int z = blockIdx.z;
    const __nv_bfloat16* Ahi = (z == 0) ? g_xqhi : (z == 1) ? g_xkhi : g_xvhi;
    const __nv_bfloat16* Alo = (z == 0) ? g_xqlo : (z == 1) ? g_xklo : g_xvlo;
    const float* bias        = (z == 0) ? bq     : (z == 1) ? bk     : bv;
    __nv_bfloat16* ophi      = (z == 0) ? g_qphi : (z == 1) ? g_kphi : g_vphi;
    __nv_bfloat16* oplo      = (z == 0) ? g_qplo : (z == 1) ? g_kplo : g_vplo;
    gemm_core(Ahi, Alo, z * 8, bias, nullptr, ophi, oplo, 1, gsm);
}

// Output projection: grid (64, 8)
__global__ __launch_bounds__(256)
void gemm_out_kernel(const float* __restrict__ bias, float* out)
{
    extern __shared__ __align__(1024) char gsm[];
    gemm_core(g_cthi, g_ctlo, 24, bias, out, nullptr, nullptr, 0, gsm);
}

// ---------------------------------------------------------------------------
// Causal flash attention on HMMA — cp.async K/V pipeline, ONE barrier/chunk,
// exp2-domain online softmax.
//   grid = 512 (1D, longest-first: qi = 15 - bid/32, bh = bid & 31), block 256.
//   Dyn smem 96KB: Qhi/Qlo [128][64]bf16 (32K) + 2 KV stages x 32K.
// ---------------------------------------------------------------------------
#define ATTN_SMEM_BYTES 98304

__global__ __launch_bounds__(256, 2)
void attn_kernel()
{
    extern __shared__ __align__(1024) char smb[];
    const uint32_t smB  = smem_u32(smb);
    const uint32_t QhiB = smB;
    const uint32_t QloB = smB + 16384;

    const int bid  = blockIdx.x;
    const int qi   = 15 - (bid >> 5);        // longest-first
    const int bh_  = bid & 31;
    const int b    = bh_ >> 3;
    const int h    = bh_ & 7;
    const int tid  = threadIdx.x;
    const int lane = tid & 31;
    const int w    = tid >> 5;               // warp: q rows w*16..+15
    const int g    = lane >> 2;              // fragment row group
    const int t2   = (lane & 3) << 1;        // fragment col pair
    // exp2 domain: c2 = log2(e) / sqrt(2048); p = 2^(s*c2 - m)
    const float c2 = (float)(0.022097086912079608 * 1.4426950408889634);
    const float NEG_INF = __int_as_float(0xff800000);

    const size_t plane = (size_t)b * (KWIN * DMODEL) + (size_t)h * 64;

    // async fill of KV stage s with chunk kt
    auto load_kv = [&](int kt, int s) {
        const uint32_t base = smB + 32768 + s * 32768;
#pragma unroll
        for (int j = 0; j < 2; ++j) {
            int f  = tid + 256 * j;           // 0..511 16B slots
            int c  = f >> 3;                  // 0..63
            int kq = (f & 7) << 3;
            const size_t src = plane + (size_t)(kt * 64 + c) * 512 + kq;
            uint32_t sw = sw128((uint32_t)(c * 128 + (kq << 1)));
            cp16(base + sw,         g_kphi + src);
            cp16(base + 8192 + sw,  g_kplo + src);
            cp16(base + 16384 + sw, g_vphi + src);
            cp16(base + 24576 + sw, g_vplo + src);
        }
    };

    // ---- Q fill: pure copy bf16 hi/lo, swizzled (once per CTA)
#pragma unroll
    for (int j = 0; j < 4; ++j) {
        int f   = tid + 256 * j;          // 0..1023 16B slots
        int row = f >> 3;                 // 0..127
        int kq  = (f & 7) << 3;           // element 0..56
        const size_t src = plane + (size_t)(qi * 128 + row) * 512 + kq;
        uint32_t sw = sw128((uint32_t)(row * 128 + (kq << 1)));
        *(uint4*)(smb + sw)          = *(const uint4*)(g_qphi + src);
        *(uint4*)(smb + 16384 + sw)  = *(const uint4*)(g_qplo + src);
    }

    float O[8][4];
#pragma unroll
    for (int ni = 0; ni < 8; ++ni)
#pragma unroll
        for (int q = 0; q < 4; ++q) O[ni][q] = 0.f;
    float m0 = NEG_INF, m1 = NEG_INF, l0 = 0.f, l1 = 0.f;

    const int ktmax = 2 * qi + 1;
    load_kv(0, 0);
    CP_COMMIT();

    for (int kt = 0; kt <= ktmax; ++kt) {
        CP_WAIT0();            // stage kt&1 landed (only group in flight)
        __syncthreads();       // visible to all; stage (kt+1)&1 free
        if (kt < ktmax) {
            load_kv(kt + 1, (kt + 1) & 1);
            CP_COMMIT();       // flies under compute(kt)
        }

        const uint32_t sbase = smB + 32768 + (kt & 1) * 32768;
        const uint32_t KhiB = sbase,         KloB = sbase + 8192;
        const uint32_t VhiB = sbase + 16384, VloB = sbase + 24576;

        // ---- S = Q K^T : warp computes 16 rows x 64 cols (8 n8 blocks)
        float S[8][4];
#pragma unroll
        for (int ni = 0; ni < 8; ++ni)
#pragma unroll
            for (int q = 0; q < 4; ++q) S[ni][q] = 0.f;

#pragma unroll
        for (int ks = 0; ks < 4; ++ks) {
            const int kb = ks * 32 + ((lane >> 4) << 4);
            uint32_t ahi[4], alo[4];
            {
                uint32_t off = sw128((uint32_t)((w * 16 + (lane & 15)) * 128 + kb));
                ldsm_x4(ahi[0], ahi[1], ahi[2], ahi[3], QhiB + off);
                ldsm_x4(alo[0], alo[1], alo[2], alo[3], QloB + off);
            }
            // per-cb: load 8 K frag regs, consume immediately (small live set)
#pragma unroll
            for (int cb = 0; cb < 4; ++cb) {
                uint32_t off = sw128((uint32_t)((cb * 16 + (lane & 15)) * 128 + kb));
                uint32_t kh[4], kl[4];
                ldsm_x4(kh[0], kh[1], kh[2], kh[3], KhiB + off);
                ldsm_x4(kl[0], kl[1], kl[2], kl[3], KloB + off);
#pragma unroll
                for (int q2 = 0; q2 < 2; ++q2) {
                    const int ni = cb * 2 + q2;
                    uint32_t bfh[2] = { kh[q2], kh[q2 + 2] };
                    uint32_t bfl[2] = { kl[q2], kl[q2 + 2] };
                    mma_bf16(S[ni], ahi, bfh);
                    mma_bf16(S[ni], ahi, bfl);
                    mma_bf16(S[ni], alo, bfh);
                }
            }
        }

        // ---- scale(log2 domain) + causal mask + online softmax
        const bool msk  = (kt >= 2 * qi);
        const int grow0 = qi * 128 + w * 16 + g;
        const int grow1 = grow0 + 8;
        const int colb  = kt * 64 + t2;
#pragma unroll
        for (int ni = 0; ni < 8; ++ni) {
            const int c0 = colb + ni * 8;
            S[ni][0] *= c2;
            S[ni][1] *= c2;
            S[ni][2] *= c2;
            S[ni][3] *= c2;
            if (msk) {
                if (c0     > grow0) S[ni][0] = NEG_INF;
                if (c0 + 1 > grow0) S[ni][1] = NEG_INF;
                if (c0     > grow1) S[ni][2] = NEG_INF;
                if (c0 + 1 > grow1) S[ni][3] = NEG_INF;
            }
        }
        float mx0 = NEG_INF, mx1 = NEG_INF;
#pragma unroll
        for (int ni = 0; ni < 8; ++ni) {
            mx0 = fmaxf(mx0, fmaxf(S[ni][0], S[ni][1]));
            mx1 = fmaxf(mx1, fmaxf(S[ni][2], S[ni][3]));
        }
        mx0 = fmaxf(mx0, __shfl_xor_sync(0xffffffffu, mx0, 1));
        mx0 = fmaxf(mx0, __shfl_xor_sync(0xffffffffu, mx0, 2));
        mx1 = fmaxf(mx1, __shfl_xor_sync(0xffffffffu, mx1, 1));
        mx1 = fmaxf(mx1, __shfl_xor_sync(0xffffffffu, mx1, 2));
        const float mn0 = fmaxf(m0, mx0);
        const float mn1 = fmaxf(m1, mx1);
        float sum0 = 0.f, sum1 = 0.f;
#pragma unroll
        for (int ni = 0; ni < 8; ++ni) {
            S[ni][0] = ex2(S[ni][0] - mn0); sum0 += S[ni][0];
            S[ni][1] = ex2(S[ni][1] - mn0); sum0 += S[ni][1];
            S[ni][2] = ex2(S[ni][2] - mn1); sum1 += S[ni][2];
            S[ni][3] = ex2(S[ni][3] - mn1); sum1 += S[ni][3];
        }
        sum0 += __shfl_xor_sync(0xffffffffu, sum0, 1);
        sum0 += __shfl_xor_sync(0xffffffffu, sum0, 2);
        sum1 += __shfl_xor_sync(0xffffffffu, sum1, 1);
        sum1 += __shfl_xor_sync(0xffffffffu, sum1, 2);
        const float al0 = ex2(m0 - mn0);
        const float al1 = ex2(m1 - mn1);
        l0 = l0 * al0 + sum0;
        l1 = l1 * al1 + sum1;
        m0 = mn0;
        m1 = mn1;
#pragma unroll
        for (int ni = 0; ni < 8; ++ni) {
            O[ni][0] *= al0; O[ni][1] *= al0;
            O[ni][2] *= al1; O[ni][3] *= al1;
        }

        // ---- O += P @ V : P trunc-split from S fragments, V hi/lo trans
#pragma unroll
        for (int ks = 0; ks < 4; ++ks) {
            uint32_t aph[4], apl[4];
            trunc_split_pack(S[2 * ks][0],     S[2 * ks][1],     aph[0], apl[0]);
            trunc_split_pack(S[2 * ks][2],     S[2 * ks][3],     aph[1], apl[1]);
            trunc_split_pack(S[2 * ks + 1][0], S[2 * ks + 1][1], aph[2], apl[2]);
            trunc_split_pack(S[2 * ks + 1][2], S[2 * ks + 1][3], aph[3], apl[3]);

            // per-nb2: load 8 V frag regs, consume immediately (small live set)
#pragma unroll
            for (int nb2 = 0; nb2 < 4; ++nb2) {
                uint32_t off = sw128((uint32_t)((ks * 16 + (lane & 15)) * 128
                                                + nb2 * 32 + ((lane >> 4) << 4)));
                uint32_t vh[4], vl[4];
                ldsm_x4_t(vh[0], vh[1], vh[2], vh[3], VhiB + off);
                ldsm_x4_t(vl[0], vl[1], vl[2], vl[3], VloB + off);
#pragma unroll
                for (int q2 = 0; q2 < 2; ++q2) {
                    const int ni = nb2 * 2 + q2;
                    uint32_t bfh[2] = { vh[q2 * 2], vh[q2 * 2 + 1] };
                    uint32_t bfl[2] = { vl[q2 * 2], vl[q2 * 2 + 1] };
                    mma_bf16(O[ni], aph, bfh);
                    mma_bf16(O[ni], aph, bfl);
                    mma_bf16(O[ni], apl, bfh);
                }
            }
        }
    }

    // ---- normalize + trunc split + write concat layout [b, k, h*64 + v]
    const float inv0 = 1.f / l0;
    const float inv1 = 1.f / l1;
    const int row0 = qi * 128 + w * 16 + g;
#pragma unroll
    for (int ni = 0; ni < 8; ++ni) {
        const int coff = ni * 8 + t2;
        float v00 = O[ni][0] * inv0, v01 = O[ni][1] * inv0;
        float v10 = O[ni][2] * inv1, v11 = O[ni][3] * inv1;
        uint32_t h0, l0v, h1, l1v;
        trunc_split_pack(v00, v01, h0, l0v);
        trunc_split_pack(v10, v11, h1, l1v);
        const size_t o0 = plane + (size_t)row0 * 512 + coff;
        const size_t o1 = plane + (size_t)(row0 + 8) * 512 + coff;
        *(uint32_t*)(g_cthi + o0) = h0;
        *(uint32_t*)(g_ctlo + o0) = l0v;
        *(uint32_t*)(g_cthi + o1) = h1;
        *(uint32_t*)(g_ctlo + o1) = l1v;
    }
}

// ---------------------------------------------------------------------------
// Launch: fused prep -> fused q/k/v projections -> attention -> out proj
// ---------------------------------------------------------------------------
extern "C" void kernel_launch(void* const* d_in, const int* in_sizes, int n_in,
                              void* d_out, int out_size)
{
    const float* query = (const float*)d_in[0];
    const float* key_  = (const float*)d_in[1];
    const float* value = (const float*)d_in[2];
    const float* W_q   = (const float*)d_in[3];
    const float* b_q   = (const float*)d_in[4];
    const float* W_k   = (const float*)d_in[5];
    const float* b_k   = (const float*)d_in[6];
    const float* W_v   = (const float*)d_in[7];
    const float* b_v   = (const float*)d_in[8];
    const float* W_o   = (const float*)d_in[9];
    const float* b_o   = (const float*)d_in[10];
    float* out = (float*)d_out;

    cudaFuncSetAttribute(attn_kernel, cudaFuncAttributeMaxDynamicSharedMemorySize,
                         ATTN_SMEM_BYTES);
    cudaFuncSetAttribute(gemm_proj_kernel, cudaFuncAttributeMaxDynamicSharedMemorySize,
                         GEMM_SMEM);
    cudaFuncSetAttribute(gemm_out_kernel, cudaFuncAttributeMaxDynamicSharedMemorySize,
                         GEMM_SMEM);

    // Fused input + weight prep (bf16 hi/lo interchange)
    prep_all_kernel<<<dim3(1024, 1, 4), 256>>>(query, key_, value,
                                               W_q, W_k, W_v, W_o);

    // Fused q/k/v projections: one launch, 1536 CTAs
    gemm_proj_kernel<<<dim3(64, 8, 3), 256, GEMM_SMEM>>>(b_q, b_k, b_v);

    // causal attention: 512 CTAs, longest-first 1D order
    attn_kernel<<<512, 256, ATTN_SMEM_BYTES>>>();

    // output projection: concat [8192,512] @ W_o [512,512] + b_o -> fp32 out
    gemm_out_kernel<<<dim3(64, 8), 256, GEMM_SMEM>>>(b_o, out);
}